// round 1
// baseline (speedup 1.0000x reference)
#include <cuda_runtime.h>
#include <math.h>

#define BB 4
#define NN 512
#define BN 2048
#define TT 64
#define DD 128
#define HH 4
#define HD 32
#define EPS 1e-5f
#define LSLOPE 0.2f

// ---------------- device scratch (no allocs allowed) ----------------
__device__ float g_h[BN * TT * DD];      // 64 MB
__device__ float g_ret[BN * TT * DD];    // 64 MB
__device__ float g_adjn[BB * NN * NN];   // 4 MB
__device__ float g_cur_a[BB * NN * DD];
__device__ float g_cur_b[BB * NN * DD];
__device__ float g_acc[BB * NN * DD];
__device__ float g_hdiff[BB * NN * DD];

__device__ __forceinline__ float lrelu(float v) { return v > 0.f ? v : LSLOPE * v; }

// ---------------- proj + pos ----------------
// grid: BN*TT blocks, 128 threads. h[row][d] = x[row]@proj_w[d] + pb[d] + pos[t][d]
__global__ void k_proj(const float* __restrict__ x, const float* __restrict__ pw,
                       const float* __restrict__ pb, const float* __restrict__ pos) {
    int row = blockIdx.x;
    int d = threadIdx.x;
    int t = row & (TT - 1);
    const float* xr = x + (size_t)row * 8;
    float xv[8];
#pragma unroll
    for (int f = 0; f < 8; f++) xv[f] = xr[f];
    float s = pb[d] + pos[t * DD + d];
#pragma unroll
    for (int f = 0; f < 8; f++) s += xv[f] * pw[d * 8 + f];
    g_h[(size_t)row * DD + d] = s;
}

// ---------------- adj row-normalize ----------------
__global__ void k_adjn(const float* __restrict__ adj) {
    int row = blockIdx.x;  // b*N+i
    __shared__ float red[8];
    const float* ar = adj + (size_t)row * NN;
    float s = 0.f;
    for (int j = threadIdx.x; j < NN; j += 256) s += ar[j];
#pragma unroll
    for (int o = 16; o; o >>= 1) s += __shfl_down_sync(0xffffffffu, s, o);
    if ((threadIdx.x & 31) == 0) red[threadIdx.x >> 5] = s;
    __syncthreads();
    if (threadIdx.x == 0) {
        float t = 0.f;
#pragma unroll
        for (int w = 0; w < 8; w++) t += red[w];
        red[0] = 1.0f / (t + 1e-9f);
    }
    __syncthreads();
    float inv = red[0];
    for (int j = threadIdx.x; j < NN; j += 256) g_adjn[(size_t)row * NN + j] = ar[j] * inv;
}

// ---------------- fused retention + group norm ----------------
// grid (BN, H), 256 threads, dyn smem 108800 B
#define RET_SMEM 108800
__global__ void __launch_bounds__(256, 2) k_retention(
    const float* __restrict__ wq, const float* __restrict__ bq,
    const float* __restrict__ wk, const float* __restrict__ bk,
    const float* __restrict__ wv, const float* __restrict__ bv,
    const float* __restrict__ gnw, const float* __restrict__ gnb,
    const float* __restrict__ gamma_p) {
    extern __shared__ float sm[];
    float* hs = sm;            // [64][128]          8192
    float* wqt = sm + 8192;    // [128][33]          4224
    float* wkt = wqt + 4224;
    float* wvt = wkt + 4224;
    float* Qs = wvt + 4224;    // [64][33]           2112
    float* Ks = Qs + 2112;
    float* Vs = Ks + 2112;
    float* Ss = sm;            // [64][68] alias hs (4352 <= 8192)
    __shared__ float gpow[64];
    __shared__ float red[18];

    int tid = threadIdx.x;
    int bn = blockIdx.x;
    int head = blockIdx.y;
    int wbase = head * HD;

    if (tid < 64) gpow[tid] = powf(gamma_p[0], (float)tid);

    const float* hb = g_h + (size_t)bn * (TT * DD);
    for (int e = tid; e < (TT * DD) / 4; e += 256)
        ((float4*)hs)[e] = ((const float4*)hb)[e];

    for (int e = tid; e < DD * HD; e += 256) {
        int k = e & 127, jj = e >> 7;
        wqt[k * 33 + jj] = wq[(wbase + jj) * DD + k];
        wkt[k * 33 + jj] = wk[(wbase + jj) * DD + k];
        wvt[k * 33 + jj] = wv[(wbase + jj) * DD + k];
    }
    __syncthreads();

    // ---- QKV: warp w handles t in {w, w+8, ..., w+56}; lane j in [0,32)
    int j = tid & 31, w = tid >> 5;
    {
        float aq[8], ak[8], av[8];
#pragma unroll
        for (int i = 0; i < 8; i++) { aq[i] = 0.f; ak[i] = 0.f; av[i] = 0.f; }
        for (int k = 0; k < DD; k += 4) {
            float q0 = wqt[(k + 0) * 33 + j], q1 = wqt[(k + 1) * 33 + j];
            float q2 = wqt[(k + 2) * 33 + j], q3 = wqt[(k + 3) * 33 + j];
            float k0 = wkt[(k + 0) * 33 + j], k1 = wkt[(k + 1) * 33 + j];
            float k2 = wkt[(k + 2) * 33 + j], k3 = wkt[(k + 3) * 33 + j];
            float v0 = wvt[(k + 0) * 33 + j], v1 = wvt[(k + 1) * 33 + j];
            float v2 = wvt[(k + 2) * 33 + j], v3 = wvt[(k + 3) * 33 + j];
#pragma unroll
            for (int i = 0; i < 8; i++) {
                float4 hv = *(const float4*)&hs[(w + i * 8) * DD + k];
                aq[i] += hv.x * q0 + hv.y * q1 + hv.z * q2 + hv.w * q3;
                ak[i] += hv.x * k0 + hv.y * k1 + hv.z * k2 + hv.w * k3;
                av[i] += hv.x * v0 + hv.y * v1 + hv.z * v2 + hv.w * v3;
            }
        }
        float bqv = bq[wbase + j], bkv = bk[wbase + j], bvv = bv[wbase + j];
#pragma unroll
        for (int i = 0; i < 8; i++) {
            int t = w + i * 8;
            Qs[t * 33 + j] = aq[i] + bqv;
            Ks[t * 33 + j] = ak[i] + bkv;
            Vs[t * 33 + j] = av[i] + bvv;
        }
    }
    __syncthreads();

    // ---- S = (Q K^T) * decay. 4x4 register tile per thread.
    {
        int qg = tid >> 4, kg = tid & 15;
        float sacc[4][4];
#pragma unroll
        for (int i2 = 0; i2 < 4; i2++)
#pragma unroll
            for (int c = 0; c < 4; c++) sacc[i2][c] = 0.f;
        for (int jj = 0; jj < 32; jj++) {
            float qv[4], kv[4];
#pragma unroll
            for (int i2 = 0; i2 < 4; i2++) qv[i2] = Qs[(qg * 4 + i2) * 33 + jj];
#pragma unroll
            for (int c = 0; c < 4; c++) kv[c] = Ks[(kg * 4 + c) * 33 + jj];
#pragma unroll
            for (int i2 = 0; i2 < 4; i2++)
#pragma unroll
                for (int c = 0; c < 4; c++) sacc[i2][c] += qv[i2] * kv[c];
        }
#pragma unroll
        for (int i2 = 0; i2 < 4; i2++) {
            int q = qg * 4 + i2;
#pragma unroll
            for (int c = 0; c < 4; c++) {
                int kk = kg * 4 + c;
                Ss[q * 68 + kk] = (kk <= q) ? sacc[i2][c] * gpow[q - kk] : 0.f;
            }
        }
    }
    __syncthreads();

    // ---- O = S @ V.  thread: jh=tid&15 -> j2=2*jh(+c), tg=tid>>4 -> t=tg*4+i
    int jh = tid & 15, tg = tid >> 4;
    float og[4][2];
#pragma unroll
    for (int i2 = 0; i2 < 4; i2++) { og[i2][0] = 0.f; og[i2][1] = 0.f; }
    for (int kk = 0; kk < 64; kk++) {
        float v0 = Vs[kk * 33 + 2 * jh];
        float v1 = Vs[kk * 33 + 2 * jh + 1];
#pragma unroll
        for (int i2 = 0; i2 < 4; i2++) {
            float sv = Ss[(tg * 4 + i2) * 68 + kk];
            og[i2][0] += sv * v0;
            og[i2][1] += sv * v1;
        }
    }

    // ---- GroupNorm over (T, hd) for this (bn, head)
    float s1 = 0.f, s2 = 0.f;
#pragma unroll
    for (int i2 = 0; i2 < 4; i2++) {
        s1 += og[i2][0] + og[i2][1];
        s2 += og[i2][0] * og[i2][0] + og[i2][1] * og[i2][1];
    }
#pragma unroll
    for (int o = 16; o; o >>= 1) {
        s1 += __shfl_down_sync(0xffffffffu, s1, o);
        s2 += __shfl_down_sync(0xffffffffu, s2, o);
    }
    if ((tid & 31) == 0) { red[tid >> 5] = s1; red[8 + (tid >> 5)] = s2; }
    __syncthreads();
    if (tid == 0) {
        float a = 0.f, b2 = 0.f;
#pragma unroll
        for (int x2 = 0; x2 < 8; x2++) { a += red[x2]; b2 += red[8 + x2]; }
        float mean = a * (1.0f / 2048.0f);
        float var = b2 * (1.0f / 2048.0f) - mean * mean;
        red[16] = mean;
        red[17] = rsqrtf(var + EPS);
    }
    __syncthreads();
    float mean = red[16], rs = red[17];
    int jb = 2 * jh;
    float gw0 = gnw[wbase + jb] * rs, gb0 = gnb[wbase + jb];
    float gw1 = gnw[wbase + jb + 1] * rs, gb1 = gnb[wbase + jb + 1];
    float* ob = g_ret + (size_t)bn * (TT * DD) + wbase + jb;
#pragma unroll
    for (int i2 = 0; i2 < 4; i2++) {
        int t = tg * 4 + i2;
        float2 vv;
        vv.x = (og[i2][0] - mean) * gw0 + gb0;
        vv.y = (og[i2][1] - mean) * gw1 + gb1;
        *(float2*)&ob[(size_t)t * DD] = vv;
    }
}

// ---------------- layer norm over D, in place on g_ret ----------------
__global__ void k_ln(const float* __restrict__ lw, const float* __restrict__ lb) {
    int row = blockIdx.x;
    int d = threadIdx.x;
    float* p = g_ret + (size_t)row * DD;
    float v = p[d];
    float s1 = v, s2 = v * v;
#pragma unroll
    for (int o = 16; o; o >>= 1) {
        s1 += __shfl_down_sync(0xffffffffu, s1, o);
        s2 += __shfl_down_sync(0xffffffffu, s2, o);
    }
    __shared__ float r1[4], r2[4], mv[2];
    int w = d >> 5;
    if ((d & 31) == 0) { r1[w] = s1; r2[w] = s2; }
    __syncthreads();
    if (d == 0) {
        float a = r1[0] + r1[1] + r1[2] + r1[3];
        float b2 = r2[0] + r2[1] + r2[2] + r2[3];
        float mean = a * (1.0f / 128.0f);
        float var = b2 * (1.0f / 128.0f) - mean * mean;
        mv[0] = mean;
        mv[1] = rsqrtf(var + EPS);
    }
    __syncthreads();
    p[d] = (v - mv[0]) * mv[1] * lw[d] + lb[d];
}

// ---------------- diffusion step 0: cur0 = h_last @ diff_w^T; acc = c0*cur0 ----------------
#define DIFF0_SMEM ((128 * 129 + 128) * 4)
__global__ void k_diff0(const float* __restrict__ dw, const float* __restrict__ convw) {
    extern __shared__ float sm[];
    float* dwt = sm;            // [128][129]
    float* hl = sm + 128 * 129; // [128]
    int bn = blockIdx.x;
    int tid = threadIdx.x;  // 128
    hl[tid] = g_ret[((size_t)bn * TT + (TT - 1)) * DD + tid];
    for (int e = tid; e < DD * DD; e += 128) {
        int ddw = e >> 7, k = e & 127;
        dwt[k * 129 + ddw] = dw[e];
    }
    __syncthreads();
    float s = 0.f;
    for (int k = 0; k < DD; k++) s += hl[k] * dwt[k * 129 + tid];
    size_t idx = (size_t)bn * DD + tid;
    g_cur_a[idx] = s;
    g_acc[idx] = convw[0] * s;
}

// ---------------- diffusion hop: cur_out = adj_n @ cur_in; acc += c_k*cur_out ----------------
// grid (N/8, B), 256 threads. dir=0: a->b, dir=1: b->a. last: finalize h_diff.
__global__ void k_hop(const float* __restrict__ convw, int kidx,
                      const float* __restrict__ convb, int dir, int last) {
    int b = blockIdx.y, i0 = blockIdx.x * 8;
    int d = threadIdx.x & 127, ih = threadIdx.x >> 7;
    __shared__ float a[8][64];
    const float* curin = dir ? g_cur_b : g_cur_a;
    float* curout = dir ? g_cur_a : g_cur_b;
    const float* curb = curin + (size_t)b * NN * DD;
    float acc[4] = {0.f, 0.f, 0.f, 0.f};
    for (int jc = 0; jc < NN; jc += 64) {
        __syncthreads();
        for (int e = threadIdx.x; e < 8 * 64; e += 256) {
            int r = e >> 6, jj = e & 63;
            a[r][jj] = g_adjn[((size_t)b * NN + i0 + r) * NN + jc + jj];
        }
        __syncthreads();
        for (int jj = 0; jj < 64; jj += 4) {
            float c0 = curb[(size_t)(jc + jj + 0) * DD + d];
            float c1 = curb[(size_t)(jc + jj + 1) * DD + d];
            float c2 = curb[(size_t)(jc + jj + 2) * DD + d];
            float c3 = curb[(size_t)(jc + jj + 3) * DD + d];
#pragma unroll
            for (int r = 0; r < 4; r++) {
                float4 av4 = *(const float4*)&a[ih * 4 + r][jj];
                acc[r] += av4.x * c0 + av4.y * c1 + av4.z * c2 + av4.w * c3;
            }
        }
    }
    float cw = convw[kidx];
#pragma unroll
    for (int r = 0; r < 4; r++) {
        int i = i0 + ih * 4 + r;
        size_t idx = ((size_t)b * NN + i) * DD + d;
        curout[idx] = acc[r];
        float av = g_acc[idx] + cw * acc[r];
        if (last) {
            av += convb[0];
            g_hdiff[idx] = lrelu(av);
        } else {
            g_acc[idx] = av;
        }
    }
}

// ---------------- MLP fusion: h = lrelu([h_ret, h_diff] @ mlp_w^T + mlp_b) ----------------
// grid BN, 256 threads. h_diff part is t-independent -> folded into a per-d bias.
#define MLP_SMEM ((64 * 128 + 64 * 129 + 128) * 4)
__global__ void __launch_bounds__(256) k_mlp(const float* __restrict__ mw,
                                             const float* __restrict__ mb) {
    extern __shared__ float sm[];
    float* hsm = sm;            // [64][128]
    float* wt = sm + 64 * 128;  // [64][129]
    float* hd = wt + 64 * 129;  // [128]
    int bn = blockIdx.x;
    int tid = threadIdx.x;
    int d = tid & 127, th = tid >> 7;
    const float* rb = g_ret + (size_t)bn * (TT * DD);
    for (int e = tid; e < (TT * DD) / 4; e += 256)
        ((float4*)hsm)[e] = ((const float4*)rb)[e];
    if (tid < 128) hd[tid] = g_hdiff[(size_t)bn * DD + tid];

    float acc[32];
#pragma unroll
    for (int i = 0; i < 32; i++) acc[i] = 0.f;
    float bias2 = 0.f;

    for (int kc = 0; kc < 256; kc += 64) {
        __syncthreads();
        for (int e = tid; e < 64 * 128; e += 256) {
            int kk = e & 63, ddw = e >> 6;
            wt[kk * 129 + ddw] = mw[(size_t)ddw * 256 + kc + kk];
        }
        __syncthreads();
        if (kc < 128) {
            for (int kk = 0; kk < 64; kk += 4) {
                float w0 = wt[(kk + 0) * 129 + d];
                float w1 = wt[(kk + 1) * 129 + d];
                float w2 = wt[(kk + 2) * 129 + d];
                float w3 = wt[(kk + 3) * 129 + d];
                int k = kc + kk;
#pragma unroll
                for (int i = 0; i < 32; i++) {
                    float4 hv = *(const float4*)&hsm[(th * 32 + i) * DD + k];
                    acc[i] += hv.x * w0 + hv.y * w1 + hv.z * w2 + hv.w * w3;
                }
            }
        } else {
            for (int kk = 0; kk < 64; kk++)
                bias2 += wt[kk * 129 + d] * hd[kc - 128 + kk];
        }
    }
    float base = bias2 + mb[d];
    float* obuf = g_h + (size_t)bn * (TT * DD);
#pragma unroll
    for (int i = 0; i < 32; i++) {
        float v = acc[i] + base;
        obuf[(size_t)(th * 32 + i) * DD + d] = lrelu(v);
    }
}

// ---------------- head ----------------
__global__ void k_head(const float* __restrict__ h1w, const float* __restrict__ h1b,
                       const float* __restrict__ h2w, const float* __restrict__ h2b,
                       float* __restrict__ out) {
    __shared__ float wt[128 * 65];
    __shared__ float lr[128];
    __shared__ float red[2];
    int bn = blockIdx.x;
    int tid = threadIdx.x;  // 64
    for (int e = tid; e < 128; e += 64)
        lr[e] = g_h[((size_t)bn * TT + (TT - 1)) * DD + e];
    for (int e = tid; e < 64 * 128; e += 64) {
        int jj = e >> 7, k = e & 127;
        wt[k * 65 + jj] = h1w[e];
    }
    __syncthreads();
    float s = 0.f;
    for (int k = 0; k < 128; k++) s += lr[k] * wt[k * 65 + tid];
    s += h1b[tid];
    s = lrelu(s);
    s *= h2w[tid];
#pragma unroll
    for (int o = 16; o; o >>= 1) s += __shfl_down_sync(0xffffffffu, s, o);
    if ((tid & 31) == 0) red[tid >> 5] = s;
    __syncthreads();
    if (tid == 0) out[bn] = red[0] + red[1] + h2b[0];
}

// ---------------- launch ----------------
extern "C" void kernel_launch(void* const* d_in, const int* in_sizes, int n_in,
                              void* d_out, int out_size) {
    const float* x      = (const float*)d_in[0];
    const float* adj    = (const float*)d_in[1];
    const float* proj_w = (const float*)d_in[2];
    const float* proj_b = (const float*)d_in[3];
    const float* pos    = (const float*)d_in[4];
    const float* diff_w = (const float*)d_in[5];
    const float* conv_w = (const float*)d_in[6];
    const float* conv_b = (const float*)d_in[7];
    const float* wq_w   = (const float*)d_in[8];
    const float* wq_b   = (const float*)d_in[9];
    const float* wk_w   = (const float*)d_in[10];
    const float* wk_b   = (const float*)d_in[11];
    const float* wv_w   = (const float*)d_in[12];
    const float* wv_b   = (const float*)d_in[13];
    const float* gn_w   = (const float*)d_in[14];
    const float* gn_b   = (const float*)d_in[15];
    const float* gamma  = (const float*)d_in[16];
    const float* ln_w   = (const float*)d_in[17];
    const float* ln_b   = (const float*)d_in[18];
    const float* mlp_w  = (const float*)d_in[19];
    const float* mlp_b  = (const float*)d_in[20];
    const float* h1w    = (const float*)d_in[21];
    const float* h1b    = (const float*)d_in[22];
    const float* h2w    = (const float*)d_in[23];
    const float* h2b    = (const float*)d_in[24];

    cudaFuncSetAttribute(k_retention, cudaFuncAttributeMaxDynamicSharedMemorySize, RET_SMEM);
    cudaFuncSetAttribute(k_mlp, cudaFuncAttributeMaxDynamicSharedMemorySize, MLP_SMEM);
    cudaFuncSetAttribute(k_diff0, cudaFuncAttributeMaxDynamicSharedMemorySize, DIFF0_SMEM);

    k_proj<<<BN * TT, 128>>>(x, proj_w, proj_b, pos);
    k_adjn<<<BB * NN, 256>>>(adj);

    for (int l = 0; l < 2; l++) {
        k_retention<<<dim3(BN, HH), 256, RET_SMEM>>>(
            wq_w + l * DD * DD, wq_b + l * DD, wk_w + l * DD * DD, wk_b + l * DD,
            wv_w + l * DD * DD, wv_b + l * DD, gn_w + l * DD, gn_b + l * DD, gamma + l);
        k_ln<<<BN * TT, 128>>>(ln_w + l * DD, ln_b + l * DD);
        k_diff0<<<BB * NN, 128, DIFF0_SMEM>>>(diff_w + l * DD * DD, conv_w + l * 3);
        k_hop<<<dim3(NN / 8, BB), 256>>>(conv_w + l * 3, 1, conv_b + l, 0, 0);
        k_hop<<<dim3(NN / 8, BB), 256>>>(conv_w + l * 3, 2, conv_b + l, 1, 1);
        k_mlp<<<BN, 256, MLP_SMEM>>>(mlp_w + (size_t)l * DD * 2 * DD, mlp_b + l * DD);
    }
    k_head<<<BN, 64>>>(h1w, h1b, h2w, h2b, (float*)d_out);
}

// round 2
// speedup vs baseline: 1.3252x; 1.3252x over previous
#include <cuda_runtime.h>
#include <math.h>

#define BB 4
#define NN 512
#define BN 2048
#define TT 64
#define DD 128
#define HH 4
#define HD 32
#define EPS 1e-5f
#define LSLOPE 0.2f

// ---------------- device scratch ----------------
__device__ float g_h[BN * TT * DD];
__device__ float g_ret[BN * TT * DD];
__device__ float g_adjn[BB * NN * NN];
__device__ float g_cur_a[BB * NN * DD];
__device__ float g_cur_b[BB * NN * DD];
__device__ float g_acc[BB * NN * DD];
__device__ float g_hdiff[BB * NN * DD];

__device__ __forceinline__ float lrelu(float v) { return v > 0.f ? v : LSLOPE * v; }

__device__ __forceinline__ float tf32f(float x) {
    unsigned u;
    asm("cvt.rna.tf32.f32 %0, %1;" : "=r"(u) : "f"(x));
    return __uint_as_float(u);
}

#define MMA_TF32(C, A0, A1, A2, A3, B0, B1)                                             \
    asm volatile(                                                                       \
        "mma.sync.aligned.m16n8k8.row.col.f32.tf32.tf32.f32 "                           \
        "{%0,%1,%2,%3},{%4,%5,%6,%7},{%8,%9},{%0,%1,%2,%3};"                            \
        : "+f"((C)[0]), "+f"((C)[1]), "+f"((C)[2]), "+f"((C)[3])                        \
        : "r"(A0), "r"(A1), "r"(A2), "r"(A3), "r"(B0), "r"(B1))

// ---------------- proj + pos ----------------
__global__ void k_proj(const float* __restrict__ x, const float* __restrict__ pw,
                       const float* __restrict__ pb, const float* __restrict__ pos) {
    int row = blockIdx.x;
    int d = threadIdx.x;
    int t = row & (TT - 1);
    const float* xr = x + (size_t)row * 8;
    float xv[8];
#pragma unroll
    for (int f = 0; f < 8; f++) xv[f] = xr[f];
    float s = pb[d] + pos[t * DD + d];
#pragma unroll
    for (int f = 0; f < 8; f++) s += xv[f] * pw[d * 8 + f];
    g_h[(size_t)row * DD + d] = s;
}

// ---------------- adj row-normalize ----------------
__global__ void k_adjn(const float* __restrict__ adj) {
    int row = blockIdx.x;
    __shared__ float red[8];
    const float* ar = adj + (size_t)row * NN;
    float s = 0.f;
    for (int j = threadIdx.x; j < NN; j += 256) s += ar[j];
#pragma unroll
    for (int o = 16; o; o >>= 1) s += __shfl_down_sync(0xffffffffu, s, o);
    if ((threadIdx.x & 31) == 0) red[threadIdx.x >> 5] = s;
    __syncthreads();
    if (threadIdx.x == 0) {
        float t = 0.f;
#pragma unroll
        for (int w = 0; w < 8; w++) t += red[w];
        red[0] = 1.0f / (t + 1e-9f);
    }
    __syncthreads();
    float inv = red[0];
    for (int j = threadIdx.x; j < NN; j += 256) g_adjn[(size_t)row * NN + j] = ar[j] * inv;
}

// ---------------- fused retention (tf32 mma) + GroupNorm + LayerNorm ----------------
// grid BN, 256 threads (8 warps), one block per sequence; all 4 heads.
#define LDH 132
#define LDW 36
#define LDVT 68
#define LDSS 68
#define LDO 132
#define OFF_HS 0
#define OFF_WB 8448
#define OFF_Q 22272
#define OFF_K 30720
#define OFF_VT 39168
#define RET_FLOATS 47872
#define RET_SMEM (RET_FLOATS * 4)

__global__ void __launch_bounds__(256, 1) k_ret(
    const float* __restrict__ wq, const float* __restrict__ bq,
    const float* __restrict__ wk, const float* __restrict__ bk,
    const float* __restrict__ wv, const float* __restrict__ bv,
    const float* __restrict__ gnw, const float* __restrict__ gnb,
    const float* __restrict__ gam,
    const float* __restrict__ lnw, const float* __restrict__ lnb) {
    extern __shared__ float sm[];
    float* hs = sm + OFF_HS;   // [64][132] h (tf32), later Ss [64][68]
    float* wb = sm + OFF_WB;   // [384][36] weight k-chunk, later obuf [64][132]
    float* Qs = sm + OFF_Q;    // [64][132]
    float* Ks = sm + OFF_K;    // [64][132]
    float* Vt = sm + OFF_VT;   // [128][68] V transposed
    float* Ss = sm + OFF_HS;
    float* ob = sm + OFF_WB;
    __shared__ float cbias[384];
    __shared__ float gpow[64];
    __shared__ float shead[8];
    __shared__ float smean[4], srstd[4];

    int tid = threadIdx.x, lane = tid & 31, w = tid >> 5, g = lane >> 2, tg = lane & 3;
    int bn = blockIdx.x;

    for (int e = tid; e < 384; e += 256)
        cbias[e] = e < 128 ? bq[e] : (e < 256 ? bk[e - 128] : bv[e - 256]);
    if (tid < 64) gpow[tid] = powf(gam[0], (float)tid);
    if (tid < 8) shead[tid] = 0.f;

    const float* hb = g_h + (size_t)bn * (TT * DD);
    for (int e = tid; e < 2048; e += 256) {
        float4 v = ((const float4*)hb)[e];
        int r = e >> 5, c4 = (e & 31) * 4;
        float* dst = hs + r * LDH + c4;
        dst[0] = tf32f(v.x); dst[1] = tf32f(v.y); dst[2] = tf32f(v.z); dst[3] = tf32f(v.w);
    }

    float c[4][6][4];
#pragma unroll
    for (int mt = 0; mt < 4; mt++)
#pragma unroll
        for (int nt = 0; nt < 6; nt++)
#pragma unroll
            for (int ci = 0; ci < 4; ci++) c[mt][nt][ci] = 0.f;

    for (int kc = 0; kc < 128; kc += 32) {
        __syncthreads();
        for (int e = tid; e < 3072; e += 256) {
            int r = e >> 3, k4 = (e & 7) * 4;
            const float* src =
                (r < 128) ? (wq + r * 128) : ((r < 256) ? (wk + (r - 128) * 128)
                                                        : (wv + (r - 256) * 128));
            float4 v = *(const float4*)(src + kc + k4);
            float* dst = wb + r * LDW + k4;
            dst[0] = tf32f(v.x); dst[1] = tf32f(v.y); dst[2] = tf32f(v.z); dst[3] = tf32f(v.w);
        }
        __syncthreads();
#pragma unroll
        for (int ks = 0; ks < 4; ks++) {
            int kk = kc + ks * 8;
            unsigned a[4][4];
#pragma unroll
            for (int mt = 0; mt < 4; mt++) {
                a[mt][0] = __float_as_uint(hs[(mt * 16 + g) * LDH + kk + tg]);
                a[mt][1] = __float_as_uint(hs[(mt * 16 + 8 + g) * LDH + kk + tg]);
                a[mt][2] = __float_as_uint(hs[(mt * 16 + g) * LDH + kk + tg + 4]);
                a[mt][3] = __float_as_uint(hs[(mt * 16 + 8 + g) * LDH + kk + tg + 4]);
            }
#pragma unroll
            for (int nt = 0; nt < 6; nt++) {
                int nc = w * 48 + nt * 8 + g;
                unsigned b0 = __float_as_uint(wb[nc * LDW + ks * 8 + tg]);
                unsigned b1 = __float_as_uint(wb[nc * LDW + ks * 8 + tg + 4]);
#pragma unroll
                for (int mt = 0; mt < 4; mt++)
                    MMA_TF32(c[mt][nt], a[mt][0], a[mt][1], a[mt][2], a[mt][3], b0, b1);
            }
        }
    }

    // QKV epilogue: bias, tf32, scatter to Qs/Ks/Vt
#pragma unroll
    for (int mt = 0; mt < 4; mt++)
#pragma unroll
        for (int nt = 0; nt < 6; nt++) {
            int gc0 = w * 48 + nt * 8 + 2 * tg;
#pragma unroll
            for (int ci = 0; ci < 4; ci++) {
                int r = mt * 16 + g + ((ci >= 2) ? 8 : 0);
                int gc = gc0 + (ci & 1);
                float tv = tf32f(c[mt][nt][ci] + cbias[gc]);
                if (gc < 128) Qs[r * LDH + gc] = tv;
                else if (gc < 256) Ks[r * LDH + gc - 128] = tv;
                else Vt[(gc - 256) * LDVT + r] = tv;
            }
        }
    __syncthreads();

    // per-head retention
    for (int hh = 0; hh < HH; hh++) {
        int hb0 = hh * 32;
        // S = Q Kt (m64 n64 k32); warp w owns n-tile w
        float scC[4][4];
#pragma unroll
        for (int mt = 0; mt < 4; mt++)
#pragma unroll
            for (int ci = 0; ci < 4; ci++) scC[mt][ci] = 0.f;
#pragma unroll
        for (int ks = 0; ks < 4; ks++) {
            int kk = hb0 + ks * 8;
            unsigned a[4][4];
#pragma unroll
            for (int mt = 0; mt < 4; mt++) {
                a[mt][0] = __float_as_uint(Qs[(mt * 16 + g) * LDH + kk + tg]);
                a[mt][1] = __float_as_uint(Qs[(mt * 16 + 8 + g) * LDH + kk + tg]);
                a[mt][2] = __float_as_uint(Qs[(mt * 16 + g) * LDH + kk + tg + 4]);
                a[mt][3] = __float_as_uint(Qs[(mt * 16 + 8 + g) * LDH + kk + tg + 4]);
            }
            int nc = w * 8 + g;
            unsigned b0 = __float_as_uint(Ks[nc * LDH + kk + tg]);
            unsigned b1 = __float_as_uint(Ks[nc * LDH + kk + tg + 4]);
#pragma unroll
            for (int mt = 0; mt < 4; mt++)
                MMA_TF32(scC[mt], a[mt][0], a[mt][1], a[mt][2], a[mt][3], b0, b1);
        }
        // decay + store S (tf32)
#pragma unroll
        for (int mt = 0; mt < 4; mt++)
#pragma unroll
            for (int ci = 0; ci < 4; ci++) {
                int q = mt * 16 + g + ((ci >= 2) ? 8 : 0);
                int kk2 = w * 8 + 2 * tg + (ci & 1);
                float v = (kk2 <= q) ? scC[mt][ci] * gpow[q - kk2] : 0.f;
                Ss[q * LDSS + kk2] = tf32f(v);
            }
        __syncthreads();

        // O = S V (m64 n32 k64); warp: mt_o = w&3, n-pair = w>>2
        int mt_o = w & 3, ntp = w >> 2;
        float oc[2][4];
#pragma unroll
        for (int ntl = 0; ntl < 2; ntl++)
#pragma unroll
            for (int ci = 0; ci < 4; ci++) oc[ntl][ci] = 0.f;
#pragma unroll
        for (int ks = 0; ks < 8; ks++) {
            int kk = ks * 8;
            unsigned a0 = __float_as_uint(Ss[(mt_o * 16 + g) * LDSS + kk + tg]);
            unsigned a1 = __float_as_uint(Ss[(mt_o * 16 + 8 + g) * LDSS + kk + tg]);
            unsigned a2 = __float_as_uint(Ss[(mt_o * 16 + g) * LDSS + kk + tg + 4]);
            unsigned a3 = __float_as_uint(Ss[(mt_o * 16 + 8 + g) * LDSS + kk + tg + 4]);
#pragma unroll
            for (int ntl = 0; ntl < 2; ntl++) {
                int nc = hb0 + ntp * 16 + ntl * 8 + g;
                unsigned b0 = __float_as_uint(Vt[nc * LDVT + kk + tg]);
                unsigned b1 = __float_as_uint(Vt[nc * LDVT + kk + tg + 4]);
                MMA_TF32(oc[ntl], a0, a1, a2, a3, b0, b1);
            }
        }
        // stats + store to obuf
        float s1 = 0.f, s2 = 0.f;
#pragma unroll
        for (int ntl = 0; ntl < 2; ntl++)
#pragma unroll
            for (int ci = 0; ci < 4; ci++) {
                float v = oc[ntl][ci];
                s1 += v; s2 += v * v;
                int r = mt_o * 16 + g + ((ci >= 2) ? 8 : 0);
                int col = hb0 + ntp * 16 + ntl * 8 + 2 * tg + (ci & 1);
                ob[r * LDO + col] = v;
            }
#pragma unroll
        for (int o = 16; o; o >>= 1) {
            s1 += __shfl_xor_sync(0xffffffffu, s1, o);
            s2 += __shfl_xor_sync(0xffffffffu, s2, o);
        }
        if (lane == 0) {
            atomicAdd(&shead[hh * 2], s1);
            atomicAdd(&shead[hh * 2 + 1], s2);
        }
        __syncthreads();
    }

    if (tid < 4) {
        float mean = shead[tid * 2] * (1.0f / 2048.0f);
        float var = shead[tid * 2 + 1] * (1.0f / 2048.0f) - mean * mean;
        smean[tid] = mean;
        srstd[tid] = rsqrtf(var + EPS);
    }
    __syncthreads();

    // GN apply + LayerNorm over D, write g_ret
    float* go = g_ret + (size_t)bn * (TT * DD);
    for (int r8 = 0; r8 < 8; r8++) {
        int t = w * 8 + r8;
        float4 v = *(float4*)&ob[t * LDO + lane * 4];
        float vv[4];
        float* vp = &v.x;
#pragma unroll
        for (int j = 0; j < 4; j++) {
            int cc = lane * 4 + j;
            int hx = cc >> 5;
            vv[j] = (vp[j] - smean[hx]) * srstd[hx] * gnw[cc] + gnb[cc];
        }
        float s1 = vv[0] + vv[1] + vv[2] + vv[3];
        float s2 = vv[0] * vv[0] + vv[1] * vv[1] + vv[2] * vv[2] + vv[3] * vv[3];
#pragma unroll
        for (int o = 16; o; o >>= 1) {
            s1 += __shfl_xor_sync(0xffffffffu, s1, o);
            s2 += __shfl_xor_sync(0xffffffffu, s2, o);
        }
        float mu = s1 * (1.0f / 128.0f);
        float rs = rsqrtf(s2 * (1.0f / 128.0f) - mu * mu + EPS);
        float4 o4;
        float* op = &o4.x;
#pragma unroll
        for (int j = 0; j < 4; j++) {
            int cc = lane * 4 + j;
            op[j] = (vv[j] - mu) * rs * lnw[cc] + lnb[cc];
        }
        *(float4*)&go[t * DD + lane * 4] = o4;
    }
}

// ---------------- diffusion step 0 ----------------
#define DIFF0_SMEM ((128 * 129 + 128) * 4)
__global__ void k_diff0(const float* __restrict__ dw, const float* __restrict__ convw) {
    extern __shared__ float sm[];
    float* dwt = sm;
    float* hl = sm + 128 * 129;
    int bn = blockIdx.x;
    int tid = threadIdx.x;
    hl[tid] = g_ret[((size_t)bn * TT + (TT - 1)) * DD + tid];
    for (int e = tid; e < DD * DD; e += 128) {
        int ddw = e >> 7, k = e & 127;
        dwt[k * 129 + ddw] = dw[e];
    }
    __syncthreads();
    float s = 0.f;
    for (int k = 0; k < DD; k++) s += hl[k] * dwt[k * 129 + tid];
    size_t idx = (size_t)bn * DD + tid;
    g_cur_a[idx] = s;
    g_acc[idx] = convw[0] * s;
}

// ---------------- diffusion hop ----------------
__global__ void k_hop(const float* __restrict__ convw, int kidx,
                      const float* __restrict__ convb, int dir, int last) {
    int b = blockIdx.y, i0 = blockIdx.x * 8;
    int d = threadIdx.x & 127, ih = threadIdx.x >> 7;
    __shared__ float a[8][64];
    const float* curin = dir ? g_cur_b : g_cur_a;
    float* curout = dir ? g_cur_a : g_cur_b;
    const float* curb = curin + (size_t)b * NN * DD;
    float acc[4] = {0.f, 0.f, 0.f, 0.f};
    for (int jc = 0; jc < NN; jc += 64) {
        __syncthreads();
        for (int e = threadIdx.x; e < 8 * 64; e += 256) {
            int r = e >> 6, jj = e & 63;
            a[r][jj] = g_adjn[((size_t)b * NN + i0 + r) * NN + jc + jj];
        }
        __syncthreads();
        for (int jj = 0; jj < 64; jj += 4) {
            float c0 = curb[(size_t)(jc + jj + 0) * DD + d];
            float c1 = curb[(size_t)(jc + jj + 1) * DD + d];
            float c2 = curb[(size_t)(jc + jj + 2) * DD + d];
            float c3 = curb[(size_t)(jc + jj + 3) * DD + d];
#pragma unroll
            for (int r = 0; r < 4; r++) {
                float4 av4 = *(const float4*)&a[ih * 4 + r][jj];
                acc[r] += av4.x * c0 + av4.y * c1 + av4.z * c2 + av4.w * c3;
            }
        }
    }
    float cw = convw[kidx];
#pragma unroll
    for (int r = 0; r < 4; r++) {
        int i = i0 + ih * 4 + r;
        size_t idx = ((size_t)b * NN + i) * DD + d;
        curout[idx] = acc[r];
        float av = g_acc[idx] + cw * acc[r];
        if (last) {
            av += convb[0];
            g_hdiff[idx] = lrelu(av);
        } else {
            g_acc[idx] = av;
        }
    }
}

// ---------------- MLP fusion (tf32 mma) ----------------
#define MLP_FLOATS (8448 + 16896)
#define MLP_SMEM (MLP_FLOATS * 4)
__global__ void __launch_bounds__(256, 2) k_mlp(const float* __restrict__ mw,
                                                const float* __restrict__ mb) {
    extern __shared__ float sm[];
    float* hs = sm;            // [64][132] tf32
    float* ws = sm + 8448;     // [128][132] tf32, later obuf [64][132]
    __shared__ float bias2[128];
    __shared__ float hds[128];
    int tid = threadIdx.x, lane = tid & 31, w = tid >> 5, g = lane >> 2, tg = lane & 3;
    int bn = blockIdx.x;

    const float* rb = g_ret + (size_t)bn * (TT * DD);
    for (int e = tid; e < 2048; e += 256) {
        float4 v = ((const float4*)rb)[e];
        int r = e >> 5, c4 = (e & 31) * 4;
        float* dst = hs + r * LDH + c4;
        dst[0] = tf32f(v.x); dst[1] = tf32f(v.y); dst[2] = tf32f(v.z); dst[3] = tf32f(v.w);
    }
    for (int e = tid; e < 4096; e += 256) {
        int r = e >> 5, k4 = (e & 31) * 4;
        float4 v = *(const float4*)(mw + (size_t)r * 256 + k4);
        float* dst = ws + r * LDH + k4;
        dst[0] = tf32f(v.x); dst[1] = tf32f(v.y); dst[2] = tf32f(v.z); dst[3] = tf32f(v.w);
    }
    if (tid < 128) hds[tid] = g_hdiff[(size_t)bn * DD + tid];
    __syncthreads();

    // bias2[d] = sum_k mw[d][128+k]*hdiff[k] + mb[d]  (warps 0-3)
    if (w < 4) {
        float4 hv = *(const float4*)&hds[lane * 4];
        for (int i = 0; i < 32; i++) {
            int d = w * 32 + i;
            float4 wv = *(const float4*)(mw + (size_t)d * 256 + 128 + lane * 4);
            float s = wv.x * hv.x + wv.y * hv.y + wv.z * hv.z + wv.w * hv.w;
#pragma unroll
            for (int o = 16; o; o >>= 1) s += __shfl_xor_sync(0xffffffffu, s, o);
            if (lane == 0) bias2[d] = s + mb[d];
        }
    }

    float c[4][2][4];
#pragma unroll
    for (int mt = 0; mt < 4; mt++)
#pragma unroll
        for (int nt = 0; nt < 2; nt++)
#pragma unroll
            for (int ci = 0; ci < 4; ci++) c[mt][nt][ci] = 0.f;

#pragma unroll
    for (int ks = 0; ks < 16; ks++) {
        int kk = ks * 8;
        unsigned a[4][4];
#pragma unroll
        for (int mt = 0; mt < 4; mt++) {
            a[mt][0] = __float_as_uint(hs[(mt * 16 + g) * LDH + kk + tg]);
            a[mt][1] = __float_as_uint(hs[(mt * 16 + 8 + g) * LDH + kk + tg]);
            a[mt][2] = __float_as_uint(hs[(mt * 16 + g) * LDH + kk + tg + 4]);
            a[mt][3] = __float_as_uint(hs[(mt * 16 + 8 + g) * LDH + kk + tg + 4]);
        }
#pragma unroll
        for (int nt = 0; nt < 2; nt++) {
            int nc = w * 16 + nt * 8 + g;
            unsigned b0 = __float_as_uint(ws[nc * LDH + kk + tg]);
            unsigned b1 = __float_as_uint(ws[nc * LDH + kk + tg + 4]);
#pragma unroll
            for (int mt = 0; mt < 4; mt++)
                MMA_TF32(c[mt][nt], a[mt][0], a[mt][1], a[mt][2], a[mt][3], b0, b1);
        }
    }
    __syncthreads();
    // epilogue -> stage in ws region
    float* ob = ws;
#pragma unroll
    for (int mt = 0; mt < 4; mt++)
#pragma unroll
        for (int nt = 0; nt < 2; nt++) {
            int col0 = w * 16 + nt * 8 + 2 * tg;
#pragma unroll
            for (int ci = 0; ci < 4; ci++) {
                int r = mt * 16 + g + ((ci >= 2) ? 8 : 0);
                int col = col0 + (ci & 1);
                ob[r * LDH + col] = lrelu(c[mt][nt][ci] + bias2[col]);
            }
        }
    __syncthreads();
    float* obuf = g_h + (size_t)bn * (TT * DD);
    for (int e = tid; e < 2048; e += 256) {
        int r = e >> 5, c4 = (e & 31) * 4;
        *(float4*)&obuf[r * DD + c4] = *(float4*)&ob[r * LDH + c4];
    }
}

// ---------------- head ----------------
__global__ void k_head(const float* __restrict__ h1w, const float* __restrict__ h1b,
                       const float* __restrict__ h2w, const float* __restrict__ h2b,
                       float* __restrict__ out) {
    __shared__ float wt[128 * 65];
    __shared__ float lr[128];
    __shared__ float red[2];
    int bn = blockIdx.x;
    int tid = threadIdx.x;
    for (int e = tid; e < 128; e += 64)
        lr[e] = g_h[((size_t)bn * TT + (TT - 1)) * DD + e];
    for (int e = tid; e < 64 * 128; e += 64) {
        int jj = e >> 7, k = e & 127;
        wt[k * 65 + jj] = h1w[e];
    }
    __syncthreads();
    float s = 0.f;
    for (int k = 0; k < 128; k++) s += lr[k] * wt[k * 65 + tid];
    s += h1b[tid];
    s = lrelu(s);
    s *= h2w[tid];
#pragma unroll
    for (int o = 16; o; o >>= 1) s += __shfl_down_sync(0xffffffffu, s, o);
    if ((tid & 31) == 0) red[tid >> 5] = s;
    __syncthreads();
    if (tid == 0) out[bn] = red[0] + red[1] + h2b[0];
}

// ---------------- launch ----------------
extern "C" void kernel_launch(void* const* d_in, const int* in_sizes, int n_in,
                              void* d_out, int out_size) {
    const float* x      = (const float*)d_in[0];
    const float* adj    = (const float*)d_in[1];
    const float* proj_w = (const float*)d_in[2];
    const float* proj_b = (const float*)d_in[3];
    const float* pos    = (const float*)d_in[4];
    const float* diff_w = (const float*)d_in[5];
    const float* conv_w = (const float*)d_in[6];
    const float* conv_b = (const float*)d_in[7];
    const float* wq_w   = (const float*)d_in[8];
    const float* wq_b   = (const float*)d_in[9];
    const float* wk_w   = (const float*)d_in[10];
    const float* wk_b   = (const float*)d_in[11];
    const float* wv_w   = (const float*)d_in[12];
    const float* wv_b   = (const float*)d_in[13];
    const float* gn_w   = (const float*)d_in[14];
    const float* gn_b   = (const float*)d_in[15];
    const float* gamma  = (const float*)d_in[16];
    const float* ln_w   = (const float*)d_in[17];
    const float* ln_b   = (const float*)d_in[18];
    const float* mlp_w  = (const float*)d_in[19];
    const float* mlp_b  = (const float*)d_in[20];
    const float* h1w    = (const float*)d_in[21];
    const float* h1b    = (const float*)d_in[22];
    const float* h2w    = (const float*)d_in[23];
    const float* h2b    = (const float*)d_in[24];

    cudaFuncSetAttribute(k_ret, cudaFuncAttributeMaxDynamicSharedMemorySize, RET_SMEM);
    cudaFuncSetAttribute(k_mlp, cudaFuncAttributeMaxDynamicSharedMemorySize, MLP_SMEM);
    cudaFuncSetAttribute(k_diff0, cudaFuncAttributeMaxDynamicSharedMemorySize, DIFF0_SMEM);

    k_proj<<<BN * TT, 128>>>(x, proj_w, proj_b, pos);
    k_adjn<<<BB * NN, 256>>>(adj);

    for (int l = 0; l < 2; l++) {
        k_ret<<<BN, 256, RET_SMEM>>>(
            wq_w + l * DD * DD, wq_b + l * DD, wk_w + l * DD * DD, wk_b + l * DD,
            wv_w + l * DD * DD, wv_b + l * DD, gn_w + l * DD, gn_b + l * DD,
            gamma + l, ln_w + l * DD, ln_b + l * DD);
        k_diff0<<<BB * NN, 128, DIFF0_SMEM>>>(diff_w + l * DD * DD, conv_w + l * 3);
        k_hop<<<dim3(NN / 8, BB), 256>>>(conv_w + l * 3, 1, conv_b + l, 0, 0);
        k_hop<<<dim3(NN / 8, BB), 256>>>(conv_w + l * 3, 2, conv_b + l, 1, 1);
        k_mlp<<<BN, 256, MLP_SMEM>>>(mlp_w + (size_t)l * DD * 2 * DD, mlp_b + l * DD);
    }
    k_head<<<BN, 64>>>(h1w, h1b, h2w, h2b, (float*)d_out);
}

// round 3
// speedup vs baseline: 1.8258x; 1.3778x over previous
#include <cuda_runtime.h>
#include <math.h>

#define BB 4
#define NN 512
#define BN 2048
#define TT 64
#define DD 128
#define HH 4
#define HD 32
#define EPS 1e-5f
#define LSLOPE 0.2f

__device__ float g_h[BN * TT * DD];
__device__ float g_ret[BN * TT * DD];
__device__ float g_adjn[BB * NN * NN];
__device__ float g_cur_a[BB * NN * DD];
__device__ float g_cur_b[BB * NN * DD];
__device__ float g_acc[BB * NN * DD];
__device__ float g_hdiff[BB * NN * DD];

__device__ __forceinline__ float lrelu(float v) { return v > 0.f ? v : LSLOPE * v; }

__device__ __forceinline__ float tf32f(float x) {
    unsigned u;
    asm("cvt.rna.tf32.f32 %0, %1;" : "=r"(u) : "f"(x));
    return __uint_as_float(u);
}

#define MMA_TF32(C, A0, A1, A2, A3, B0, B1)                                             \
    asm volatile(                                                                       \
        "mma.sync.aligned.m16n8k8.row.col.f32.tf32.tf32.f32 "                           \
        "{%0,%1,%2,%3},{%4,%5,%6,%7},{%8,%9},{%0,%1,%2,%3};"                            \
        : "+f"((C)[0]), "+f"((C)[1]), "+f"((C)[2]), "+f"((C)[3])                        \
        : "r"(A0), "r"(A1), "r"(A2), "r"(A3), "r"(B0), "r"(B1))

// ---------------- proj + pos: one block per bn ----------------
__global__ void k_proj(const float* __restrict__ x, const float* __restrict__ pw,
                       const float* __restrict__ pb, const float* __restrict__ pos) {
    __shared__ float sx[TT * 8];
    int bn = blockIdx.x;
    int d = threadIdx.x;  // 128
    for (int e = d; e < TT * 8; e += 128) sx[e] = x[(size_t)bn * TT * 8 + e];
    float4 w0 = *(const float4*)(pw + d * 8);
    float4 w1 = *(const float4*)(pw + d * 8 + 4);
    float bv = pb[d];
    __syncthreads();
    float* ob = g_h + (size_t)bn * (TT * DD);
    for (int t = 0; t < TT; t++) {
        const float* xr = &sx[t * 8];
        float s = bv + pos[t * DD + d];
        s += xr[0] * w0.x + xr[1] * w0.y + xr[2] * w0.z + xr[3] * w0.w;
        s += xr[4] * w1.x + xr[5] * w1.y + xr[6] * w1.z + xr[7] * w1.w;
        ob[t * DD + d] = s;
    }
}

// ---------------- adj row-normalize ----------------
__global__ void k_adjn(const float* __restrict__ adj) {
    int row = blockIdx.x;
    __shared__ float red[8];
    const float* ar = adj + (size_t)row * NN;
    float s = 0.f;
    for (int j = threadIdx.x; j < NN; j += 256) s += ar[j];
#pragma unroll
    for (int o = 16; o; o >>= 1) s += __shfl_down_sync(0xffffffffu, s, o);
    if ((threadIdx.x & 31) == 0) red[threadIdx.x >> 5] = s;
    __syncthreads();
    if (threadIdx.x == 0) {
        float t = 0.f;
#pragma unroll
        for (int w = 0; w < 8; w++) t += red[w];
        red[0] = 1.0f / (t + 1e-9f);
    }
    __syncthreads();
    float inv = red[0];
    for (int j = threadIdx.x; j < NN; j += 256) g_adjn[(size_t)row * NN + j] = ar[j] * inv;
}

// ---------------- fused retention (per-head, 2 CTA/SM) + GN + LN ----------------
#define LDH 132
#define LDWH 36
#define LDVT 68
#define LDSS 68
#define OFF_WBH 8448
#define OFF_QH 11904
#define OFF_KH 14208
#define OFF_VTH 16512
#define OFF_SS 18688
#define RET_FLOATS 23040
#define RET_SMEM (RET_FLOATS * 4)

__global__ void __launch_bounds__(256, 2) k_ret(
    const float* __restrict__ wq, const float* __restrict__ bq,
    const float* __restrict__ wk, const float* __restrict__ bk,
    const float* __restrict__ wv, const float* __restrict__ bv,
    const float* __restrict__ gnw, const float* __restrict__ gnb,
    const float* __restrict__ gam,
    const float* __restrict__ lnw, const float* __restrict__ lnb) {
    extern __shared__ float sm[];
    float* hs = sm;             // [64][132]
    float* wbh = sm + OFF_WBH;  // [96][36]
    float* Qh = sm + OFF_QH;    // [64][36]
    float* Kh = sm + OFF_KH;    // [64][36]
    float* Vth = sm + OFF_VTH;  // [32][68]
    float* Ss = sm + OFF_SS;    // [64][68]
    __shared__ float cbias[384];
    __shared__ float gpow[64];
    __shared__ float shead[8];
    __shared__ float smean[4], srstd[4];
    __shared__ float sum1[64], sum2[64];

    int tid = threadIdx.x, lane = tid & 31, w = tid >> 5, g = lane >> 2, tg = lane & 3;
    int bn = blockIdx.x;

    for (int e = tid; e < 384; e += 256)
        cbias[e] = e < 128 ? bq[e] : (e < 256 ? bk[e - 128] : bv[e - 256]);
    if (tid < 64) {
        gpow[tid] = powf(gam[0], (float)tid);
        sum1[tid] = 0.f;
        sum2[tid] = 0.f;
    }
    if (tid < 8) shead[tid] = 0.f;

    const float* hb = g_h + (size_t)bn * (TT * DD);
    for (int e = tid; e < 2048; e += 256) {
        float4 v = ((const float4*)hb)[e];
        int r = e >> 5, c4 = (e & 31) * 4;
        float* dst = hs + r * LDH + c4;
        dst[0] = tf32f(v.x); dst[1] = tf32f(v.y); dst[2] = tf32f(v.z); dst[3] = tf32f(v.w);
    }

    float oreg[HH][2][4];
    int mq = w & 3, nqh = w >> 2;      // phase A layout
    int mt_o = w & 3, ntp = w >> 2;    // phase C layout

#pragma unroll
    for (int hh = 0; hh < HH; hh++) {
        int hb0 = hh * HD;
        // ---- A: QKV_h = h @ W_h^T  (m64 n96 k128)
        float c[6][4];
#pragma unroll
        for (int nt = 0; nt < 6; nt++)
#pragma unroll
            for (int ci = 0; ci < 4; ci++) c[nt][ci] = 0.f;

        for (int kc = 0; kc < 128; kc += 32) {
            __syncthreads();
            for (int e = tid; e < 768; e += 256) {
                int r = e >> 3, k4 = (e & 7) * 4;
                const float* src = (r < 32) ? (wq + (hb0 + r) * DD)
                                 : (r < 64) ? (wk + (hb0 + r - 32) * DD)
                                            : (wv + (hb0 + r - 64) * DD);
                float4 v = *(const float4*)(src + kc + k4);
                float* dst = wbh + r * LDWH + k4;
                dst[0] = tf32f(v.x); dst[1] = tf32f(v.y);
                dst[2] = tf32f(v.z); dst[3] = tf32f(v.w);
            }
            __syncthreads();
#pragma unroll
            for (int ks = 0; ks < 4; ks++) {
                int kk = ks * 8;
                unsigned a0 = __float_as_uint(hs[(mq * 16 + g) * LDH + kc + kk + tg]);
                unsigned a1 = __float_as_uint(hs[(mq * 16 + 8 + g) * LDH + kc + kk + tg]);
                unsigned a2 = __float_as_uint(hs[(mq * 16 + g) * LDH + kc + kk + tg + 4]);
                unsigned a3 = __float_as_uint(hs[(mq * 16 + 8 + g) * LDH + kc + kk + tg + 4]);
#pragma unroll
                for (int nt = 0; nt < 6; nt++) {
                    int nc = nqh * 48 + nt * 8 + g;
                    unsigned b0 = __float_as_uint(wbh[nc * LDWH + kk + tg]);
                    unsigned b1 = __float_as_uint(wbh[nc * LDWH + kk + tg + 4]);
                    MMA_TF32(c[nt], a0, a1, a2, a3, b0, b1);
                }
            }
        }
        // epilogue -> Qh/Kh/Vth
#pragma unroll
        for (int nt = 0; nt < 6; nt++) {
            int gc0 = nqh * 48 + nt * 8 + 2 * tg;
#pragma unroll
            for (int ci = 0; ci < 4; ci++) {
                int r = mq * 16 + g + ((ci >= 2) ? 8 : 0);
                int gc = gc0 + (ci & 1);
                int bi = (gc < 32) ? (hb0 + gc) : (gc < 64) ? (128 + hb0 + gc - 32)
                                                            : (256 + hb0 + gc - 64);
                float tv = tf32f(c[nt][ci] + cbias[bi]);
                if (gc < 32) Qh[r * LDWH + gc] = tv;
                else if (gc < 64) Kh[r * LDWH + gc - 32] = tv;
                else Vth[(gc - 64) * LDVT + r] = tv;
            }
        }
        __syncthreads();

        // ---- B: S = Q K^T (m64 n64 k32), warp owns n-tile w
        float scC[4][4];
#pragma unroll
        for (int mt = 0; mt < 4; mt++)
#pragma unroll
            for (int ci = 0; ci < 4; ci++) scC[mt][ci] = 0.f;
#pragma unroll
        for (int ks = 0; ks < 4; ks++) {
            int kk = ks * 8;
            unsigned a[4][4];
#pragma unroll
            for (int mt = 0; mt < 4; mt++) {
                a[mt][0] = __float_as_uint(Qh[(mt * 16 + g) * LDWH + kk + tg]);
                a[mt][1] = __float_as_uint(Qh[(mt * 16 + 8 + g) * LDWH + kk + tg]);
                a[mt][2] = __float_as_uint(Qh[(mt * 16 + g) * LDWH + kk + tg + 4]);
                a[mt][3] = __float_as_uint(Qh[(mt * 16 + 8 + g) * LDWH + kk + tg + 4]);
            }
            int nc = w * 8 + g;
            unsigned b0 = __float_as_uint(Kh[nc * LDWH + kk + tg]);
            unsigned b1 = __float_as_uint(Kh[nc * LDWH + kk + tg + 4]);
#pragma unroll
            for (int mt = 0; mt < 4; mt++)
                MMA_TF32(scC[mt], a[mt][0], a[mt][1], a[mt][2], a[mt][3], b0, b1);
        }
#pragma unroll
        for (int mt = 0; mt < 4; mt++)
#pragma unroll
            for (int ci = 0; ci < 4; ci++) {
                int q = mt * 16 + g + ((ci >= 2) ? 8 : 0);
                int kk2 = w * 8 + 2 * tg + (ci & 1);
                float v = (kk2 <= q) ? scC[mt][ci] * gpow[q - kk2] : 0.f;
                Ss[q * LDSS + kk2] = tf32f(v);
            }
        __syncthreads();

        // ---- C: O = S V (m64 n32 k64)
#pragma unroll
        for (int ntl = 0; ntl < 2; ntl++)
#pragma unroll
            for (int ci = 0; ci < 4; ci++) oreg[hh][ntl][ci] = 0.f;
#pragma unroll
        for (int ks = 0; ks < 8; ks++) {
            int kk = ks * 8;
            unsigned a0 = __float_as_uint(Ss[(mt_o * 16 + g) * LDSS + kk + tg]);
            unsigned a1 = __float_as_uint(Ss[(mt_o * 16 + 8 + g) * LDSS + kk + tg]);
            unsigned a2 = __float_as_uint(Ss[(mt_o * 16 + g) * LDSS + kk + tg + 4]);
            unsigned a3 = __float_as_uint(Ss[(mt_o * 16 + 8 + g) * LDSS + kk + tg + 4]);
#pragma unroll
            for (int ntl = 0; ntl < 2; ntl++) {
                int nc = ntp * 16 + ntl * 8 + g;
                unsigned b0 = __float_as_uint(Vth[nc * LDVT + kk + tg]);
                unsigned b1 = __float_as_uint(Vth[nc * LDVT + kk + tg + 4]);
                MMA_TF32(oreg[hh][ntl], a0, a1, a2, a3, b0, b1);
            }
        }
        // GN stats for this head
        float s1 = 0.f, s2 = 0.f;
#pragma unroll
        for (int ntl = 0; ntl < 2; ntl++)
#pragma unroll
            for (int ci = 0; ci < 4; ci++) {
                float v = oreg[hh][ntl][ci];
                s1 += v; s2 += v * v;
            }
#pragma unroll
        for (int o = 16; o; o >>= 1) {
            s1 += __shfl_xor_sync(0xffffffffu, s1, o);
            s2 += __shfl_xor_sync(0xffffffffu, s2, o);
        }
        if (lane == 0) {
            atomicAdd(&shead[hh * 2], s1);
            atomicAdd(&shead[hh * 2 + 1], s2);
        }
        __syncthreads();
    }

    if (tid < 4) {
        float mean = shead[tid * 2] * (1.0f / 2048.0f);
        float var = shead[tid * 2 + 1] * (1.0f / 2048.0f) - mean * mean;
        smean[tid] = mean;
        srstd[tid] = rsqrtf(var + EPS);
    }
    __syncthreads();

    // GN apply in registers + per-row LN partials
    float p1[2] = {0.f, 0.f}, p2[2] = {0.f, 0.f};
#pragma unroll
    for (int hh = 0; hh < HH; hh++) {
        float mn = smean[hh], rs = srstd[hh];
#pragma unroll
        for (int ntl = 0; ntl < 2; ntl++)
#pragma unroll
            for (int ci = 0; ci < 4; ci++) {
                int col = hh * 32 + ntp * 16 + ntl * 8 + 2 * tg + (ci & 1);
                float v = (oreg[hh][ntl][ci] - mn) * rs * gnw[col] + gnb[col];
                oreg[hh][ntl][ci] = v;
                int half = (ci >= 2) ? 1 : 0;
                p1[half] += v;
                p2[half] += v * v;
            }
    }
    // reduce over the 4 tg threads of the quad (lanes differ only in bits 0-1)
#pragma unroll
    for (int o = 1; o <= 2; o <<= 1) {
        p1[0] += __shfl_xor_sync(0xffffffffu, p1[0], o);
        p1[1] += __shfl_xor_sync(0xffffffffu, p1[1], o);
        p2[0] += __shfl_xor_sync(0xffffffffu, p2[0], o);
        p2[1] += __shfl_xor_sync(0xffffffffu, p2[1], o);
    }
    int r0 = mt_o * 16 + g, r1 = r0 + 8;
    if (tg == 0) {
        atomicAdd(&sum1[r0], p1[0]);
        atomicAdd(&sum2[r0], p2[0]);
        atomicAdd(&sum1[r1], p1[1]);
        atomicAdd(&sum2[r1], p2[1]);
    }
    __syncthreads();

    float mu0 = sum1[r0] * (1.0f / 128.0f);
    float rs0 = rsqrtf(sum2[r0] * (1.0f / 128.0f) - mu0 * mu0 + EPS);
    float mu1 = sum1[r1] * (1.0f / 128.0f);
    float rs1 = rsqrtf(sum2[r1] * (1.0f / 128.0f) - mu1 * mu1 + EPS);

    float* go = g_ret + (size_t)bn * (TT * DD);
#pragma unroll
    for (int hh = 0; hh < HH; hh++) {
#pragma unroll
        for (int ntl = 0; ntl < 2; ntl++) {
            int cb = hh * 32 + ntp * 16 + ntl * 8 + 2 * tg;
            float lw0 = lnw[cb], lb0 = lnb[cb];
            float lw1 = lnw[cb + 1], lb1 = lnb[cb + 1];
            float2 v0, v1;
            v0.x = (oreg[hh][ntl][0] - mu0) * rs0 * lw0 + lb0;
            v0.y = (oreg[hh][ntl][1] - mu0) * rs0 * lw1 + lb1;
            v1.x = (oreg[hh][ntl][2] - mu1) * rs1 * lw0 + lb0;
            v1.y = (oreg[hh][ntl][3] - mu1) * rs1 * lw1 + lb1;
            *(float2*)&go[r0 * DD + cb] = v0;
            *(float2*)&go[r1 * DD + cb] = v1;
        }
    }
}

// ---------------- diffusion step 0 as batched GEMM ----------------
// C[2048,128] = h_last @ dw^T ; grid 32 blocks x 64 rows
#define DG_SMEM ((8448 + 16896) * 4)
__global__ void __launch_bounds__(256, 2) k_diffg(const float* __restrict__ dw,
                                                  const float* __restrict__ convw) {
    extern __shared__ float sm[];
    float* hs = sm;          // [64][132]
    float* ws = sm + 8448;   // [128][132]
    int tid = threadIdx.x, lane = tid & 31, w = tid >> 5, g = lane >> 2, tg = lane & 3;
    int row0 = blockIdx.x * 64;

    for (int e = tid; e < 2048; e += 256) {
        int r = e >> 5, c4 = (e & 31) * 4;
        int bn = row0 + r;
        float4 v = *(const float4*)(g_ret + ((size_t)bn * TT + (TT - 1)) * DD + c4);
        float* dst = hs + r * LDH + c4;
        dst[0] = tf32f(v.x); dst[1] = tf32f(v.y); dst[2] = tf32f(v.z); dst[3] = tf32f(v.w);
    }
    for (int e = tid; e < 4096; e += 256) {
        int r = e >> 5, k4 = (e & 31) * 4;
        float4 v = *(const float4*)(dw + (size_t)r * DD + k4);
        float* dst = ws + r * LDH + k4;
        dst[0] = tf32f(v.x); dst[1] = tf32f(v.y); dst[2] = tf32f(v.z); dst[3] = tf32f(v.w);
    }
    __syncthreads();

    int mq = w & 3, nqh = w >> 2;
    float c[8][4];
#pragma unroll
    for (int nt = 0; nt < 8; nt++)
#pragma unroll
        for (int ci = 0; ci < 4; ci++) c[nt][ci] = 0.f;
#pragma unroll
    for (int ks = 0; ks < 16; ks++) {
        int kk = ks * 8;
        unsigned a0 = __float_as_uint(hs[(mq * 16 + g) * LDH + kk + tg]);
        unsigned a1 = __float_as_uint(hs[(mq * 16 + 8 + g) * LDH + kk + tg]);
        unsigned a2 = __float_as_uint(hs[(mq * 16 + g) * LDH + kk + tg + 4]);
        unsigned a3 = __float_as_uint(hs[(mq * 16 + 8 + g) * LDH + kk + tg + 4]);
#pragma unroll
        for (int nt = 0; nt < 8; nt++) {
            int nc = nqh * 64 + nt * 8 + g;
            unsigned b0 = __float_as_uint(ws[nc * LDH + kk + tg]);
            unsigned b1 = __float_as_uint(ws[nc * LDH + kk + tg + 4]);
            MMA_TF32(c[nt], a0, a1, a2, a3, b0, b1);
        }
    }
    float c0 = convw[0];
#pragma unroll
    for (int nt = 0; nt < 8; nt++) {
        int col0 = nqh * 64 + nt * 8 + 2 * tg;
#pragma unroll
        for (int ci = 0; ci < 4; ci++) {
            int r = mq * 16 + g + ((ci >= 2) ? 8 : 0);
            int col = col0 + (ci & 1);
            size_t idx = (size_t)(row0 + r) * DD + col;
            float v = c[nt][ci];
            g_cur_a[idx] = v;
            g_acc[idx] = c0 * v;
        }
    }
}

// ---------------- diffusion hop as tf32 GEMM ----------------
// per b: cur_out = adj_n @ cur_in ; grid (8 m-blocks of 64, B)
#define LDB_HOP 33
__global__ void __launch_bounds__(256, 2) k_hop(const float* __restrict__ convw, int kidx,
                                                const float* __restrict__ convb,
                                                int dir, int last) {
    __shared__ float As[64 * LDWH];       // [64][36]
    __shared__ float Bs[128 * LDB_HOP];   // [128][33]
    int tid = threadIdx.x, lane = tid & 31, w = tid >> 5, g = lane >> 2, tg = lane & 3;
    int b = blockIdx.y, i0 = blockIdx.x * 64;
    const float* curin = dir ? g_cur_b : g_cur_a;
    float* curout = dir ? g_cur_a : g_cur_b;
    const float* curb = curin + (size_t)b * NN * DD;
    const float* adjb = g_adjn + (size_t)b * NN * NN;

    int mq = w & 3, nqh = w >> 2;
    float c[8][4];
#pragma unroll
    for (int nt = 0; nt < 8; nt++)
#pragma unroll
        for (int ci = 0; ci < 4; ci++) c[nt][ci] = 0.f;

    for (int kc = 0; kc < NN; kc += 32) {
        __syncthreads();
        // A: adj[i0..i0+64][kc..kc+32]
        for (int e = tid; e < 512; e += 256) {
            int r = e >> 3, k4 = (e & 7) * 4;
            float4 v = *(const float4*)(adjb + (size_t)(i0 + r) * NN + kc + k4);
            float* dst = As + r * LDWH + k4;
            dst[0] = tf32f(v.x); dst[1] = tf32f(v.y); dst[2] = tf32f(v.z); dst[3] = tf32f(v.w);
        }
        // B: cur[kc..kc+32][0..128] transposed -> Bs[n][k]
        for (int e = tid; e < 1024; e += 256) {
            int kr = e >> 5, n4 = (e & 31) * 4;
            float4 v = *(const float4*)(curb + (size_t)(kc + kr) * DD + n4);
            Bs[(n4 + 0) * LDB_HOP + kr] = tf32f(v.x);
            Bs[(n4 + 1) * LDB_HOP + kr] = tf32f(v.y);
            Bs[(n4 + 2) * LDB_HOP + kr] = tf32f(v.z);
            Bs[(n4 + 3) * LDB_HOP + kr] = tf32f(v.w);
        }
        __syncthreads();
#pragma unroll
        for (int ks = 0; ks < 4; ks++) {
            int kk = ks * 8;
            unsigned a0 = __float_as_uint(As[(mq * 16 + g) * LDWH + kk + tg]);
            unsigned a1 = __float_as_uint(As[(mq * 16 + 8 + g) * LDWH + kk + tg]);
            unsigned a2 = __float_as_uint(As[(mq * 16 + g) * LDWH + kk + tg + 4]);
            unsigned a3 = __float_as_uint(As[(mq * 16 + 8 + g) * LDWH + kk + tg + 4]);
#pragma unroll
            for (int nt = 0; nt < 8; nt++) {
                int nc = nqh * 64 + nt * 8 + g;
                unsigned b0 = __float_as_uint(Bs[nc * LDB_HOP + kk + tg]);
                unsigned b1 = __float_as_uint(Bs[nc * LDB_HOP + kk + tg + 4]);
                MMA_TF32(c[nt], a0, a1, a2, a3, b0, b1);
            }
        }
    }
    float cw = convw[kidx];
    float cb = convb[0];
#pragma unroll
    for (int nt = 0; nt < 8; nt++) {
        int col0 = nqh * 64 + nt * 8 + 2 * tg;
#pragma unroll
        for (int ci = 0; ci < 4; ci++) {
            int r = mq * 16 + g + ((ci >= 2) ? 8 : 0);
            int col = col0 + (ci & 1);
            size_t idx = ((size_t)b * NN + i0 + r) * DD + col;
            float v = c[nt][ci];
            curout[idx] = v;
            float av = g_acc[idx] + cw * v;
            if (last) g_hdiff[idx] = lrelu(av + cb);
            else g_acc[idx] = av;
        }
    }
}

// ---------------- MLP fusion (tf32 mma) ----------------
#define MLP_SMEM ((8448 + 16896) * 4)
__global__ void __launch_bounds__(256, 2) k_mlp(const float* __restrict__ mw,
                                                const float* __restrict__ mb) {
    extern __shared__ float sm[];
    float* hs = sm;
    float* ws = sm + 8448;
    __shared__ float bias2[128];
    __shared__ float hds[128];
    int tid = threadIdx.x, lane = tid & 31, w = tid >> 5, g = lane >> 2, tg = lane & 3;
    int bn = blockIdx.x;

    const float* rb = g_ret + (size_t)bn * (TT * DD);
    for (int e = tid; e < 2048; e += 256) {
        float4 v = ((const float4*)rb)[e];
        int r = e >> 5, c4 = (e & 31) * 4;
        float* dst = hs + r * LDH + c4;
        dst[0] = tf32f(v.x); dst[1] = tf32f(v.y); dst[2] = tf32f(v.z); dst[3] = tf32f(v.w);
    }
    for (int e = tid; e < 4096; e += 256) {
        int r = e >> 5, k4 = (e & 31) * 4;
        float4 v = *(const float4*)(mw + (size_t)r * 256 + k4);
        float* dst = ws + r * LDH + k4;
        dst[0] = tf32f(v.x); dst[1] = tf32f(v.y); dst[2] = tf32f(v.z); dst[3] = tf32f(v.w);
    }
    if (tid < 128) hds[tid] = g_hdiff[(size_t)bn * DD + tid];
    __syncthreads();

    if (w < 4) {
        float4 hv = *(const float4*)&hds[lane * 4];
        for (int i = 0; i < 32; i++) {
            int d = w * 32 + i;
            float4 wv = *(const float4*)(mw + (size_t)d * 256 + 128 + lane * 4);
            float s = wv.x * hv.x + wv.y * hv.y + wv.z * hv.z + wv.w * hv.w;
#pragma unroll
            for (int o = 16; o; o >>= 1) s += __shfl_xor_sync(0xffffffffu, s, o);
            if (lane == 0) bias2[d] = s + mb[d];
        }
    }

    float c[4][2][4];
#pragma unroll
    for (int mt = 0; mt < 4; mt++)
#pragma unroll
        for (int nt = 0; nt < 2; nt++)
#pragma unroll
            for (int ci = 0; ci < 4; ci++) c[mt][nt][ci] = 0.f;

#pragma unroll
    for (int ks = 0; ks < 16; ks++) {
        int kk = ks * 8;
        unsigned a[4][4];
#pragma unroll
        for (int mt = 0; mt < 4; mt++) {
            a[mt][0] = __float_as_uint(hs[(mt * 16 + g) * LDH + kk + tg]);
            a[mt][1] = __float_as_uint(hs[(mt * 16 + 8 + g) * LDH + kk + tg]);
            a[mt][2] = __float_as_uint(hs[(mt * 16 + g) * LDH + kk + tg + 4]);
            a[mt][3] = __float_as_uint(hs[(mt * 16 + 8 + g) * LDH + kk + tg + 4]);
        }
#pragma unroll
        for (int nt = 0; nt < 2; nt++) {
            int nc = w * 16 + nt * 8 + g;
            unsigned b0 = __float_as_uint(ws[nc * LDH + kk + tg]);
            unsigned b1 = __float_as_uint(ws[nc * LDH + kk + tg + 4]);
#pragma unroll
            for (int mt = 0; mt < 4; mt++)
                MMA_TF32(c[mt][nt], a[mt][0], a[mt][1], a[mt][2], a[mt][3], b0, b1);
        }
    }
    __syncthreads();
    float* ob = ws;
#pragma unroll
    for (int mt = 0; mt < 4; mt++)
#pragma unroll
        for (int nt = 0; nt < 2; nt++) {
            int col0 = w * 16 + nt * 8 + 2 * tg;
#pragma unroll
            for (int ci = 0; ci < 4; ci++) {
                int r = mt * 16 + g + ((ci >= 2) ? 8 : 0);
                int col = col0 + (ci & 1);
                ob[r * LDH + col] = lrelu(c[mt][nt][ci] + bias2[col]);
            }
        }
    __syncthreads();
    float* obuf = g_h + (size_t)bn * (TT * DD);
    for (int e = tid; e < 2048; e += 256) {
        int r = e >> 5, c4 = (e & 31) * 4;
        *(float4*)&obuf[r * DD + c4] = *(float4*)&ob[r * LDH + c4];
    }
}

// ---------------- head ----------------
__global__ void k_head(const float* __restrict__ h1w, const float* __restrict__ h1b,
                       const float* __restrict__ h2w, const float* __restrict__ h2b,
                       float* __restrict__ out) {
    __shared__ float wt[128 * 65];
    __shared__ float lr[128];
    __shared__ float red[2];
    int bn = blockIdx.x;
    int tid = threadIdx.x;
    for (int e = tid; e < 128; e += 64)
        lr[e] = g_h[((size_t)bn * TT + (TT - 1)) * DD + e];
    for (int e = tid; e < 64 * 128; e += 64) {
        int jj = e >> 7, k = e & 127;
        wt[k * 65 + jj] = h1w[e];
    }
    __syncthreads();
    float s = 0.f;
    for (int k = 0; k < 128; k++) s += lr[k] * wt[k * 65 + tid];
    s += h1b[tid];
    s = lrelu(s);
    s *= h2w[tid];
#pragma unroll
    for (int o = 16; o; o >>= 1) s += __shfl_down_sync(0xffffffffu, s, o);
    if ((tid & 31) == 0) red[tid >> 5] = s;
    __syncthreads();
    if (tid == 0) out[bn] = red[0] + red[1] + h2b[0];
}

// ---------------- launch ----------------
extern "C" void kernel_launch(void* const* d_in, const int* in_sizes, int n_in,
                              void* d_out, int out_size) {
    const float* x      = (const float*)d_in[0];
    const float* adj    = (const float*)d_in[1];
    const float* proj_w = (const float*)d_in[2];
    const float* proj_b = (const float*)d_in[3];
    const float* pos    = (const float*)d_in[4];
    const float* diff_w = (const float*)d_in[5];
    const float* conv_w = (const float*)d_in[6];
    const float* conv_b = (const float*)d_in[7];
    const float* wq_w   = (const float*)d_in[8];
    const float* wq_b   = (const float*)d_in[9];
    const float* wk_w   = (const float*)d_in[10];
    const float* wk_b   = (const float*)d_in[11];
    const float* wv_w   = (const float*)d_in[12];
    const float* wv_b   = (const float*)d_in[13];
    const float* gn_w   = (const float*)d_in[14];
    const float* gn_b   = (const float*)d_in[15];
    const float* gamma  = (const float*)d_in[16];
    const float* ln_w   = (const float*)d_in[17];
    const float* ln_b   = (const float*)d_in[18];
    const float* mlp_w  = (const float*)d_in[19];
    const float* mlp_b  = (const float*)d_in[20];
    const float* h1w    = (const float*)d_in[21];
    const float* h1b    = (const float*)d_in[22];
    const float* h2w    = (const float*)d_in[23];
    const float* h2b    = (const float*)d_in[24];

    cudaFuncSetAttribute(k_ret, cudaFuncAttributeMaxDynamicSharedMemorySize, RET_SMEM);
    cudaFuncSetAttribute(k_mlp, cudaFuncAttributeMaxDynamicSharedMemorySize, MLP_SMEM);
    cudaFuncSetAttribute(k_diffg, cudaFuncAttributeMaxDynamicSharedMemorySize, DG_SMEM);

    k_proj<<<BN, 128>>>(x, proj_w, proj_b, pos);
    k_adjn<<<BB * NN, 256>>>(adj);

    for (int l = 0; l < 2; l++) {
        k_ret<<<BN, 256, RET_SMEM>>>(
            wq_w + l * DD * DD, wq_b + l * DD, wk_w + l * DD * DD, wk_b + l * DD,
            wv_w + l * DD * DD, wv_b + l * DD, gn_w + l * DD, gn_b + l * DD,
            gamma + l, ln_w + l * DD, ln_b + l * DD);
        k_diffg<<<BN / 64, 256, DG_SMEM>>>(diff_w + l * DD * DD, conv_w + l * 3);
        k_hop<<<dim3(NN / 64, BB), 256>>>(conv_w + l * 3, 1, conv_b + l, 0, 0);
        k_hop<<<dim3(NN / 64, BB), 256>>>(conv_w + l * 3, 2, conv_b + l, 1, 1);
        k_mlp<<<BN, 256, MLP_SMEM>>>(mlp_w + (size_t)l * DD * 2 * DD, mlp_b + l * DD);
    }
    k_head<<<BN, 64>>>(h1w, h1b, h2w, h2b, (float*)d_out);
}

// round 4
// speedup vs baseline: 2.3835x; 1.3054x over previous
#include <cuda_runtime.h>
#include <math.h>

#define BB 4
#define NN 512
#define BN 2048
#define TT 64
#define DD 128
#define HH 4
#define HD 32
#define EPS 1e-5f
#define LSLOPE 0.2f

__device__ float g_h[BN * TT * DD];
__device__ float g_ret[BN * TT * DD];
__device__ float g_adjn[BB * NN * NN];
__device__ float g_cur_a[BB * NN * DD];
__device__ float g_cur_b[BB * NN * DD];
__device__ float g_acc[BB * NN * DD];
__device__ float g_hdiff[BB * NN * DD];

__device__ __forceinline__ float lrelu(float v) { return v > 0.f ? v : LSLOPE * v; }

__device__ __forceinline__ float tf32f(float x) {
    unsigned u;
    asm("cvt.rna.tf32.f32 %0, %1;" : "=r"(u) : "f"(x));
    return __uint_as_float(u);
}

#define MMA_TF32(C, A0, A1, A2, A3, B0, B1)                                             \
    asm volatile(                                                                       \
        "mma.sync.aligned.m16n8k8.row.col.f32.tf32.tf32.f32 "                           \
        "{%0,%1,%2,%3},{%4,%5,%6,%7},{%8,%9},{%0,%1,%2,%3};"                            \
        : "+f"((C)[0]), "+f"((C)[1]), "+f"((C)[2]), "+f"((C)[3])                        \
        : "r"(A0), "r"(A1), "r"(A2), "r"(A3), "r"(B0), "r"(B1))

#define LDH 132
#define LDWH 36
#define LDVT 68
#define LDSS 68

// ---------------- proj + pos ----------------
__global__ void k_proj(const float* __restrict__ x, const float* __restrict__ pw,
                       const float* __restrict__ pb, const float* __restrict__ pos) {
    __shared__ float sx[TT * 8];
    int bn = blockIdx.x;
    int d = threadIdx.x;
    for (int e = d; e < TT * 8; e += 128) sx[e] = x[(size_t)bn * TT * 8 + e];
    float4 w0 = *(const float4*)(pw + d * 8);
    float4 w1 = *(const float4*)(pw + d * 8 + 4);
    float bv = pb[d];
    __syncthreads();
    float* ob = g_h + (size_t)bn * (TT * DD);
    for (int t = 0; t < TT; t++) {
        const float* xr = &sx[t * 8];
        float s = bv + pos[t * DD + d];
        s += xr[0] * w0.x + xr[1] * w0.y + xr[2] * w0.z + xr[3] * w0.w;
        s += xr[4] * w1.x + xr[5] * w1.y + xr[6] * w1.z + xr[7] * w1.w;
        ob[t * DD + d] = s;
    }
}

// ---------------- adj row-normalize ----------------
__global__ void k_adjn(const float* __restrict__ adj) {
    int row = blockIdx.x;
    __shared__ float red[8];
    const float* ar = adj + (size_t)row * NN;
    float s = 0.f;
    for (int j = threadIdx.x; j < NN; j += 256) s += ar[j];
#pragma unroll
    for (int o = 16; o; o >>= 1) s += __shfl_down_sync(0xffffffffu, s, o);
    if ((threadIdx.x & 31) == 0) red[threadIdx.x >> 5] = s;
    __syncthreads();
    if (threadIdx.x == 0) {
        float t = 0.f;
#pragma unroll
        for (int w = 0; w < 8; w++) t += red[w];
        red[0] = 1.0f / (t + 1e-9f);
    }
    __syncthreads();
    float inv = red[0];
    for (int j = threadIdx.x; j < NN; j += 256) g_adjn[(size_t)row * NN + j] = ar[j] * inv;
}

// ---------------- fused retention: 512 threads, single weight pass ----------------
#define OFF_WB0 8448
#define OFF_WB1 22272
#define OFF_VT 36096
#define OFF_SS 44800
#define RET_FLOATS 53504
#define RET_SMEM (RET_FLOATS * 4)

__global__ void __launch_bounds__(512, 1) k_ret(
    const float* __restrict__ wq, const float* __restrict__ bq,
    const float* __restrict__ wk, const float* __restrict__ bk,
    const float* __restrict__ wv, const float* __restrict__ bv,
    const float* __restrict__ gnw, const float* __restrict__ gnb,
    const float* __restrict__ gam,
    const float* __restrict__ lnw, const float* __restrict__ lnb) {
    extern __shared__ float sm[];
    float* hs = sm;              // [64][132] (h) -> later Qs
    float* Vt = sm + OFF_VT;     // [128][68]
    float* Ss = sm + OFF_SS;     // 2 x [64][68]
    float* Qs = sm;              // alias hs
    float* Ks = sm + 8448;       // alias wb0
    __shared__ float cbias[384];
    __shared__ float gpow[64];
    __shared__ float shead[8];
    __shared__ float smean[4], srstd[4];
    __shared__ float sum1[64], sum2[64];

    int tid = threadIdx.x, lane = tid & 31, w = tid >> 5, g = lane >> 2, tg = lane & 3;
    int bn = blockIdx.x;

    for (int e = tid; e < 384; e += 512)
        cbias[e] = e < 128 ? bq[e] : (e < 256 ? bk[e - 128] : bv[e - 256]);
    if (tid < 64) {
        gpow[tid] = powf(gam[0], (float)tid);
        sum1[tid] = 0.f;
        sum2[tid] = 0.f;
    }
    if (tid < 8) shead[tid] = 0.f;

    const float* hb = g_h + (size_t)bn * (TT * DD);
    for (int e = tid; e < 2048; e += 512) {
        float4 v = ((const float4*)hb)[e];
        int r = e >> 5, c4 = (e & 31) * 4;
        float* dst = hs + r * LDH + c4;
        dst[0] = tf32f(v.x); dst[1] = tf32f(v.y); dst[2] = tf32f(v.z); dst[3] = tf32f(v.w);
    }
    // stage chunk 0 into wb0
    {
        int e = tid;
#pragma unroll
        for (int i = 0; i < 6; i++) {
            int r = e >> 3, k4 = (e & 7) * 4;
            const float* src = (r < 128) ? (wq + r * DD)
                             : (r < 256) ? (wk + (r - 128) * DD)
                                         : (wv + (r - 256) * DD);
            float4 v = *(const float4*)(src + k4);
            float* dst = sm + OFF_WB0 + r * LDWH + k4;
            dst[0] = tf32f(v.x); dst[1] = tf32f(v.y); dst[2] = tf32f(v.z); dst[3] = tf32f(v.w);
            e += 512;
        }
    }
    __syncthreads();

    // ---- QKV: m64 n384 k128, warp: m-tile mq, n-range nq*96
    int mq = w & 3, nq = w >> 2;
    float c[12][4];
#pragma unroll
    for (int nt = 0; nt < 12; nt++)
#pragma unroll
        for (int ci = 0; ci < 4; ci++) c[nt][ci] = 0.f;

#pragma unroll
    for (int kc = 0; kc < 4; kc++) {
        float4 pref[6];
        if (kc < 3) {
            int kcn = (kc + 1) * 32;
            int e = tid;
#pragma unroll
            for (int i = 0; i < 6; i++) {
                int r = e >> 3, k4 = (e & 7) * 4;
                const float* src = (r < 128) ? (wq + r * DD)
                                 : (r < 256) ? (wk + (r - 128) * DD)
                                             : (wv + (r - 256) * DD);
                pref[i] = *(const float4*)(src + kcn + k4);
                e += 512;
            }
        }
        const float* wb = sm + ((kc & 1) ? OFF_WB1 : OFF_WB0);
#pragma unroll
        for (int ks = 0; ks < 4; ks++) {
            int hc = kc * 32 + ks * 8;
            unsigned a0 = __float_as_uint(hs[(mq * 16 + g) * LDH + hc + tg]);
            unsigned a1 = __float_as_uint(hs[(mq * 16 + 8 + g) * LDH + hc + tg]);
            unsigned a2 = __float_as_uint(hs[(mq * 16 + g) * LDH + hc + tg + 4]);
            unsigned a3 = __float_as_uint(hs[(mq * 16 + 8 + g) * LDH + hc + tg + 4]);
#pragma unroll
            for (int nt = 0; nt < 12; nt++) {
                int nc = nq * 96 + nt * 8 + g;
                unsigned b0 = __float_as_uint(wb[nc * LDWH + ks * 8 + tg]);
                unsigned b1 = __float_as_uint(wb[nc * LDWH + ks * 8 + tg + 4]);
                MMA_TF32(c[nt], a0, a1, a2, a3, b0, b1);
            }
        }
        if (kc < 3) {
            float* dstb = sm + (((kc + 1) & 1) ? OFF_WB1 : OFF_WB0);
            int e = tid;
#pragma unroll
            for (int i = 0; i < 6; i++) {
                int r = e >> 3, k4 = (e & 7) * 4;
                float* dst = dstb + r * LDWH + k4;
                dst[0] = tf32f(pref[i].x); dst[1] = tf32f(pref[i].y);
                dst[2] = tf32f(pref[i].z); dst[3] = tf32f(pref[i].w);
                e += 512;
            }
        }
        __syncthreads();
    }

    // QKV epilogue -> Qs (over hs), Ks (over wb0), Vt
#pragma unroll
    for (int nt = 0; nt < 12; nt++) {
        int gc0 = nq * 96 + nt * 8 + 2 * tg;
#pragma unroll
        for (int ci = 0; ci < 4; ci++) {
            int r = mq * 16 + g + ((ci >= 2) ? 8 : 0);
            int gc = gc0 + (ci & 1);
            float tv = tf32f(c[nt][ci] + cbias[gc]);
            if (gc < 128) Qs[r * LDH + gc] = tv;
            else if (gc < 256) Ks[r * LDH + gc - 128] = tv;
            else Vt[(gc - 256) * LDVT + r] = tv;
        }
    }
    __syncthreads();

    // ---- retention: 2 heads in parallel, 2 passes
    float oreg[2][2][4];
    int hsel = w >> 3;          // head within pass
    int ns = w & 7;             // S phase n-tile
    int mo = w & 3, nh = (w >> 2) & 1;  // O phase mapping
    float* Sp = Ss + hsel * 4352;

#pragma unroll
    for (int p = 0; p < 2; p++) {
        int hh = p * 2 + hsel, hb0 = hh * 32;
        // S = Q K^T (m64 n64 k32) per head, 8 warps per head
        float scC[4][4];
#pragma unroll
        for (int mt = 0; mt < 4; mt++)
#pragma unroll
            for (int ci = 0; ci < 4; ci++) scC[mt][ci] = 0.f;
#pragma unroll
        for (int ks = 0; ks < 4; ks++) {
            int kk = hb0 + ks * 8;
            unsigned a[4][4];
#pragma unroll
            for (int mt = 0; mt < 4; mt++) {
                a[mt][0] = __float_as_uint(Qs[(mt * 16 + g) * LDH + kk + tg]);
                a[mt][1] = __float_as_uint(Qs[(mt * 16 + 8 + g) * LDH + kk + tg]);
                a[mt][2] = __float_as_uint(Qs[(mt * 16 + g) * LDH + kk + tg + 4]);
                a[mt][3] = __float_as_uint(Qs[(mt * 16 + 8 + g) * LDH + kk + tg + 4]);
            }
            int nc = ns * 8 + g;
            unsigned b0 = __float_as_uint(Ks[nc * LDH + kk + tg]);
            unsigned b1 = __float_as_uint(Ks[nc * LDH + kk + tg + 4]);
#pragma unroll
            for (int mt = 0; mt < 4; mt++)
                MMA_TF32(scC[mt], a[mt][0], a[mt][1], a[mt][2], a[mt][3], b0, b1);
        }
#pragma unroll
        for (int mt = 0; mt < 4; mt++)
#pragma unroll
            for (int ci = 0; ci < 4; ci++) {
                int q = mt * 16 + g + ((ci >= 2) ? 8 : 0);
                int kk2 = ns * 8 + 2 * tg + (ci & 1);
                float v = (kk2 <= q) ? scC[mt][ci] * gpow[q - kk2] : 0.f;
                Sp[q * LDSS + kk2] = tf32f(v);
            }
        __syncthreads();

        // O = S V (m64 n32 k64) per head
#pragma unroll
        for (int ntl = 0; ntl < 2; ntl++)
#pragma unroll
            for (int ci = 0; ci < 4; ci++) oreg[p][ntl][ci] = 0.f;
#pragma unroll
        for (int ks = 0; ks < 8; ks++) {
            int kk = ks * 8;
            unsigned a0 = __float_as_uint(Sp[(mo * 16 + g) * LDSS + kk + tg]);
            unsigned a1 = __float_as_uint(Sp[(mo * 16 + 8 + g) * LDSS + kk + tg]);
            unsigned a2 = __float_as_uint(Sp[(mo * 16 + g) * LDSS + kk + tg + 4]);
            unsigned a3 = __float_as_uint(Sp[(mo * 16 + 8 + g) * LDSS + kk + tg + 4]);
#pragma unroll
            for (int ntl = 0; ntl < 2; ntl++) {
                int nc = hb0 + nh * 16 + ntl * 8 + g;
                unsigned b0 = __float_as_uint(Vt[nc * LDVT + kk + tg]);
                unsigned b1 = __float_as_uint(Vt[nc * LDVT + kk + tg + 4]);
                MMA_TF32(oreg[p][ntl], a0, a1, a2, a3, b0, b1);
            }
        }
        float s1 = 0.f, s2 = 0.f;
#pragma unroll
        for (int ntl = 0; ntl < 2; ntl++)
#pragma unroll
            for (int ci = 0; ci < 4; ci++) {
                float v = oreg[p][ntl][ci];
                s1 += v; s2 += v * v;
            }
#pragma unroll
        for (int o = 16; o; o >>= 1) {
            s1 += __shfl_xor_sync(0xffffffffu, s1, o);
            s2 += __shfl_xor_sync(0xffffffffu, s2, o);
        }
        if (lane == 0) {
            atomicAdd(&shead[hh * 2], s1);
            atomicAdd(&shead[hh * 2 + 1], s2);
        }
        __syncthreads();
    }

    if (tid < 4) {
        float mean = shead[tid * 2] * (1.0f / 2048.0f);
        float var = shead[tid * 2 + 1] * (1.0f / 2048.0f) - mean * mean;
        smean[tid] = mean;
        srstd[tid] = rsqrtf(var + EPS);
    }
    __syncthreads();

    // GN apply + LN partials
    float p1[2] = {0.f, 0.f}, p2[2] = {0.f, 0.f};
#pragma unroll
    for (int p = 0; p < 2; p++) {
        int hh = p * 2 + hsel;
        float mn = smean[hh], rs = srstd[hh];
#pragma unroll
        for (int ntl = 0; ntl < 2; ntl++)
#pragma unroll
            for (int ci = 0; ci < 4; ci++) {
                int col = hh * 32 + nh * 16 + ntl * 8 + 2 * tg + (ci & 1);
                float v = (oreg[p][ntl][ci] - mn) * rs * gnw[col] + gnb[col];
                oreg[p][ntl][ci] = v;
                int half = (ci >= 2) ? 1 : 0;
                p1[half] += v;
                p2[half] += v * v;
            }
    }
#pragma unroll
    for (int o = 1; o <= 2; o <<= 1) {
        p1[0] += __shfl_xor_sync(0xffffffffu, p1[0], o);
        p1[1] += __shfl_xor_sync(0xffffffffu, p1[1], o);
        p2[0] += __shfl_xor_sync(0xffffffffu, p2[0], o);
        p2[1] += __shfl_xor_sync(0xffffffffu, p2[1], o);
    }
    int r0 = mo * 16 + g, r1 = r0 + 8;
    if (tg == 0) {
        atomicAdd(&sum1[r0], p1[0]);
        atomicAdd(&sum2[r0], p2[0]);
        atomicAdd(&sum1[r1], p1[1]);
        atomicAdd(&sum2[r1], p2[1]);
    }
    __syncthreads();

    float mu0 = sum1[r0] * (1.0f / 128.0f);
    float rs0 = rsqrtf(sum2[r0] * (1.0f / 128.0f) - mu0 * mu0 + EPS);
    float mu1 = sum1[r1] * (1.0f / 128.0f);
    float rs1 = rsqrtf(sum2[r1] * (1.0f / 128.0f) - mu1 * mu1 + EPS);

    float* go = g_ret + (size_t)bn * (TT * DD);
#pragma unroll
    for (int p = 0; p < 2; p++) {
        int hh = p * 2 + hsel;
#pragma unroll
        for (int ntl = 0; ntl < 2; ntl++) {
            int cb = hh * 32 + nh * 16 + ntl * 8 + 2 * tg;
            float lw0 = lnw[cb], lb0 = lnb[cb];
            float lw1 = lnw[cb + 1], lb1 = lnb[cb + 1];
            float2 v0, v1;
            v0.x = (oreg[p][ntl][0] - mu0) * rs0 * lw0 + lb0;
            v0.y = (oreg[p][ntl][1] - mu0) * rs0 * lw1 + lb1;
            v1.x = (oreg[p][ntl][2] - mu1) * rs1 * lw0 + lb0;
            v1.y = (oreg[p][ntl][3] - mu1) * rs1 * lw1 + lb1;
            *(float2*)&go[r0 * DD + cb] = v0;
            *(float2*)&go[r1 * DD + cb] = v1;
        }
    }
}

// ---------------- diffusion step 0: m16 tiles, grid 128 ----------------
#define DG_SMEM ((2112 + 16896) * 4)
__global__ void __launch_bounds__(256, 2) k_diffg(const float* __restrict__ dw,
                                                  const float* __restrict__ convw) {
    extern __shared__ float sm[];
    float* hs = sm;          // [16][132]
    float* ws = sm + 2112;   // [128][132]
    int tid = threadIdx.x, lane = tid & 31, w = tid >> 5, g = lane >> 2, tg = lane & 3;
    int row0 = blockIdx.x * 16;

    for (int e = tid; e < 512; e += 256) {
        int r = e >> 5, c4 = (e & 31) * 4;
        float4 v = *(const float4*)(g_ret + ((size_t)(row0 + r) * TT + (TT - 1)) * DD + c4);
        float* dst = hs + r * LDH + c4;
        dst[0] = tf32f(v.x); dst[1] = tf32f(v.y); dst[2] = tf32f(v.z); dst[3] = tf32f(v.w);
    }
    for (int e = tid; e < 4096; e += 256) {
        int r = e >> 5, k4 = (e & 31) * 4;
        float4 v = *(const float4*)(dw + (size_t)r * DD + k4);
        float* dst = ws + r * LDH + k4;
        dst[0] = tf32f(v.x); dst[1] = tf32f(v.y); dst[2] = tf32f(v.z); dst[3] = tf32f(v.w);
    }
    __syncthreads();

    float c[2][4];
#pragma unroll
    for (int nt = 0; nt < 2; nt++)
#pragma unroll
        for (int ci = 0; ci < 4; ci++) c[nt][ci] = 0.f;
#pragma unroll
    for (int ks = 0; ks < 16; ks++) {
        int kk = ks * 8;
        unsigned a0 = __float_as_uint(hs[g * LDH + kk + tg]);
        unsigned a1 = __float_as_uint(hs[(8 + g) * LDH + kk + tg]);
        unsigned a2 = __float_as_uint(hs[g * LDH + kk + tg + 4]);
        unsigned a3 = __float_as_uint(hs[(8 + g) * LDH + kk + tg + 4]);
#pragma unroll
        for (int nt = 0; nt < 2; nt++) {
            int nc = w * 16 + nt * 8 + g;
            unsigned b0 = __float_as_uint(ws[nc * LDH + kk + tg]);
            unsigned b1 = __float_as_uint(ws[nc * LDH + kk + tg + 4]);
            MMA_TF32(c[nt], a0, a1, a2, a3, b0, b1);
        }
    }
    float c0 = convw[0];
#pragma unroll
    for (int nt = 0; nt < 2; nt++) {
        int col0 = w * 16 + nt * 8 + 2 * tg;
#pragma unroll
        for (int ci = 0; ci < 4; ci++) {
            int r = g + ((ci >= 2) ? 8 : 0);
            int col = col0 + (ci & 1);
            size_t idx = (size_t)(row0 + r) * DD + col;
            float v = c[nt][ci];
            g_cur_a[idx] = v;
            g_acc[idx] = c0 * v;
        }
    }
}

// ---------------- diffusion hop: m32 tiles, grid (16,B) ----------------
#define LDB_HOP 37
__global__ void __launch_bounds__(256, 4) k_hop(const float* __restrict__ convw, int kidx,
                                                const float* __restrict__ convb,
                                                int dir, int last) {
    __shared__ float As[32 * LDWH];
    __shared__ float Bs[128 * LDB_HOP];
    int tid = threadIdx.x, lane = tid & 31, w = tid >> 5, g = lane >> 2, tg = lane & 3;
    int b = blockIdx.y, i0 = blockIdx.x * 32;
    const float* curin = dir ? g_cur_b : g_cur_a;
    float* curout = dir ? g_cur_a : g_cur_b;
    const float* curb = curin + (size_t)b * NN * DD;
    const float* adjb = g_adjn + (size_t)b * NN * NN;

    int mt2 = w & 1, nq = w >> 1;
    float c[4][4];
#pragma unroll
    for (int nt = 0; nt < 4; nt++)
#pragma unroll
        for (int ci = 0; ci < 4; ci++) c[nt][ci] = 0.f;

    for (int kc = 0; kc < NN; kc += 32) {
        __syncthreads();
        {
            int e = tid;  // 256 float4 for As
            int r = e >> 3, k4 = (e & 7) * 4;
            float4 v = *(const float4*)(adjb + (size_t)(i0 + r) * NN + kc + k4);
            float* dst = As + r * LDWH + k4;
            dst[0] = tf32f(v.x); dst[1] = tf32f(v.y); dst[2] = tf32f(v.z); dst[3] = tf32f(v.w);
        }
        for (int e = tid; e < 1024; e += 256) {
            int kr = e >> 5, n4 = (e & 31) * 4;
            float4 v = *(const float4*)(curb + (size_t)(kc + kr) * DD + n4);
            Bs[(n4 + 0) * LDB_HOP + kr] = tf32f(v.x);
            Bs[(n4 + 1) * LDB_HOP + kr] = tf32f(v.y);
            Bs[(n4 + 2) * LDB_HOP + kr] = tf32f(v.z);
            Bs[(n4 + 3) * LDB_HOP + kr] = tf32f(v.w);
        }
        __syncthreads();
#pragma unroll
        for (int ks = 0; ks < 4; ks++) {
            int kk = ks * 8;
            unsigned a0 = __float_as_uint(As[(mt2 * 16 + g) * LDWH + kk + tg]);
            unsigned a1 = __float_as_uint(As[(mt2 * 16 + 8 + g) * LDWH + kk + tg]);
            unsigned a2 = __float_as_uint(As[(mt2 * 16 + g) * LDWH + kk + tg + 4]);
            unsigned a3 = __float_as_uint(As[(mt2 * 16 + 8 + g) * LDWH + kk + tg + 4]);
#pragma unroll
            for (int nt = 0; nt < 4; nt++) {
                int nc = nq * 32 + nt * 8 + g;
                unsigned b0 = __float_as_uint(Bs[nc * LDB_HOP + kk + tg]);
                unsigned b1 = __float_as_uint(Bs[nc * LDB_HOP + kk + tg + 4]);
                MMA_TF32(c[nt], a0, a1, a2, a3, b0, b1);
            }
        }
    }
    float cw = convw[kidx];
    float cb = convb[0];
#pragma unroll
    for (int nt = 0; nt < 4; nt++) {
        int col0 = nq * 32 + nt * 8 + 2 * tg;
#pragma unroll
        for (int ci = 0; ci < 4; ci++) {
            int r = mt2 * 16 + g + ((ci >= 2) ? 8 : 0);
            int col = col0 + (ci & 1);
            size_t idx = ((size_t)b * NN + i0 + r) * DD + col;
            float v = c[nt][ci];
            curout[idx] = v;
            float av = g_acc[idx] + cw * v;
            if (last) g_hdiff[idx] = lrelu(av + cb);
            else g_acc[idx] = av;
        }
    }
}

// ---------------- MLP fusion: 2 bn per block ----------------
#define MLP_SMEM ((16896 + 8448) * 4)
__global__ void __launch_bounds__(256, 2) k_mlp(const float* __restrict__ mw,
                                                const float* __restrict__ mb) {
    extern __shared__ float sm[];
    float* ws = sm;            // [128][132]
    float* hs = sm + 16896;    // [64][132], also output staging
    __shared__ float bias2[128];
    __shared__ float hds[128];
    int tid = threadIdx.x, lane = tid & 31, w = tid >> 5, g = lane >> 2, tg = lane & 3;

    for (int e = tid; e < 4096; e += 256) {
        int r = e >> 5, k4 = (e & 31) * 4;
        float4 v = *(const float4*)(mw + (size_t)r * 256 + k4);
        float* dst = ws + r * LDH + k4;
        dst[0] = tf32f(v.x); dst[1] = tf32f(v.y); dst[2] = tf32f(v.z); dst[3] = tf32f(v.w);
    }

    for (int bi = 0; bi < 2; bi++) {
        int bn = blockIdx.x * 2 + bi;
        __syncthreads();  // ws ready / previous output copy done
        const float* rb = g_ret + (size_t)bn * (TT * DD);
        for (int e = tid; e < 2048; e += 256) {
            float4 v = ((const float4*)rb)[e];
            int r = e >> 5, c4 = (e & 31) * 4;
            float* dst = hs + r * LDH + c4;
            dst[0] = tf32f(v.x); dst[1] = tf32f(v.y); dst[2] = tf32f(v.z); dst[3] = tf32f(v.w);
        }
        if (tid < 128) hds[tid] = g_hdiff[(size_t)bn * DD + tid];
        __syncthreads();

        // bias2 from h_diff half of weights (global reads, L2-hot)
        {
            float4 hv = *(const float4*)&hds[lane * 4];
#pragma unroll
            for (int i = 0; i < 16; i++) {
                int d = w * 16 + i;
                float4 wv = *(const float4*)(mw + (size_t)d * 256 + 128 + lane * 4);
                float s = wv.x * hv.x + wv.y * hv.y + wv.z * hv.z + wv.w * hv.w;
#pragma unroll
                for (int o = 16; o; o >>= 1) s += __shfl_xor_sync(0xffffffffu, s, o);
                if (lane == 0) bias2[d] = s + mb[d];
            }
        }

        float c[4][2][4];
#pragma unroll
        for (int mt = 0; mt < 4; mt++)
#pragma unroll
            for (int nt = 0; nt < 2; nt++)
#pragma unroll
                for (int ci = 0; ci < 4; ci++) c[mt][nt][ci] = 0.f;

#pragma unroll
        for (int ks = 0; ks < 16; ks++) {
            int kk = ks * 8;
            unsigned a[4][4];
#pragma unroll
            for (int mt = 0; mt < 4; mt++) {
                a[mt][0] = __float_as_uint(hs[(mt * 16 + g) * LDH + kk + tg]);
                a[mt][1] = __float_as_uint(hs[(mt * 16 + 8 + g) * LDH + kk + tg]);
                a[mt][2] = __float_as_uint(hs[(mt * 16 + g) * LDH + kk + tg + 4]);
                a[mt][3] = __float_as_uint(hs[(mt * 16 + 8 + g) * LDH + kk + tg + 4]);
            }
#pragma unroll
            for (int nt = 0; nt < 2; nt++) {
                int nc = w * 16 + nt * 8 + g;
                unsigned b0 = __float_as_uint(ws[nc * LDH + kk + tg]);
                unsigned b1 = __float_as_uint(ws[nc * LDH + kk + tg + 4]);
#pragma unroll
                for (int mt = 0; mt < 4; mt++)
                    MMA_TF32(c[mt][nt], a[mt][0], a[mt][1], a[mt][2], a[mt][3], b0, b1);
            }
        }
        __syncthreads();  // hs reads done; bias2 visible
#pragma unroll
        for (int mt = 0; mt < 4; mt++)
#pragma unroll
            for (int nt = 0; nt < 2; nt++) {
                int col0 = w * 16 + nt * 8 + 2 * tg;
#pragma unroll
                for (int ci = 0; ci < 4; ci++) {
                    int r = mt * 16 + g + ((ci >= 2) ? 8 : 0);
                    int col = col0 + (ci & 1);
                    hs[r * LDH + col] = lrelu(c[mt][nt][ci] + bias2[col]);
                }
            }
        __syncthreads();
        float* obuf = g_h + (size_t)bn * (TT * DD);
        for (int e = tid; e < 2048; e += 256) {
            int r = e >> 5, c4 = (e & 31) * 4;
            *(float4*)&obuf[r * DD + c4] = *(float4*)&hs[r * LDH + c4];
        }
    }
}

// ---------------- head ----------------
__global__ void k_head(const float* __restrict__ h1w, const float* __restrict__ h1b,
                       const float* __restrict__ h2w, const float* __restrict__ h2b,
                       float* __restrict__ out) {
    __shared__ float wt[128 * 65];
    __shared__ float lr[128];
    __shared__ float red[2];
    int bn = blockIdx.x;
    int tid = threadIdx.x;
    for (int e = tid; e < 128; e += 64)
        lr[e] = g_h[((size_t)bn * TT + (TT - 1)) * DD + e];
    for (int e = tid; e < 64 * 128; e += 64) {
        int jj = e >> 7, k = e & 127;
        wt[k * 65 + jj] = h1w[e];
    }
    __syncthreads();
    float s = 0.f;
    for (int k = 0; k < 128; k++) s += lr[k] * wt[k * 65 + tid];
    s += h1b[tid];
    s = lrelu(s);
    s *= h2w[tid];
#pragma unroll
    for (int o = 16; o; o >>= 1) s += __shfl_down_sync(0xffffffffu, s, o);
    if ((tid & 31) == 0) red[tid >> 5] = s;
    __syncthreads();
    if (tid == 0) out[bn] = red[0] + red[1] + h2b[0];
}

// ---------------- launch ----------------
extern "C" void kernel_launch(void* const* d_in, const int* in_sizes, int n_in,
                              void* d_out, int out_size) {
    const float* x      = (const float*)d_in[0];
    const float* adj    = (const float*)d_in[1];
    const float* proj_w = (const float*)d_in[2];
    const float* proj_b = (const float*)d_in[3];
    const float* pos    = (const float*)d_in[4];
    const float* diff_w = (const float*)d_in[5];
    const float* conv_w = (const float*)d_in[6];
    const float* conv_b = (const float*)d_in[7];
    const float* wq_w   = (const float*)d_in[8];
    const float* wq_b   = (const float*)d_in[9];
    const float* wk_w   = (const float*)d_in[10];
    const float* wk_b   = (const float*)d_in[11];
    const float* wv_w   = (const float*)d_in[12];
    const float* wv_b   = (const float*)d_in[13];
    const float* gn_w   = (const float*)d_in[14];
    const float* gn_b   = (const float*)d_in[15];
    const float* gamma  = (const float*)d_in[16];
    const float* ln_w   = (const float*)d_in[17];
    const float* ln_b   = (const float*)d_in[18];
    const float* mlp_w  = (const float*)d_in[19];
    const float* mlp_b  = (const float*)d_in[20];
    const float* h1w    = (const float*)d_in[21];
    const float* h1b    = (const float*)d_in[22];
    const float* h2w    = (const float*)d_in[23];
    const float* h2b    = (const float*)d_in[24];

    cudaFuncSetAttribute(k_ret, cudaFuncAttributeMaxDynamicSharedMemorySize, RET_SMEM);
    cudaFuncSetAttribute(k_mlp, cudaFuncAttributeMaxDynamicSharedMemorySize, MLP_SMEM);
    cudaFuncSetAttribute(k_diffg, cudaFuncAttributeMaxDynamicSharedMemorySize, DG_SMEM);

    k_proj<<<BN, 128>>>(x, proj_w, proj_b, pos);
    k_adjn<<<BB * NN, 256>>>(adj);

    for (int l = 0; l < 2; l++) {
        k_ret<<<BN, 512, RET_SMEM>>>(
            wq_w + l * DD * DD, wq_b + l * DD, wk_w + l * DD * DD, wk_b + l * DD,
            wv_w + l * DD * DD, wv_b + l * DD, gn_w + l * DD, gn_b + l * DD,
            gamma + l, ln_w + l * DD, ln_b + l * DD);
        k_diffg<<<BN / 16, 256, DG_SMEM>>>(diff_w + l * DD * DD, conv_w + l * 3);
        k_hop<<<dim3(NN / 32, BB), 256>>>(conv_w + l * 3, 1, conv_b + l, 0, 0);
        k_hop<<<dim3(NN / 32, BB), 256>>>(conv_w + l * 3, 2, conv_b + l, 1, 1);
        k_mlp<<<BN / 2, 256, MLP_SMEM>>>(mlp_w + (size_t)l * DD * 2 * DD, mlp_b + l * DD);
    }
    k_head<<<BN, 64>>>(h1w, h1b, h2w, h2b, (float*)d_out);
}

// round 5
// speedup vs baseline: 3.0016x; 1.2593x over previous
#include <cuda_runtime.h>
#include <cuda_fp16.h>
#include <math.h>

#define BB 4
#define NN 512
#define BN 2048
#define TT 64
#define DD 128
#define HH 4
#define HD 32
#define EPS 1e-5f
#define LSLOPE 0.2f

__device__ float g_h[BN * TT * DD];
__device__ float g_ret[BN * TT * DD];
__device__ float g_adjn[BB * NN * NN];
__device__ float g_cur_a[BB * NN * DD];
__device__ float g_cur_b[BB * NN * DD];
__device__ float g_acc[BB * NN * DD];
__device__ float g_hdiff[BB * NN * DD];

__device__ __forceinline__ float lrelu(float v) { return v > 0.f ? v : LSLOPE * v; }

__device__ __forceinline__ unsigned ldh2(const __half* p) {
    return *(const unsigned*)p;
}
__device__ __forceinline__ void sth2(__half* p, float a, float b) {
    *(__half2*)p = __floats2half2_rn(a, b);
}

#define MMA_F16(C, A0, A1, A2, A3, B0, B1)                                              \
    asm volatile(                                                                       \
        "mma.sync.aligned.m16n8k16.row.col.f32.f16.f16.f32 "                            \
        "{%0,%1,%2,%3},{%4,%5,%6,%7},{%8,%9},{%0,%1,%2,%3};"                            \
        : "+f"((C)[0]), "+f"((C)[1]), "+f"((C)[2]), "+f"((C)[3])                        \
        : "r"(A0), "r"(A1), "r"(A2), "r"(A3), "r"(B0), "r"(B1))

#define LDH_H 136
#define LDW_H 40
#define LDVT_H 72
#define LDSS_H 72

// ---------------- proj + pos ----------------
__global__ void k_proj(const float* __restrict__ x, const float* __restrict__ pw,
                       const float* __restrict__ pb, const float* __restrict__ pos) {
    __shared__ float sx[TT * 8];
    int bn = blockIdx.x;
    int d = threadIdx.x;
    for (int e = d; e < TT * 8; e += 128) sx[e] = x[(size_t)bn * TT * 8 + e];
    float4 w0 = *(const float4*)(pw + d * 8);
    float4 w1 = *(const float4*)(pw + d * 8 + 4);
    float bv = pb[d];
    __syncthreads();
    float* ob = g_h + (size_t)bn * (TT * DD);
    for (int t = 0; t < TT; t++) {
        const float* xr = &sx[t * 8];
        float s = bv + pos[t * DD + d];
        s += xr[0] * w0.x + xr[1] * w0.y + xr[2] * w0.z + xr[3] * w0.w;
        s += xr[4] * w1.x + xr[5] * w1.y + xr[6] * w1.z + xr[7] * w1.w;
        ob[t * DD + d] = s;
    }
}

// ---------------- adj row-normalize ----------------
__global__ void k_adjn(const float* __restrict__ adj) {
    int row = blockIdx.x;
    __shared__ float red[8];
    const float* ar = adj + (size_t)row * NN;
    float s = 0.f;
    for (int j = threadIdx.x; j < NN; j += 256) s += ar[j];
#pragma unroll
    for (int o = 16; o; o >>= 1) s += __shfl_down_sync(0xffffffffu, s, o);
    if ((threadIdx.x & 31) == 0) red[threadIdx.x >> 5] = s;
    __syncthreads();
    if (threadIdx.x == 0) {
        float t = 0.f;
#pragma unroll
        for (int w = 0; w < 8; w++) t += red[w];
        red[0] = 1.0f / (t + 1e-9f);
    }
    __syncthreads();
    float inv = red[0];
    for (int j = threadIdx.x; j < NN; j += 256) g_adjn[(size_t)row * NN + j] = ar[j] * inv;
}

// ---------------- fused retention (fp16 mma) + GN + LN ----------------
#define HOFF_WB0 8704
#define HOFF_WB1 24064
#define HOFF_KS 8704   /* alias WB0 after mainloop */
#define HOFF_VT 24064  /* alias WB1 after mainloop */
#define HOFF_SS 39424
#define RET_HALVES 48640
#define RET_SMEM (RET_HALVES * 2)

__global__ void __launch_bounds__(512, 1) k_ret(
    const float* __restrict__ wq, const float* __restrict__ bq,
    const float* __restrict__ wk, const float* __restrict__ bk,
    const float* __restrict__ wv, const float* __restrict__ bv,
    const float* __restrict__ gnw, const float* __restrict__ gnb,
    const float* __restrict__ gam,
    const float* __restrict__ lnw, const float* __restrict__ lnb) {
    extern __shared__ unsigned char smraw[];
    __half* smh = (__half*)smraw;
    __half* hs = smh;               // [64][136] h -> later Qs
    __half* Ks = smh + HOFF_KS;     // after mainloop
    __half* Vt = smh + HOFF_VT;     // [128][72]
    __half* Ss = smh + HOFF_SS;     // 2 x [64][72]
    __half* Qs = smh;
    __shared__ float cbias[384];
    __shared__ float gpow[64];
    __shared__ float shead[8];
    __shared__ float smean[4], srstd[4];
    __shared__ float sum1[64], sum2[64];

    int tid = threadIdx.x, lane = tid & 31, w = tid >> 5, g = lane >> 2, tg = lane & 3;
    int bn = blockIdx.x;

    for (int e = tid; e < 384; e += 512)
        cbias[e] = e < 128 ? bq[e] : (e < 256 ? bk[e - 128] : bv[e - 256]);
    if (tid < 64) {
        gpow[tid] = powf(gam[0], (float)tid);
        sum1[tid] = 0.f;
        sum2[tid] = 0.f;
    }
    if (tid < 8) shead[tid] = 0.f;

    const float* hb = g_h + (size_t)bn * (TT * DD);
    for (int e = tid; e < 2048; e += 512) {
        float4 v = ((const float4*)hb)[e];
        int r = e >> 5, c4 = (e & 31) * 4;
        __half* dst = hs + r * LDH_H + c4;
        sth2(dst, v.x, v.y);
        sth2(dst + 2, v.z, v.w);
    }
    // stage weight chunk 0 into WB0
    {
        int e = tid;
#pragma unroll
        for (int i = 0; i < 6; i++) {
            int r = e >> 3, k4 = (e & 7) * 4;
            const float* src = (r < 128) ? (wq + r * DD)
                             : (r < 256) ? (wk + (r - 128) * DD)
                                         : (wv + (r - 256) * DD);
            float4 v = *(const float4*)(src + k4);
            __half* dst = smh + HOFF_WB0 + r * LDW_H + k4;
            sth2(dst, v.x, v.y);
            sth2(dst + 2, v.z, v.w);
            e += 512;
        }
    }
    __syncthreads();

    // ---- QKV: m64 n384 k128
    int mq = w & 3, nq = w >> 2;
    float c[12][4];
#pragma unroll
    for (int nt = 0; nt < 12; nt++)
#pragma unroll
        for (int ci = 0; ci < 4; ci++) c[nt][ci] = 0.f;

#pragma unroll
    for (int kc = 0; kc < 4; kc++) {
        float4 pref[6];
        if (kc < 3) {
            int kcn = (kc + 1) * 32;
            int e = tid;
#pragma unroll
            for (int i = 0; i < 6; i++) {
                int r = e >> 3, k4 = (e & 7) * 4;
                const float* src = (r < 128) ? (wq + r * DD)
                                 : (r < 256) ? (wk + (r - 128) * DD)
                                             : (wv + (r - 256) * DD);
                pref[i] = *(const float4*)(src + kcn + k4);
                e += 512;
            }
        }
        const __half* wb = smh + ((kc & 1) ? HOFF_WB1 : HOFF_WB0);
#pragma unroll
        for (int ks2 = 0; ks2 < 2; ks2++) {
            int hc = kc * 32 + ks2 * 16;
            const __half* ar0 = hs + (mq * 16 + g) * LDH_H + hc + 2 * tg;
            const __half* ar1 = hs + (mq * 16 + 8 + g) * LDH_H + hc + 2 * tg;
            unsigned a0 = ldh2(ar0), a1 = ldh2(ar1);
            unsigned a2 = ldh2(ar0 + 8), a3 = ldh2(ar1 + 8);
#pragma unroll
            for (int nt = 0; nt < 12; nt++) {
                int nc = nq * 96 + nt * 8 + g;
                const __half* br = wb + nc * LDW_H + ks2 * 16 + 2 * tg;
                unsigned b0 = ldh2(br), b1 = ldh2(br + 8);
                MMA_F16(c[nt], a0, a1, a2, a3, b0, b1);
            }
        }
        if (kc < 3) {
            __half* dstb = smh + (((kc + 1) & 1) ? HOFF_WB1 : HOFF_WB0);
            int e = tid;
#pragma unroll
            for (int i = 0; i < 6; i++) {
                int r = e >> 3, k4 = (e & 7) * 4;
                __half* dst = dstb + r * LDW_H + k4;
                sth2(dst, pref[i].x, pref[i].y);
                sth2(dst + 2, pref[i].z, pref[i].w);
                e += 512;
            }
        }
        __syncthreads();
    }

    // QKV epilogue -> Qs(hs), Ks(WB0), Vt(WB1)
    int r0e = mq * 16 + g, r1e = r0e + 8;
#pragma unroll
    for (int nt = 0; nt < 12; nt++) {
        int gc0 = nq * 96 + nt * 8 + 2 * tg;
        float v00 = c[nt][0] + cbias[gc0], v01 = c[nt][1] + cbias[gc0 + 1];
        float v10 = c[nt][2] + cbias[gc0], v11 = c[nt][3] + cbias[gc0 + 1];
        if (gc0 < 128) {
            sth2(&Qs[r0e * LDH_H + gc0], v00, v01);
            sth2(&Qs[r1e * LDH_H + gc0], v10, v11);
        } else if (gc0 < 256) {
            int k0 = gc0 - 128;
            sth2(&Ks[r0e * LDH_H + k0], v00, v01);
            sth2(&Ks[r1e * LDH_H + k0], v10, v11);
        } else {
            int d0 = gc0 - 256;
            Vt[d0 * LDVT_H + r0e] = __float2half(v00);
            Vt[(d0 + 1) * LDVT_H + r0e] = __float2half(v01);
            Vt[d0 * LDVT_H + r1e] = __float2half(v10);
            Vt[(d0 + 1) * LDVT_H + r1e] = __float2half(v11);
        }
    }
    __syncthreads();

    // ---- retention: 2 heads in parallel, 2 passes
    float oreg[2][2][4];
    int hsel = w >> 3;
    int ns = w & 7;
    int mo = w & 3, nh = (w >> 2) & 1;
    __half* Sp = Ss + hsel * (64 * LDSS_H);

#pragma unroll
    for (int p = 0; p < 2; p++) {
        int hh = p * 2 + hsel, hb0 = hh * 32;
        // S = Q K^T (m64 n64 k32)
        float scC[4][4];
#pragma unroll
        for (int mt = 0; mt < 4; mt++)
#pragma unroll
            for (int ci = 0; ci < 4; ci++) scC[mt][ci] = 0.f;
#pragma unroll
        for (int ks2 = 0; ks2 < 2; ks2++) {
            int off = hb0 + ks2 * 16;
            unsigned a[4][4];
#pragma unroll
            for (int mt = 0; mt < 4; mt++) {
                const __half* ar0 = Qs + (mt * 16 + g) * LDH_H + off + 2 * tg;
                const __half* ar1 = Qs + (mt * 16 + 8 + g) * LDH_H + off + 2 * tg;
                a[mt][0] = ldh2(ar0); a[mt][1] = ldh2(ar1);
                a[mt][2] = ldh2(ar0 + 8); a[mt][3] = ldh2(ar1 + 8);
            }
            const __half* br = Ks + (ns * 8 + g) * LDH_H + off + 2 * tg;
            unsigned b0 = ldh2(br), b1 = ldh2(br + 8);
#pragma unroll
            for (int mt = 0; mt < 4; mt++)
                MMA_F16(scC[mt], a[mt][0], a[mt][1], a[mt][2], a[mt][3], b0, b1);
        }
#pragma unroll
        for (int mt = 0; mt < 4; mt++) {
            int q0 = mt * 16 + g, q1 = q0 + 8;
            int kk2 = ns * 8 + 2 * tg;
            float v00 = (kk2 <= q0) ? scC[mt][0] * gpow[q0 - kk2] : 0.f;
            float v01 = (kk2 + 1 <= q0) ? scC[mt][1] * gpow[q0 - kk2 - 1] : 0.f;
            float v10 = (kk2 <= q1) ? scC[mt][2] * gpow[q1 - kk2] : 0.f;
            float v11 = (kk2 + 1 <= q1) ? scC[mt][3] * gpow[q1 - kk2 - 1] : 0.f;
            sth2(&Sp[q0 * LDSS_H + kk2], v00, v01);
            sth2(&Sp[q1 * LDSS_H + kk2], v10, v11);
        }
        __syncthreads();

        // O = S V (m64 n32 k64)
#pragma unroll
        for (int ntl = 0; ntl < 2; ntl++)
#pragma unroll
            for (int ci = 0; ci < 4; ci++) oreg[p][ntl][ci] = 0.f;
#pragma unroll
        for (int ks2 = 0; ks2 < 4; ks2++) {
            int off = ks2 * 16;
            const __half* ar0 = Sp + (mo * 16 + g) * LDSS_H + off + 2 * tg;
            const __half* ar1 = Sp + (mo * 16 + 8 + g) * LDSS_H + off + 2 * tg;
            unsigned a0 = ldh2(ar0), a1 = ldh2(ar1);
            unsigned a2 = ldh2(ar0 + 8), a3 = ldh2(ar1 + 8);
#pragma unroll
            for (int ntl = 0; ntl < 2; ntl++) {
                int nc = hb0 + nh * 16 + ntl * 8 + g;
                const __half* br = Vt + nc * LDVT_H + off + 2 * tg;
                unsigned b0 = ldh2(br), b1 = ldh2(br + 8);
                MMA_F16(oreg[p][ntl], a0, a1, a2, a3, b0, b1);
            }
        }
        float s1 = 0.f, s2 = 0.f;
#pragma unroll
        for (int ntl = 0; ntl < 2; ntl++)
#pragma unroll
            for (int ci = 0; ci < 4; ci++) {
                float v = oreg[p][ntl][ci];
                s1 += v; s2 += v * v;
            }
#pragma unroll
        for (int o = 16; o; o >>= 1) {
            s1 += __shfl_xor_sync(0xffffffffu, s1, o);
            s2 += __shfl_xor_sync(0xffffffffu, s2, o);
        }
        if (lane == 0) {
            atomicAdd(&shead[hh * 2], s1);
            atomicAdd(&shead[hh * 2 + 1], s2);
        }
        __syncthreads();
    }

    if (tid < 4) {
        float mean = shead[tid * 2] * (1.0f / 2048.0f);
        float var = shead[tid * 2 + 1] * (1.0f / 2048.0f) - mean * mean;
        smean[tid] = mean;
        srstd[tid] = rsqrtf(var + EPS);
    }
    __syncthreads();

    // GN apply + LN partials
    float p1[2] = {0.f, 0.f}, p2[2] = {0.f, 0.f};
#pragma unroll
    for (int p = 0; p < 2; p++) {
        int hh = p * 2 + hsel;
        float mn = smean[hh], rs = srstd[hh];
#pragma unroll
        for (int ntl = 0; ntl < 2; ntl++)
#pragma unroll
            for (int ci = 0; ci < 4; ci++) {
                int col = hh * 32 + nh * 16 + ntl * 8 + 2 * tg + (ci & 1);
                float v = (oreg[p][ntl][ci] - mn) * rs * gnw[col] + gnb[col];
                oreg[p][ntl][ci] = v;
                int half_ = (ci >= 2) ? 1 : 0;
                p1[half_] += v;
                p2[half_] += v * v;
            }
    }
#pragma unroll
    for (int o = 1; o <= 2; o <<= 1) {
        p1[0] += __shfl_xor_sync(0xffffffffu, p1[0], o);
        p1[1] += __shfl_xor_sync(0xffffffffu, p1[1], o);
        p2[0] += __shfl_xor_sync(0xffffffffu, p2[0], o);
        p2[1] += __shfl_xor_sync(0xffffffffu, p2[1], o);
    }
    int r0 = mo * 16 + g, r1 = r0 + 8;
    if (tg == 0) {
        atomicAdd(&sum1[r0], p1[0]);
        atomicAdd(&sum2[r0], p2[0]);
        atomicAdd(&sum1[r1], p1[1]);
        atomicAdd(&sum2[r1], p2[1]);
    }
    __syncthreads();

    float mu0 = sum1[r0] * (1.0f / 128.0f);
    float rs0 = rsqrtf(sum2[r0] * (1.0f / 128.0f) - mu0 * mu0 + EPS);
    float mu1 = sum1[r1] * (1.0f / 128.0f);
    float rs1 = rsqrtf(sum2[r1] * (1.0f / 128.0f) - mu1 * mu1 + EPS);

    float* go = g_ret + (size_t)bn * (TT * DD);
#pragma unroll
    for (int p = 0; p < 2; p++) {
        int hh = p * 2 + hsel;
#pragma unroll
        for (int ntl = 0; ntl < 2; ntl++) {
            int cb = hh * 32 + nh * 16 + ntl * 8 + 2 * tg;
            float lw0 = lnw[cb], lb0 = lnb[cb];
            float lw1 = lnw[cb + 1], lb1 = lnb[cb + 1];
            float2 v0, v1;
            v0.x = (oreg[p][ntl][0] - mu0) * rs0 * lw0 + lb0;
            v0.y = (oreg[p][ntl][1] - mu0) * rs0 * lw1 + lb1;
            v1.x = (oreg[p][ntl][2] - mu1) * rs1 * lw0 + lb0;
            v1.y = (oreg[p][ntl][3] - mu1) * rs1 * lw1 + lb1;
            *(float2*)&go[r0 * DD + cb] = v0;
            *(float2*)&go[r1 * DD + cb] = v1;
        }
    }
}

// ---------------- diffusion step 0 (fp16 mma) ----------------
#define DG_HALVES (16 * LDH_H + 128 * LDH_H)
#define DG_SMEM (DG_HALVES * 2)
__global__ void __launch_bounds__(256, 2) k_diffg(const float* __restrict__ dw,
                                                  const float* __restrict__ convw) {
    extern __shared__ unsigned char smraw[];
    __half* hs = (__half*)smraw;            // [16][136]
    __half* ws = hs + 16 * LDH_H;           // [128][136]
    int tid = threadIdx.x, lane = tid & 31, w = tid >> 5, g = lane >> 2, tg = lane & 3;
    int row0 = blockIdx.x * 16;

    for (int e = tid; e < 512; e += 256) {
        int r = e >> 5, c4 = (e & 31) * 4;
        float4 v = *(const float4*)(g_ret + ((size_t)(row0 + r) * TT + (TT - 1)) * DD + c4);
        __half* dst = hs + r * LDH_H + c4;
        sth2(dst, v.x, v.y);
        sth2(dst + 2, v.z, v.w);
    }
    for (int e = tid; e < 4096; e += 256) {
        int r = e >> 5, k4 = (e & 31) * 4;
        float4 v = *(const float4*)(dw + (size_t)r * DD + k4);
        __half* dst = ws + r * LDH_H + k4;
        sth2(dst, v.x, v.y);
        sth2(dst + 2, v.z, v.w);
    }
    __syncthreads();

    float c[2][4];
#pragma unroll
    for (int nt = 0; nt < 2; nt++)
#pragma unroll
        for (int ci = 0; ci < 4; ci++) c[nt][ci] = 0.f;
#pragma unroll
    for (int ks2 = 0; ks2 < 8; ks2++) {
        int off = ks2 * 16;
        const __half* ar0 = hs + g * LDH_H + off + 2 * tg;
        const __half* ar1 = hs + (8 + g) * LDH_H + off + 2 * tg;
        unsigned a0 = ldh2(ar0), a1 = ldh2(ar1);
        unsigned a2 = ldh2(ar0 + 8), a3 = ldh2(ar1 + 8);
#pragma unroll
        for (int nt = 0; nt < 2; nt++) {
            int nc = w * 16 + nt * 8 + g;
            const __half* br = ws + nc * LDH_H + off + 2 * tg;
            unsigned b0 = ldh2(br), b1 = ldh2(br + 8);
            MMA_F16(c[nt], a0, a1, a2, a3, b0, b1);
        }
    }
    float c0 = convw[0];
#pragma unroll
    for (int nt = 0; nt < 2; nt++) {
        int col0 = w * 16 + nt * 8 + 2 * tg;
#pragma unroll
        for (int ci = 0; ci < 4; ci++) {
            int r = g + ((ci >= 2) ? 8 : 0);
            int col = col0 + (ci & 1);
            size_t idx = (size_t)(row0 + r) * DD + col;
            float v = c[nt][ci];
            g_cur_a[idx] = v;
            g_acc[idx] = c0 * v;
        }
    }
}

// ---------------- diffusion hop (fp16 mma) ----------------
__global__ void __launch_bounds__(256, 4) k_hop(const float* __restrict__ convw, int kidx,
                                                const float* __restrict__ convb,
                                                int dir, int last) {
    __shared__ __half As[32 * LDW_H];
    __shared__ __half Bs[128 * LDW_H];
    int tid = threadIdx.x, lane = tid & 31, w = tid >> 5, g = lane >> 2, tg = lane & 3;
    int b = blockIdx.y, i0 = blockIdx.x * 32;
    const float* curin = dir ? g_cur_b : g_cur_a;
    float* curout = dir ? g_cur_a : g_cur_b;
    const float* curb = curin + (size_t)b * NN * DD;
    const float* adjb = g_adjn + (size_t)b * NN * NN;

    int mt2 = w & 1, nq = w >> 1;
    float c[4][4];
#pragma unroll
    for (int nt = 0; nt < 4; nt++)
#pragma unroll
        for (int ci = 0; ci < 4; ci++) c[nt][ci] = 0.f;

    for (int kc = 0; kc < NN; kc += 32) {
        __syncthreads();
        {
            int e = tid;
            int r = e >> 3, k4 = (e & 7) * 4;
            float4 v = *(const float4*)(adjb + (size_t)(i0 + r) * NN + kc + k4);
            __half* dst = As + r * LDW_H + k4;
            sth2(dst, v.x, v.y);
            sth2(dst + 2, v.z, v.w);
        }
        for (int e = tid; e < 1024; e += 256) {
            int kr = e >> 5, n4 = (e & 31) * 4;
            float4 v = *(const float4*)(curb + (size_t)(kc + kr) * DD + n4);
            Bs[(n4 + 0) * LDW_H + kr] = __float2half(v.x);
            Bs[(n4 + 1) * LDW_H + kr] = __float2half(v.y);
            Bs[(n4 + 2) * LDW_H + kr] = __float2half(v.z);
            Bs[(n4 + 3) * LDW_H + kr] = __float2half(v.w);
        }
        __syncthreads();
#pragma unroll
        for (int ks2 = 0; ks2 < 2; ks2++) {
            int off = ks2 * 16;
            const __half* ar0 = As + (mt2 * 16 + g) * LDW_H + off + 2 * tg;
            const __half* ar1 = As + (mt2 * 16 + 8 + g) * LDW_H + off + 2 * tg;
            unsigned a0 = ldh2(ar0), a1 = ldh2(ar1);
            unsigned a2 = ldh2(ar0 + 8), a3 = ldh2(ar1 + 8);
#pragma unroll
            for (int nt = 0; nt < 4; nt++) {
                int nc = nq * 32 + nt * 8 + g;
                const __half* br = Bs + nc * LDW_H + off + 2 * tg;
                unsigned b0 = ldh2(br), b1 = ldh2(br + 8);
                MMA_F16(c[nt], a0, a1, a2, a3, b0, b1);
            }
        }
    }
    float cw = convw[kidx];
    float cb = convb[0];
#pragma unroll
    for (int nt = 0; nt < 4; nt++) {
        int col0 = nq * 32 + nt * 8 + 2 * tg;
#pragma unroll
        for (int ci = 0; ci < 4; ci++) {
            int r = mt2 * 16 + g + ((ci >= 2) ? 8 : 0);
            int col = col0 + (ci & 1);
            size_t idx = ((size_t)b * NN + i0 + r) * DD + col;
            float v = c[nt][ci];
            curout[idx] = v;
            float av = g_acc[idx] + cw * v;
            if (last) g_hdiff[idx] = lrelu(av + cb);
            else g_acc[idx] = av;
        }
    }
}

// ---------------- MLP fusion (fp16 mma), 2 bn per block ----------------
#define MLP_H_WS (128 * LDH_H)
#define MLP_H_HS (64 * LDH_H)
#define MLP_F_OB (64 * 132)
#define MLP_SMEM ((MLP_H_WS + MLP_H_HS) * 2 + MLP_F_OB * 4)
__global__ void __launch_bounds__(256, 2) k_mlp(const float* __restrict__ mw,
                                                const float* __restrict__ mb) {
    extern __shared__ unsigned char smraw[];
    __half* ws = (__half*)smraw;                 // [128][136]
    __half* hs = ws + MLP_H_WS;                  // [64][136]
    float* fob = (float*)(smraw + (MLP_H_WS + MLP_H_HS) * 2);  // [64][132]
    __shared__ float bias2[128];
    __shared__ float hds[128];
    int tid = threadIdx.x, lane = tid & 31, w = tid >> 5, g = lane >> 2, tg = lane & 3;

    for (int e = tid; e < 4096; e += 256) {
        int r = e >> 5, k4 = (e & 31) * 4;
        float4 v = *(const float4*)(mw + (size_t)r * 256 + k4);
        __half* dst = ws + r * LDH_H + k4;
        sth2(dst, v.x, v.y);
        sth2(dst + 2, v.z, v.w);
    }

    for (int bi = 0; bi < 2; bi++) {
        int bn = blockIdx.x * 2 + bi;
        __syncthreads();
        const float* rb = g_ret + (size_t)bn * (TT * DD);
        for (int e = tid; e < 2048; e += 256) {
            float4 v = ((const float4*)rb)[e];
            int r = e >> 5, c4 = (e & 31) * 4;
            __half* dst = hs + r * LDH_H + c4;
            sth2(dst, v.x, v.y);
            sth2(dst + 2, v.z, v.w);
        }
        if (tid < 128) hds[tid] = g_hdiff[(size_t)bn * DD + tid];
        __syncthreads();

        // bias2 from h_diff half of weights
        {
            float4 hv = *(const float4*)&hds[lane * 4];
#pragma unroll
            for (int i = 0; i < 16; i++) {
                int d = w * 16 + i;
                float4 wv = *(const float4*)(mw + (size_t)d * 256 + 128 + lane * 4);
                float s = wv.x * hv.x + wv.y * hv.y + wv.z * hv.z + wv.w * hv.w;
#pragma unroll
                for (int o = 16; o; o >>= 1) s += __shfl_xor_sync(0xffffffffu, s, o);
                if (lane == 0) bias2[d] = s + mb[d];
            }
        }

        float c[4][2][4];
#pragma unroll
        for (int mt = 0; mt < 4; mt++)
#pragma unroll
            for (int nt = 0; nt < 2; nt++)
#pragma unroll
                for (int ci = 0; ci < 4; ci++) c[mt][nt][ci] = 0.f;

#pragma unroll
        for (int ks2 = 0; ks2 < 8; ks2++) {
            int off = ks2 * 16;
            unsigned a[4][4];
#pragma unroll
            for (int mt = 0; mt < 4; mt++) {
                const __half* ar0 = hs + (mt * 16 + g) * LDH_H + off + 2 * tg;
                const __half* ar1 = hs + (mt * 16 + 8 + g) * LDH_H + off + 2 * tg;
                a[mt][0] = ldh2(ar0); a[mt][1] = ldh2(ar1);
                a[mt][2] = ldh2(ar0 + 8); a[mt][3] = ldh2(ar1 + 8);
            }
#pragma unroll
            for (int nt = 0; nt < 2; nt++) {
                int nc = w * 16 + nt * 8 + g;
                const __half* br = ws + nc * LDH_H + off + 2 * tg;
                unsigned b0 = ldh2(br), b1 = ldh2(br + 8);
#pragma unroll
                for (int mt = 0; mt < 4; mt++)
                    MMA_F16(c[mt][nt], a[mt][0], a[mt][1], a[mt][2], a[mt][3], b0, b1);
            }
        }
        __syncthreads();
#pragma unroll
        for (int mt = 0; mt < 4; mt++)
#pragma unroll
            for (int nt = 0; nt < 2; nt++) {
                int col0 = w * 16 + nt * 8 + 2 * tg;
#pragma unroll
                for (int ci = 0; ci < 4; ci++) {
                    int r = mt * 16 + g + ((ci >= 2) ? 8 : 0);
                    int col = col0 + (ci & 1);
                    fob[r * 132 + col] = lrelu(c[mt][nt][ci] + bias2[col]);
                }
            }
        __syncthreads();
        float* obuf = g_h + (size_t)bn * (TT * DD);
        for (int e = tid; e < 2048; e += 256) {
            int r = e >> 5, c4 = (e & 31) * 4;
            *(float4*)&obuf[r * DD + c4] = *(float4*)&fob[r * 132 + c4];
        }
    }
}

// ---------------- head ----------------
__global__ void k_head(const float* __restrict__ h1w, const float* __restrict__ h1b,
                       const float* __restrict__ h2w, const float* __restrict__ h2b,
                       float* __restrict__ out) {
    __shared__ float wt[128 * 65];
    __shared__ float lr[128];
    __shared__ float red[2];
    int bn = blockIdx.x;
    int tid = threadIdx.x;
    for (int e = tid; e < 128; e += 64)
        lr[e] = g_h[((size_t)bn * TT + (TT - 1)) * DD + e];
    for (int e = tid; e < 64 * 128; e += 64) {
        int jj = e >> 7, k = e & 127;
        wt[k * 65 + jj] = h1w[e];
    }
    __syncthreads();
    float s = 0.f;
    for (int k = 0; k < 128; k++) s += lr[k] * wt[k * 65 + tid];
    s += h1b[tid];
    s = lrelu(s);
    s *= h2w[tid];
#pragma unroll
    for (int o = 16; o; o >>= 1) s += __shfl_down_sync(0xffffffffu, s, o);
    if ((tid & 31) == 0) red[tid >> 5] = s;
    __syncthreads();
    if (tid == 0) out[bn] = red[0] + red[1] + h2b[0];
}

// ---------------- launch ----------------
extern "C" void kernel_launch(void* const* d_in, const int* in_sizes, int n_in,
                              void* d_out, int out_size) {
    const float* x      = (const float*)d_in[0];
    const float* adj    = (const float*)d_in[1];
    const float* proj_w = (const float*)d_in[2];
    const float* proj_b = (const float*)d_in[3];
    const float* pos    = (const float*)d_in[4];
    const float* diff_w = (const float*)d_in[5];
    const float* conv_w = (const float*)d_in[6];
    const float* conv_b = (const float*)d_in[7];
    const float* wq_w   = (const float*)d_in[8];
    const float* wq_b   = (const float*)d_in[9];
    const float* wk_w   = (const float*)d_in[10];
    const float* wk_b   = (const float*)d_in[11];
    const float* wv_w   = (const float*)d_in[12];
    const float* wv_b   = (const float*)d_in[13];
    const float* gn_w   = (const float*)d_in[14];
    const float* gn_b   = (const float*)d_in[15];
    const float* gamma  = (const float*)d_in[16];
    const float* ln_w   = (const float*)d_in[17];
    const float* ln_b   = (const float*)d_in[18];
    const float* mlp_w  = (const float*)d_in[19];
    const float* mlp_b  = (const float*)d_in[20];
    const float* h1w    = (const float*)d_in[21];
    const float* h1b    = (const float*)d_in[22];
    const float* h2w    = (const float*)d_in[23];
    const float* h2b    = (const float*)d_in[24];

    cudaFuncSetAttribute(k_ret, cudaFuncAttributeMaxDynamicSharedMemorySize, RET_SMEM);
    cudaFuncSetAttribute(k_mlp, cudaFuncAttributeMaxDynamicSharedMemorySize, MLP_SMEM);
    cudaFuncSetAttribute(k_diffg, cudaFuncAttributeMaxDynamicSharedMemorySize, DG_SMEM);

    k_proj<<<BN, 128>>>(x, proj_w, proj_b, pos);
    k_adjn<<<BB * NN, 256>>>(adj);

    for (int l = 0; l < 2; l++) {
        k_ret<<<BN, 512, RET_SMEM>>>(
            wq_w + l * DD * DD, wq_b + l * DD, wk_w + l * DD * DD, wk_b + l * DD,
            wv_w + l * DD * DD, wv_b + l * DD, gn_w + l * DD, gn_b + l * DD,
            gamma + l, ln_w + l * DD, ln_b + l * DD);
        k_diffg<<<BN / 16, 256, DG_SMEM>>>(diff_w + l * DD * DD, conv_w + l * 3);
        k_hop<<<dim3(NN / 32, BB), 256>>>(conv_w + l * 3, 1, conv_b + l, 0, 0);
        k_hop<<<dim3(NN / 32, BB), 256>>>(conv_w + l * 3, 2, conv_b + l, 1, 1);
        k_mlp<<<BN / 2, 256, MLP_SMEM>>>(mlp_w + (size_t)l * DD * 2 * DD, mlp_b + l * DD);
    }
    k_head<<<BN, 64>>>(h1w, h1b, h2w, h2b, (float*)d_out);
}

// round 6
// speedup vs baseline: 4.0272x; 1.3417x over previous
#include <cuda_runtime.h>
#include <cuda_fp16.h>
#include <math.h>

#define BB 4
#define NN 512
#define BN 2048
#define TT 64
#define DD 128
#define HH 4
#define HD 32
#define EPS 1e-5f
#define LSLOPE 0.2f
#define NSM 148

__device__ __half g_h[BN * TT * DD];
__device__ __half g_ret[BN * TT * DD];
__device__ __half g_adjn[BB * NN * NN];
__device__ __half g_cur_a[BB * NN * DD];
__device__ __half g_cur_b[BB * NN * DD];
__device__ float g_bias2[BN * DD];

__device__ __forceinline__ float lrelu(float v) { return v > 0.f ? v : LSLOPE * v; }
__device__ __forceinline__ unsigned ldh2(const __half* p) { return *(const unsigned*)p; }
__device__ __forceinline__ void sth2(__half* p, float a, float b) {
    *(__half2*)p = __floats2half2_rn(a, b);
}

#define MMA_F16(C, A0, A1, A2, A3, B0, B1)                                              \
    asm volatile(                                                                       \
        "mma.sync.aligned.m16n8k16.row.col.f32.f16.f16.f32 "                            \
        "{%0,%1,%2,%3},{%4,%5,%6,%7},{%8,%9},{%0,%1,%2,%3};"                            \
        : "+f"((C)[0]), "+f"((C)[1]), "+f"((C)[2]), "+f"((C)[3])                        \
        : "r"(A0), "r"(A1), "r"(A2), "r"(A3), "r"(B0), "r"(B1))

#define RW 136
#define LDA_HOP 40
#define LDVT 72
#define LDSS 72

// ---------------- proj + pos (writes half) ----------------
__global__ void k_proj(const float* __restrict__ x, const float* __restrict__ pw,
                       const float* __restrict__ pb, const float* __restrict__ pos) {
    __shared__ float sx[TT * 8];
    int bn = blockIdx.x;
    int d = threadIdx.x;
    for (int e = d; e < TT * 8; e += 128) sx[e] = x[(size_t)bn * TT * 8 + e];
    float4 w0 = *(const float4*)(pw + d * 8);
    float4 w1 = *(const float4*)(pw + d * 8 + 4);
    float bv = pb[d];
    __syncthreads();
    __half* ob = g_h + (size_t)bn * (TT * DD);
    for (int t = 0; t < TT; t++) {
        const float* xr = &sx[t * 8];
        float s = bv + pos[t * DD + d];
        s += xr[0] * w0.x + xr[1] * w0.y + xr[2] * w0.z + xr[3] * w0.w;
        s += xr[4] * w1.x + xr[5] * w1.y + xr[6] * w1.z + xr[7] * w1.w;
        ob[t * DD + d] = __float2half(s);
    }
}

// ---------------- adj row-normalize (writes half) ----------------
__global__ void k_adjn(const float* __restrict__ adj) {
    int row = blockIdx.x;
    __shared__ float red[8];
    const float* ar = adj + (size_t)row * NN;
    float s = 0.f;
    for (int j = threadIdx.x; j < NN; j += 256) s += ar[j];
#pragma unroll
    for (int o = 16; o; o >>= 1) s += __shfl_down_sync(0xffffffffu, s, o);
    if ((threadIdx.x & 31) == 0) red[threadIdx.x >> 5] = s;
    __syncthreads();
    if (threadIdx.x == 0) {
        float t = 0.f;
#pragma unroll
        for (int w = 0; w < 8; w++) t += red[w];
        red[0] = 1.0f / (t + 1e-9f);
    }
    __syncthreads();
    float inv = red[0];
    for (int j = threadIdx.x; j < NN; j += 256)
        g_adjn[(size_t)row * NN + j] = __float2half(ar[j] * inv);
}

// ---------------- fused retention: persistent weights, many seqs per CTA ----------------
// smem halves: ws[384][136], hs/Qs[64][136], Ks[64][136], Vt[128][72], Ss 2x[64][72]
#define O_WS 0
#define O_HS 52224
#define O_KS 60928
#define O_VT 69632
#define O_SS 78848
#define RET_HALVES 88064
#define RET_SMEM (RET_HALVES * 2)

__global__ void __launch_bounds__(512, 1) k_ret(
    const float* __restrict__ wq, const float* __restrict__ bq,
    const float* __restrict__ wk, const float* __restrict__ bk,
    const float* __restrict__ wv, const float* __restrict__ bv,
    const float* __restrict__ gnw, const float* __restrict__ gnb,
    const float* __restrict__ gam,
    const float* __restrict__ lnw, const float* __restrict__ lnb) {
    extern __shared__ unsigned char smraw[];
    __half* smh = (__half*)smraw;
    __half* ws = smh + O_WS;
    __half* hs = smh + O_HS;  // aliased by Qs
    __half* Qs = hs;
    __half* Ks = smh + O_KS;
    __half* Vt = smh + O_VT;
    __shared__ float cbias[384];
    __shared__ float gpow[64];
    __shared__ float shead[8];
    __shared__ float smean[4], srstd[4];
    __shared__ float sum1[64], sum2[64];

    int tid = threadIdx.x, lane = tid & 31, w = tid >> 5, g = lane >> 2, tg = lane & 3;

    // stage ALL weights once (fp32 -> fp16)
    for (int e = tid; e < 12288; e += 512) {
        int r = e >> 5, k4 = (e & 31) * 4;
        const float* src = (r < 128) ? (wq + r * DD)
                         : (r < 256) ? (wk + (r - 128) * DD)
                                     : (wv + (r - 256) * DD);
        float4 v = *(const float4*)(src + k4);
        __half* dst = ws + r * RW + k4;
        sth2(dst, v.x, v.y);
        sth2(dst + 2, v.z, v.w);
    }
    for (int e = tid; e < 384; e += 512)
        cbias[e] = e < 128 ? bq[e] : (e < 256 ? bk[e - 128] : bv[e - 256]);
    if (tid < 64) gpow[tid] = powf(gam[0], (float)tid);

    int mq = w & 3, nq = w >> 2;
    int hsel = w >> 3, ns = w & 7;
    int mo = w & 3, nh = (w >> 2) & 1;
    __half* Sp = smh + O_SS + hsel * 4608;

    int bid = blockIdx.x;
    int s0 = (int)(((long)bid * BN) / NSM);
    int s1 = (int)(((long)(bid + 1) * BN) / NSM);

    for (int s = s0; s < s1; s++) {
        if (tid < 64) { sum1[tid] = 0.f; sum2[tid] = 0.f; }
        if (tid < 8) shead[tid] = 0.f;
        const __half* hb = g_h + (size_t)s * (TT * DD);
        for (int e = tid; e < 1024; e += 512) {
            int r = e >> 4, c8 = (e & 15) * 8;
            *(uint4*)(hs + r * RW + c8) = *(const uint4*)(hb + r * DD + c8);
        }
        __syncthreads();

        // ---- QKV: m64 n384 k128 (weights resident)
        float c[12][4];
#pragma unroll
        for (int nt = 0; nt < 12; nt++)
#pragma unroll
            for (int ci = 0; ci < 4; ci++) c[nt][ci] = 0.f;
#pragma unroll
        for (int ks2 = 0; ks2 < 8; ks2++) {
            int off = ks2 * 16;
            const __half* ar0 = hs + (mq * 16 + g) * RW + off + 2 * tg;
            const __half* ar1 = ar0 + 8 * RW;
            unsigned a0 = ldh2(ar0), a1 = ldh2(ar1);
            unsigned a2 = ldh2(ar0 + 8), a3 = ldh2(ar1 + 8);
#pragma unroll
            for (int nt = 0; nt < 12; nt++) {
                int nc = nq * 96 + nt * 8 + g;
                const __half* br = ws + nc * RW + off + 2 * tg;
                unsigned b0 = ldh2(br), b1 = ldh2(br + 8);
                MMA_F16(c[nt], a0, a1, a2, a3, b0, b1);
            }
        }
        __syncthreads();  // done reading hs

        // epilogue -> Qs(hs), Ks, Vt
        int r0e = mq * 16 + g, r1e = r0e + 8;
#pragma unroll
        for (int nt = 0; nt < 12; nt++) {
            int gc0 = nq * 96 + nt * 8 + 2 * tg;
            float v00 = c[nt][0] + cbias[gc0], v01 = c[nt][1] + cbias[gc0 + 1];
            float v10 = c[nt][2] + cbias[gc0], v11 = c[nt][3] + cbias[gc0 + 1];
            if (gc0 < 128) {
                sth2(&Qs[r0e * RW + gc0], v00, v01);
                sth2(&Qs[r1e * RW + gc0], v10, v11);
            } else if (gc0 < 256) {
                int k0 = gc0 - 128;
                sth2(&Ks[r0e * RW + k0], v00, v01);
                sth2(&Ks[r1e * RW + k0], v10, v11);
            } else {
                int d0 = gc0 - 256;
                Vt[d0 * LDVT + r0e] = __float2half(v00);
                Vt[(d0 + 1) * LDVT + r0e] = __float2half(v01);
                Vt[d0 * LDVT + r1e] = __float2half(v10);
                Vt[(d0 + 1) * LDVT + r1e] = __float2half(v11);
            }
        }
        __syncthreads();

        // ---- retention: 2 heads in parallel, 2 passes
        float oreg[2][2][4];
#pragma unroll
        for (int p = 0; p < 2; p++) {
            int hh = p * 2 + hsel, hb0 = hh * 32;
            float scC[4][4];
#pragma unroll
            for (int mt = 0; mt < 4; mt++)
#pragma unroll
                for (int ci = 0; ci < 4; ci++) scC[mt][ci] = 0.f;
#pragma unroll
            for (int ks2 = 0; ks2 < 2; ks2++) {
                int off = hb0 + ks2 * 16;
                unsigned a[4][4];
#pragma unroll
                for (int mt = 0; mt < 4; mt++) {
                    const __half* ar0 = Qs + (mt * 16 + g) * RW + off + 2 * tg;
                    const __half* ar1 = ar0 + 8 * RW;
                    a[mt][0] = ldh2(ar0); a[mt][1] = ldh2(ar1);
                    a[mt][2] = ldh2(ar0 + 8); a[mt][3] = ldh2(ar1 + 8);
                }
                const __half* br = Ks + (ns * 8 + g) * RW + off + 2 * tg;
                unsigned b0 = ldh2(br), b1 = ldh2(br + 8);
#pragma unroll
                for (int mt = 0; mt < 4; mt++)
                    MMA_F16(scC[mt], a[mt][0], a[mt][1], a[mt][2], a[mt][3], b0, b1);
            }
#pragma unroll
            for (int mt = 0; mt < 4; mt++) {
                int q0 = mt * 16 + g, q1 = q0 + 8;
                int kk2 = ns * 8 + 2 * tg;
                float v00 = (kk2 <= q0) ? scC[mt][0] * gpow[q0 - kk2] : 0.f;
                float v01 = (kk2 + 1 <= q0) ? scC[mt][1] * gpow[q0 - kk2 - 1] : 0.f;
                float v10 = (kk2 <= q1) ? scC[mt][2] * gpow[q1 - kk2] : 0.f;
                float v11 = (kk2 + 1 <= q1) ? scC[mt][3] * gpow[q1 - kk2 - 1] : 0.f;
                sth2(&Sp[q0 * LDSS + kk2], v00, v01);
                sth2(&Sp[q1 * LDSS + kk2], v10, v11);
            }
            __syncthreads();

#pragma unroll
            for (int ntl = 0; ntl < 2; ntl++)
#pragma unroll
                for (int ci = 0; ci < 4; ci++) oreg[p][ntl][ci] = 0.f;
#pragma unroll
            for (int ks2 = 0; ks2 < 4; ks2++) {
                int off = ks2 * 16;
                const __half* ar0 = Sp + (mo * 16 + g) * LDSS + off + 2 * tg;
                const __half* ar1 = ar0 + 8 * LDSS;
                unsigned a0 = ldh2(ar0), a1 = ldh2(ar1);
                unsigned a2 = ldh2(ar0 + 8), a3 = ldh2(ar1 + 8);
#pragma unroll
                for (int ntl = 0; ntl < 2; ntl++) {
                    int nc = hb0 + nh * 16 + ntl * 8 + g;
                    const __half* br = Vt + nc * LDVT + off + 2 * tg;
                    unsigned b0 = ldh2(br), b1 = ldh2(br + 8);
                    MMA_F16(oreg[p][ntl], a0, a1, a2, a3, b0, b1);
                }
            }
            float s1v = 0.f, s2v = 0.f;
#pragma unroll
            for (int ntl = 0; ntl < 2; ntl++)
#pragma unroll
                for (int ci = 0; ci < 4; ci++) {
                    float v = oreg[p][ntl][ci];
                    s1v += v; s2v += v * v;
                }
#pragma unroll
            for (int o = 16; o; o >>= 1) {
                s1v += __shfl_xor_sync(0xffffffffu, s1v, o);
                s2v += __shfl_xor_sync(0xffffffffu, s2v, o);
            }
            if (lane == 0) {
                atomicAdd(&shead[hh * 2], s1v);
                atomicAdd(&shead[hh * 2 + 1], s2v);
            }
            __syncthreads();
        }

        if (tid < 4) {
            float mean = shead[tid * 2] * (1.0f / 2048.0f);
            float var = shead[tid * 2 + 1] * (1.0f / 2048.0f) - mean * mean;
            smean[tid] = mean;
            srstd[tid] = rsqrtf(var + EPS);
        }
        __syncthreads();

        float p1[2] = {0.f, 0.f}, p2[2] = {0.f, 0.f};
#pragma unroll
        for (int p = 0; p < 2; p++) {
            int hh = p * 2 + hsel;
            float mn = smean[hh], rs = srstd[hh];
#pragma unroll
            for (int ntl = 0; ntl < 2; ntl++)
#pragma unroll
                for (int ci = 0; ci < 4; ci++) {
                    int col = hh * 32 + nh * 16 + ntl * 8 + 2 * tg + (ci & 1);
                    float v = (oreg[p][ntl][ci] - mn) * rs * gnw[col] + gnb[col];
                    oreg[p][ntl][ci] = v;
                    int hf = (ci >= 2) ? 1 : 0;
                    p1[hf] += v;
                    p2[hf] += v * v;
                }
        }
#pragma unroll
        for (int o = 1; o <= 2; o <<= 1) {
            p1[0] += __shfl_xor_sync(0xffffffffu, p1[0], o);
            p1[1] += __shfl_xor_sync(0xffffffffu, p1[1], o);
            p2[0] += __shfl_xor_sync(0xffffffffu, p2[0], o);
            p2[1] += __shfl_xor_sync(0xffffffffu, p2[1], o);
        }
        int r0 = mo * 16 + g, r1 = r0 + 8;
        if (tg == 0) {
            atomicAdd(&sum1[r0], p1[0]);
            atomicAdd(&sum2[r0], p2[0]);
            atomicAdd(&sum1[r1], p1[1]);
            atomicAdd(&sum2[r1], p2[1]);
        }
        __syncthreads();

        float mu0 = sum1[r0] * (1.0f / 128.0f);
        float rs0 = rsqrtf(sum2[r0] * (1.0f / 128.0f) - mu0 * mu0 + EPS);
        float mu1 = sum1[r1] * (1.0f / 128.0f);
        float rs1 = rsqrtf(sum2[r1] * (1.0f / 128.0f) - mu1 * mu1 + EPS);

        __half* go = g_ret + (size_t)s * (TT * DD);
#pragma unroll
        for (int p = 0; p < 2; p++) {
            int hh = p * 2 + hsel;
#pragma unroll
            for (int ntl = 0; ntl < 2; ntl++) {
                int cb = hh * 32 + nh * 16 + ntl * 8 + 2 * tg;
                float lw0 = lnw[cb], lb0 = lnb[cb];
                float lw1 = lnw[cb + 1], lb1 = lnb[cb + 1];
                sth2(&go[r0 * DD + cb], (oreg[p][ntl][0] - mu0) * rs0 * lw0 + lb0,
                     (oreg[p][ntl][1] - mu0) * rs0 * lw1 + lb1);
                sth2(&go[r1 * DD + cb], (oreg[p][ntl][2] - mu1) * rs1 * lw0 + lb0,
                     (oreg[p][ntl][3] - mu1) * rs1 * lw1 + lb1);
            }
        }
        __syncthreads();
    }
}

// ---------------- diffusion hop: P_out = adjn @ src (fp16 everywhere) ----------------
__global__ void __launch_bounds__(256, 4) k_hop(int srcSel, int dstSel) {
    __shared__ __half As[32 * LDA_HOP];
    __shared__ __half Bs[128 * LDA_HOP];
    int tid = threadIdx.x, lane = tid & 31, w = tid >> 5, g = lane >> 2, tg = lane & 3;
    int b = blockIdx.y, i0 = blockIdx.x * 32;
    const __half* srcb;
    size_t rstride;
    if (srcSel == 0) {
        srcb = g_ret + ((size_t)b * NN * TT + (TT - 1)) * DD;
        rstride = (size_t)TT * DD;
    } else {
        srcb = g_cur_a + (size_t)b * NN * DD;
        rstride = DD;
    }
    __half* dst = (dstSel ? g_cur_b : g_cur_a) + (size_t)b * NN * DD;
    const __half* adjb = g_adjn + (size_t)b * NN * NN;

    int mt2 = w & 1, nq = w >> 1;
    float c[4][4];
#pragma unroll
    for (int nt = 0; nt < 4; nt++)
#pragma unroll
        for (int ci = 0; ci < 4; ci++) c[nt][ci] = 0.f;

    for (int kc = 0; kc < NN; kc += 32) {
        __syncthreads();
        {
            int r = tid >> 3, k4 = (tid & 7) * 4;
            *(uint2*)(As + r * LDA_HOP + k4) =
                *(const uint2*)(adjb + (size_t)(i0 + r) * NN + kc + k4);
        }
        for (int e = tid; e < 1024; e += 256) {
            int kr = e >> 5, n4 = (e & 31) * 4;
            uint2 raw = *(const uint2*)(srcb + (size_t)(kc + kr) * rstride + n4);
            __half2 v0 = *(__half2*)&raw.x;
            __half2 v1 = *(__half2*)&raw.y;
            Bs[(n4 + 0) * LDA_HOP + kr] = __low2half(v0);
            Bs[(n4 + 1) * LDA_HOP + kr] = __high2half(v0);
            Bs[(n4 + 2) * LDA_HOP + kr] = __low2half(v1);
            Bs[(n4 + 3) * LDA_HOP + kr] = __high2half(v1);
        }
        __syncthreads();
#pragma unroll
        for (int ks2 = 0; ks2 < 2; ks2++) {
            int off = ks2 * 16;
            const __half* ar0 = As + (mt2 * 16 + g) * LDA_HOP + off + 2 * tg;
            const __half* ar1 = ar0 + 8 * LDA_HOP;
            unsigned a0 = ldh2(ar0), a1 = ldh2(ar1);
            unsigned a2 = ldh2(ar0 + 8), a3 = ldh2(ar1 + 8);
#pragma unroll
            for (int nt = 0; nt < 4; nt++) {
                int nc = nq * 32 + nt * 8 + g;
                const __half* br = Bs + nc * LDA_HOP + off + 2 * tg;
                unsigned b0 = ldh2(br), b1 = ldh2(br + 8);
                MMA_F16(c[nt], a0, a1, a2, a3, b0, b1);
            }
        }
    }
#pragma unroll
    for (int nt = 0; nt < 4; nt++) {
        int col0 = nq * 32 + nt * 8 + 2 * tg;
#pragma unroll
        for (int ci2 = 0; ci2 < 2; ci2++) {
            int r = mt2 * 16 + g + ci2 * 8;
            sth2(&dst[(size_t)(i0 + r) * DD + col0], c[nt][ci2 * 2], c[nt][ci2 * 2 + 1]);
        }
    }
}

// ---------------- diffusion finish: hdiff = lrelu((c0H+c1P1+c2P2)@dw^T + cb);
//                  bias2 = hdiff @ w2^T + mb  ----------------
// grid 64, m32 per CTA, 256 threads
#define DF_O_W1 0
#define DF_O_W2 17408
#define DF_O_HS 34816
#define DF_O_HD 39168
#define DF_HALVES 43520
#define DF_SMEM (DF_HALVES * 2)
__global__ void __launch_bounds__(256, 2) k_dfin(
    const float* __restrict__ dw, const float* __restrict__ mw,
    const float* __restrict__ convw, const float* __restrict__ convb,
    const float* __restrict__ mbp) {
    extern __shared__ unsigned char smraw[];
    __half* ws1 = (__half*)smraw + DF_O_W1;  // [128][136] dw
    __half* ws2 = (__half*)smraw + DF_O_W2;  // [128][136] mlp second half
    __half* hs = (__half*)smraw + DF_O_HS;   // [32][136]
    __half* hd = (__half*)smraw + DF_O_HD;   // [32][136]
    int tid = threadIdx.x, lane = tid & 31, w = tid >> 5, g = lane >> 2, tg = lane & 3;
    int row0 = blockIdx.x * 32;

    for (int e = tid; e < 4096; e += 256) {
        int r = e >> 5, k4 = (e & 31) * 4;
        float4 v = *(const float4*)(dw + (size_t)r * DD + k4);
        sth2(ws1 + r * RW + k4, v.x, v.y);
        sth2(ws1 + r * RW + k4 + 2, v.z, v.w);
        float4 v2 = *(const float4*)(mw + (size_t)r * 256 + 128 + k4);
        sth2(ws2 + r * RW + k4, v2.x, v2.y);
        sth2(ws2 + r * RW + k4 + 2, v2.z, v2.w);
    }
    float c0 = convw[0], c1 = convw[1], c2 = convw[2], cb = convb[0];
    // combine
    for (int e = tid; e < 1024; e += 256) {
        int r = e >> 5, n4 = (e & 31) * 4;
        int row = row0 + r;
        const __half* Hp = g_ret + ((size_t)row * TT + (TT - 1)) * DD + n4;
        const __half* P1p = g_cur_a + (size_t)row * DD + n4;
        const __half* P2p = g_cur_b + (size_t)row * DD + n4;
#pragma unroll
        for (int j = 0; j < 4; j += 2) {
            float h0 = __half2float(Hp[j]), h1 = __half2float(Hp[j + 1]);
            float a0 = __half2float(P1p[j]), a1 = __half2float(P1p[j + 1]);
            float b0 = __half2float(P2p[j]), b1 = __half2float(P2p[j + 1]);
            sth2(&hs[r * RW + n4 + j], c0 * h0 + c1 * a0 + c2 * b0,
                 c0 * h1 + c1 * a1 + c2 * b1);
        }
    }
    __syncthreads();

    int mt2 = w & 1, nq = w >> 1;
    // GEMM1: hd = lrelu(hs @ ws1^T + cb)
    {
        float c[4][4];
#pragma unroll
        for (int nt = 0; nt < 4; nt++)
#pragma unroll
            for (int ci = 0; ci < 4; ci++) c[nt][ci] = 0.f;
#pragma unroll
        for (int ks2 = 0; ks2 < 8; ks2++) {
            int off = ks2 * 16;
            const __half* ar0 = hs + (mt2 * 16 + g) * RW + off + 2 * tg;
            const __half* ar1 = ar0 + 8 * RW;
            unsigned a0 = ldh2(ar0), a1 = ldh2(ar1);
            unsigned a2 = ldh2(ar0 + 8), a3 = ldh2(ar1 + 8);
#pragma unroll
            for (int nt = 0; nt < 4; nt++) {
                int nc = nq * 32 + nt * 8 + g;
                const __half* br = ws1 + nc * RW + off + 2 * tg;
                unsigned b0 = ldh2(br), b1 = ldh2(br + 8);
                MMA_F16(c[nt], a0, a1, a2, a3, b0, b1);
            }
        }
#pragma unroll
        for (int nt = 0; nt < 4; nt++) {
            int col0 = nq * 32 + nt * 8 + 2 * tg;
#pragma unroll
            for (int ci2 = 0; ci2 < 2; ci2++) {
                int r = mt2 * 16 + g + ci2 * 8;
                sth2(&hd[r * RW + col0], lrelu(c[nt][ci2 * 2] + cb),
                     lrelu(c[nt][ci2 * 2 + 1] + cb));
            }
        }
    }
    __syncthreads();
    // GEMM2: bias2 = hd @ ws2^T + mb
    {
        float c[4][4];
#pragma unroll
        for (int nt = 0; nt < 4; nt++)
#pragma unroll
            for (int ci = 0; ci < 4; ci++) c[nt][ci] = 0.f;
#pragma unroll
        for (int ks2 = 0; ks2 < 8; ks2++) {
            int off = ks2 * 16;
            const __half* ar0 = hd + (mt2 * 16 + g) * RW + off + 2 * tg;
            const __half* ar1 = ar0 + 8 * RW;
            unsigned a0 = ldh2(ar0), a1 = ldh2(ar1);
            unsigned a2 = ldh2(ar0 + 8), a3 = ldh2(ar1 + 8);
#pragma unroll
            for (int nt = 0; nt < 4; nt++) {
                int nc = nq * 32 + nt * 8 + g;
                const __half* br = ws2 + nc * RW + off + 2 * tg;
                unsigned b0 = ldh2(br), b1 = ldh2(br + 8);
                MMA_F16(c[nt], a0, a1, a2, a3, b0, b1);
            }
        }
#pragma unroll
        for (int nt = 0; nt < 4; nt++) {
            int col0 = nq * 32 + nt * 8 + 2 * tg;
            float m0 = mbp[col0], m1 = mbp[col0 + 1];
#pragma unroll
            for (int ci2 = 0; ci2 < 2; ci2++) {
                int r = mt2 * 16 + g + ci2 * 8;
                float2 ov = make_float2(c[nt][ci2 * 2] + m0, c[nt][ci2 * 2 + 1] + m1);
                *(float2*)&g_bias2[(size_t)(row0 + r) * DD + col0] = ov;
            }
        }
    }
}

// ---------------- MLP: persistent weights, 8 seqs per CTA ----------------
#define MLP_O_WS 0
#define MLP_O_HS 17408
#define MLP_HALVES 26112
#define MLP_SMEM (MLP_HALVES * 2)
__global__ void __launch_bounds__(256) k_mlp(const float* __restrict__ mw) {
    extern __shared__ unsigned char smraw[];
    __half* ws = (__half*)smraw + MLP_O_WS;  // [128][136]
    __half* hs = (__half*)smraw + MLP_O_HS;  // [64][136]
    __shared__ float sb[128];
    int tid = threadIdx.x, lane = tid & 31, w = tid >> 5, g = lane >> 2, tg = lane & 3;

    for (int e = tid; e < 4096; e += 256) {
        int r = e >> 5, k4 = (e & 31) * 4;
        float4 v = *(const float4*)(mw + (size_t)r * 256 + k4);
        sth2(ws + r * RW + k4, v.x, v.y);
        sth2(ws + r * RW + k4 + 2, v.z, v.w);
    }

    for (int bi = 0; bi < 8; bi++) {
        int s = blockIdx.x * 8 + bi;
        const __half* rb = g_ret + (size_t)s * (TT * DD);
        for (int e = tid; e < 1024; e += 256) {
            int r = e >> 4, c8 = (e & 15) * 8;
            *(uint4*)(hs + r * RW + c8) = *(const uint4*)(rb + r * DD + c8);
        }
        if (tid < 128) sb[tid] = g_bias2[(size_t)s * DD + tid];
        __syncthreads();

        float c[4][2][4];
#pragma unroll
        for (int mt = 0; mt < 4; mt++)
#pragma unroll
            for (int nt = 0; nt < 2; nt++)
#pragma unroll
                for (int ci = 0; ci < 4; ci++) c[mt][nt][ci] = 0.f;
#pragma unroll
        for (int ks2 = 0; ks2 < 8; ks2++) {
            int off = ks2 * 16;
            unsigned a[4][4];
#pragma unroll
            for (int mt = 0; mt < 4; mt++) {
                const __half* ar0 = hs + (mt * 16 + g) * RW + off + 2 * tg;
                const __half* ar1 = ar0 + 8 * RW;
                a[mt][0] = ldh2(ar0); a[mt][1] = ldh2(ar1);
                a[mt][2] = ldh2(ar0 + 8); a[mt][3] = ldh2(ar1 + 8);
            }
#pragma unroll
            for (int nt = 0; nt < 2; nt++) {
                int nc = w * 16 + nt * 8 + g;
                const __half* br = ws + nc * RW + off + 2 * tg;
                unsigned b0 = ldh2(br), b1 = ldh2(br + 8);
#pragma unroll
                for (int mt = 0; mt < 4; mt++)
                    MMA_F16(c[mt][nt], a[mt][0], a[mt][1], a[mt][2], a[mt][3], b0, b1);
            }
        }
        __half* gh = g_h + (size_t)s * (TT * DD);
#pragma unroll
        for (int mt = 0; mt < 4; mt++)
#pragma unroll
            for (int nt = 0; nt < 2; nt++) {
                int col0 = w * 16 + nt * 8 + 2 * tg;
                float b0 = sb[col0], b1 = sb[col0 + 1];
#pragma unroll
                for (int ci2 = 0; ci2 < 2; ci2++) {
                    int r = mt * 16 + g + ci2 * 8;
                    sth2(&gh[r * DD + col0], lrelu(c[mt][nt][ci2 * 2] + b0),
                         lrelu(c[mt][nt][ci2 * 2 + 1] + b1));
                }
            }
        __syncthreads();
    }
}

// ---------------- head ----------------
__global__ void k_head(const float* __restrict__ h1w, const float* __restrict__ h1b,
                       const float* __restrict__ h2w, const float* __restrict__ h2b,
                       float* __restrict__ out) {
    __shared__ float wt[128 * 65];
    __shared__ float lr[128];
    __shared__ float red[2];
    int bn = blockIdx.x;
    int tid = threadIdx.x;
    for (int e = tid; e < 128; e += 64)
        lr[e] = __half2float(g_h[((size_t)bn * TT + (TT - 1)) * DD + e]);
    for (int e = tid; e < 64 * 128; e += 64) {
        int jj = e >> 7, k = e & 127;
        wt[k * 65 + jj] = h1w[e];
    }
    __syncthreads();
    float s = 0.f;
    for (int k = 0; k < 128; k++) s += lr[k] * wt[k * 65 + tid];
    s += h1b[tid];
    s = lrelu(s);
    s *= h2w[tid];
#pragma unroll
    for (int o = 16; o; o >>= 1) s += __shfl_down_sync(0xffffffffu, s, o);
    if ((tid & 31) == 0) red[tid >> 5] = s;
    __syncthreads();
    if (tid == 0) out[bn] = red[0] + red[1] + h2b[0];
}

// ---------------- launch ----------------
extern "C" void kernel_launch(void* const* d_in, const int* in_sizes, int n_in,
                              void* d_out, int out_size) {
    const float* x      = (const float*)d_in[0];
    const float* adj    = (const float*)d_in[1];
    const float* proj_w = (const float*)d_in[2];
    const float* proj_b = (const float*)d_in[3];
    const float* pos    = (const float*)d_in[4];
    const float* diff_w = (const float*)d_in[5];
    const float* conv_w = (const float*)d_in[6];
    const float* conv_b = (const float*)d_in[7];
    const float* wq_w   = (const float*)d_in[8];
    const float* wq_b   = (const float*)d_in[9];
    const float* wk_w   = (const float*)d_in[10];
    const float* wk_b   = (const float*)d_in[11];
    const float* wv_w   = (const float*)d_in[12];
    const float* wv_b   = (const float*)d_in[13];
    const float* gn_w   = (const float*)d_in[14];
    const float* gn_b   = (const float*)d_in[15];
    const float* gamma  = (const float*)d_in[16];
    const float* ln_w   = (const float*)d_in[17];
    const float* ln_b   = (const float*)d_in[18];
    const float* mlp_w  = (const float*)d_in[19];
    const float* mlp_b  = (const float*)d_in[20];
    const float* h1w    = (const float*)d_in[21];
    const float* h1b    = (const float*)d_in[22];
    const float* h2w    = (const float*)d_in[23];
    const float* h2b    = (const float*)d_in[24];

    cudaFuncSetAttribute(k_ret, cudaFuncAttributeMaxDynamicSharedMemorySize, RET_SMEM);
    cudaFuncSetAttribute(k_mlp, cudaFuncAttributeMaxDynamicSharedMemorySize, MLP_SMEM);
    cudaFuncSetAttribute(k_dfin, cudaFuncAttributeMaxDynamicSharedMemorySize, DF_SMEM);

    k_proj<<<BN, 128>>>(x, proj_w, proj_b, pos);
    k_adjn<<<BB * NN, 256>>>(adj);

    for (int l = 0; l < 2; l++) {
        k_ret<<<NSM, 512, RET_SMEM>>>(
            wq_w + l * DD * DD, wq_b + l * DD, wk_w + l * DD * DD, wk_b + l * DD,
            wv_w + l * DD * DD, wv_b + l * DD, gn_w + l * DD, gn_b + l * DD,
            gamma + l, ln_w + l * DD, ln_b + l * DD);
        k_hop<<<dim3(NN / 32, BB), 256>>>(0, 0);  // P1 = A @ H_last -> cur_a
        k_hop<<<dim3(NN / 32, BB), 256>>>(1, 1);  // P2 = A @ P1     -> cur_b
        k_dfin<<<BN / 32, 256, DF_SMEM>>>(diff_w + l * DD * DD,
                                          mlp_w + (size_t)l * DD * 2 * DD,
                                          conv_w + l * 3, conv_b + l, mlp_b + l * DD);
        k_mlp<<<BN / 8, 256, MLP_SMEM>>>(mlp_w + (size_t)l * DD * 2 * DD);
    }
    k_head<<<BN, 64>>>(h1w, h1b, h2w, h2b, (float*)d_out);
}

// round 7
// speedup vs baseline: 4.4661x; 1.1090x over previous
#include <cuda_runtime.h>
#include <cuda_fp16.h>
#include <math.h>

#define BB 4
#define NN 512
#define BN 2048
#define TT 64
#define DD 128
#define HH 4
#define HD 32
#define EPS 1e-5f
#define LSLOPE 0.2f
#define NSM 148

__device__ __half g_h[BN * TT * DD];
__device__ __half g_ret[BN * TT * DD];
__device__ __half g_adjn[BB * NN * NN];
__device__ __half g_hlT[BB * DD * NN];     // H_last transposed [b][d][i]
__device__ __half g_curT_a[BB * DD * NN];  // P1 transposed
__device__ __half g_curT_b[BB * DD * NN];  // P2 transposed
__device__ float g_bias2[BN * DD];

__device__ __forceinline__ float lrelu(float v) { return v > 0.f ? v : LSLOPE * v; }
__device__ __forceinline__ unsigned ldh2(const __half* p) { return *(const unsigned*)p; }
__device__ __forceinline__ void sth2(__half* p, float a, float b) {
    *(__half2*)p = __floats2half2_rn(a, b);
}

#define MMA_F16(C, A0, A1, A2, A3, B0, B1)                                              \
    asm volatile(                                                                       \
        "mma.sync.aligned.m16n8k16.row.col.f32.f16.f16.f32 "                            \
        "{%0,%1,%2,%3},{%4,%5,%6,%7},{%8,%9},{%0,%1,%2,%3};"                            \
        : "+f"((C)[0]), "+f"((C)[1]), "+f"((C)[2]), "+f"((C)[3])                        \
        : "r"(A0), "r"(A1), "r"(A2), "r"(A3), "r"(B0), "r"(B1))

#define RW 136
#define LDVT 72
#define LDSS 72
#define HX_LD 72

// ---------------- proj + pos (writes half) ----------------
__global__ void k_proj(const float* __restrict__ x, const float* __restrict__ pw,
                       const float* __restrict__ pb, const float* __restrict__ pos) {
    __shared__ float sx[TT * 8];
    int bn = blockIdx.x;
    int d = threadIdx.x;
    for (int e = d; e < TT * 8; e += 128) sx[e] = x[(size_t)bn * TT * 8 + e];
    float4 w0 = *(const float4*)(pw + d * 8);
    float4 w1 = *(const float4*)(pw + d * 8 + 4);
    float bv = pb[d];
    __syncthreads();
    __half* ob = g_h + (size_t)bn * (TT * DD);
    for (int t = 0; t < TT; t++) {
        const float* xr = &sx[t * 8];
        float s = bv + pos[t * DD + d];
        s += xr[0] * w0.x + xr[1] * w0.y + xr[2] * w0.z + xr[3] * w0.w;
        s += xr[4] * w1.x + xr[5] * w1.y + xr[6] * w1.z + xr[7] * w1.w;
        ob[t * DD + d] = __float2half(s);
    }
}

// ---------------- adj row-normalize (writes half) ----------------
__global__ void k_adjn(const float* __restrict__ adj) {
    int row = blockIdx.x;
    __shared__ float red[8];
    const float* ar = adj + (size_t)row * NN;
    float s = 0.f;
    for (int j = threadIdx.x; j < NN; j += 256) s += ar[j];
#pragma unroll
    for (int o = 16; o; o >>= 1) s += __shfl_down_sync(0xffffffffu, s, o);
    if ((threadIdx.x & 31) == 0) red[threadIdx.x >> 5] = s;
    __syncthreads();
    if (threadIdx.x == 0) {
        float t = 0.f;
#pragma unroll
        for (int w = 0; w < 8; w++) t += red[w];
        red[0] = 1.0f / (t + 1e-9f);
    }
    __syncthreads();
    float inv = red[0];
    for (int j = threadIdx.x; j < NN; j += 256)
        g_adjn[(size_t)row * NN + j] = __float2half(ar[j] * inv);
}

// ---------------- fused retention: persistent weights ----------------
#define O_WS 0
#define O_HS 52224
#define O_KS 60928
#define O_VT 69632
#define O_SS 78848
#define RET_HALVES 88064
#define RET_SMEM (RET_HALVES * 2)

__global__ void __launch_bounds__(512, 1) k_ret(
    const float* __restrict__ wq, const float* __restrict__ bq,
    const float* __restrict__ wk, const float* __restrict__ bk,
    const float* __restrict__ wv, const float* __restrict__ bv,
    const float* __restrict__ gnw, const float* __restrict__ gnb,
    const float* __restrict__ gam,
    const float* __restrict__ lnw, const float* __restrict__ lnb) {
    extern __shared__ unsigned char smraw[];
    __half* smh = (__half*)smraw;
    __half* ws = smh + O_WS;
    __half* hs = smh + O_HS;
    __half* Qs = hs;
    __half* Ks = smh + O_KS;
    __half* Vt = smh + O_VT;
    __shared__ float cbias[384];
    __shared__ float gpow[64];
    __shared__ float shead[8];
    __shared__ float smean[4], srstd[4];
    __shared__ float sum1[64], sum2[64];

    int tid = threadIdx.x, lane = tid & 31, w = tid >> 5, g = lane >> 2, tg = lane & 3;

    for (int e = tid; e < 12288; e += 512) {
        int r = e >> 5, k4 = (e & 31) * 4;
        const float* src = (r < 128) ? (wq + r * DD)
                         : (r < 256) ? (wk + (r - 128) * DD)
                                     : (wv + (r - 256) * DD);
        float4 v = *(const float4*)(src + k4);
        __half* dst = ws + r * RW + k4;
        sth2(dst, v.x, v.y);
        sth2(dst + 2, v.z, v.w);
    }
    for (int e = tid; e < 384; e += 512)
        cbias[e] = e < 128 ? bq[e] : (e < 256 ? bk[e - 128] : bv[e - 256]);
    if (tid < 64) gpow[tid] = powf(gam[0], (float)tid);

    int mq = w & 3, nq = w >> 2;
    int hsel = w >> 3, ns = w & 7;
    int mo = w & 3, nh = (w >> 2) & 1;
    __half* Sp = smh + O_SS + hsel * 4608;

    int bid = blockIdx.x;
    int s0 = (int)(((long)bid * BN) / NSM);
    int s1 = (int)(((long)(bid + 1) * BN) / NSM);

    for (int s = s0; s < s1; s++) {
        if (tid < 64) { sum1[tid] = 0.f; sum2[tid] = 0.f; }
        if (tid < 8) shead[tid] = 0.f;
        const __half* hb = g_h + (size_t)s * (TT * DD);
        for (int e = tid; e < 1024; e += 512) {
            int r = e >> 4, c8 = (e & 15) * 8;
            *(uint4*)(hs + r * RW + c8) = *(const uint4*)(hb + r * DD + c8);
        }
        __syncthreads();

        // ---- QKV: m64 n384 k128
        float c[12][4];
#pragma unroll
        for (int nt = 0; nt < 12; nt++)
#pragma unroll
            for (int ci = 0; ci < 4; ci++) c[nt][ci] = 0.f;
#pragma unroll
        for (int ks2 = 0; ks2 < 8; ks2++) {
            int off = ks2 * 16;
            const __half* ar0 = hs + (mq * 16 + g) * RW + off + 2 * tg;
            const __half* ar1 = ar0 + 8 * RW;
            unsigned a0 = ldh2(ar0), a1 = ldh2(ar1);
            unsigned a2 = ldh2(ar0 + 8), a3 = ldh2(ar1 + 8);
#pragma unroll
            for (int nt = 0; nt < 12; nt++) {
                int nc = nq * 96 + nt * 8 + g;
                const __half* br = ws + nc * RW + off + 2 * tg;
                unsigned b0 = ldh2(br), b1 = ldh2(br + 8);
                MMA_F16(c[nt], a0, a1, a2, a3, b0, b1);
            }
        }
        __syncthreads();

        int r0e = mq * 16 + g, r1e = r0e + 8;
#pragma unroll
        for (int nt = 0; nt < 12; nt++) {
            int gc0 = nq * 96 + nt * 8 + 2 * tg;
            float v00 = c[nt][0] + cbias[gc0], v01 = c[nt][1] + cbias[gc0 + 1];
            float v10 = c[nt][2] + cbias[gc0], v11 = c[nt][3] + cbias[gc0 + 1];
            if (gc0 < 128) {
                sth2(&Qs[r0e * RW + gc0], v00, v01);
                sth2(&Qs[r1e * RW + gc0], v10, v11);
            } else if (gc0 < 256) {
                int k0 = gc0 - 128;
                sth2(&Ks[r0e * RW + k0], v00, v01);
                sth2(&Ks[r1e * RW + k0], v10, v11);
            } else {
                int d0 = gc0 - 256;
                Vt[d0 * LDVT + r0e] = __float2half(v00);
                Vt[(d0 + 1) * LDVT + r0e] = __float2half(v01);
                Vt[d0 * LDVT + r1e] = __float2half(v10);
                Vt[(d0 + 1) * LDVT + r1e] = __float2half(v11);
            }
        }
        __syncthreads();

        float oreg[2][2][4];
#pragma unroll
        for (int p = 0; p < 2; p++) {
            int hh = p * 2 + hsel, hb0 = hh * 32;
            float scC[4][4];
#pragma unroll
            for (int mt = 0; mt < 4; mt++)
#pragma unroll
                for (int ci = 0; ci < 4; ci++) scC[mt][ci] = 0.f;
#pragma unroll
            for (int ks2 = 0; ks2 < 2; ks2++) {
                int off = hb0 + ks2 * 16;
                unsigned a[4][4];
#pragma unroll
                for (int mt = 0; mt < 4; mt++) {
                    const __half* ar0 = Qs + (mt * 16 + g) * RW + off + 2 * tg;
                    const __half* ar1 = ar0 + 8 * RW;
                    a[mt][0] = ldh2(ar0); a[mt][1] = ldh2(ar1);
                    a[mt][2] = ldh2(ar0 + 8); a[mt][3] = ldh2(ar1 + 8);
                }
                const __half* br = Ks + (ns * 8 + g) * RW + off + 2 * tg;
                unsigned b0 = ldh2(br), b1 = ldh2(br + 8);
#pragma unroll
                for (int mt = 0; mt < 4; mt++)
                    MMA_F16(scC[mt], a[mt][0], a[mt][1], a[mt][2], a[mt][3], b0, b1);
            }
#pragma unroll
            for (int mt = 0; mt < 4; mt++) {
                int q0 = mt * 16 + g, q1 = q0 + 8;
                int kk2 = ns * 8 + 2 * tg;
                float v00 = (kk2 <= q0) ? scC[mt][0] * gpow[q0 - kk2] : 0.f;
                float v01 = (kk2 + 1 <= q0) ? scC[mt][1] * gpow[q0 - kk2 - 1] : 0.f;
                float v10 = (kk2 <= q1) ? scC[mt][2] * gpow[q1 - kk2] : 0.f;
                float v11 = (kk2 + 1 <= q1) ? scC[mt][3] * gpow[q1 - kk2 - 1] : 0.f;
                sth2(&Sp[q0 * LDSS + kk2], v00, v01);
                sth2(&Sp[q1 * LDSS + kk2], v10, v11);
            }
            __syncthreads();

#pragma unroll
            for (int ntl = 0; ntl < 2; ntl++)
#pragma unroll
                for (int ci = 0; ci < 4; ci++) oreg[p][ntl][ci] = 0.f;
#pragma unroll
            for (int ks2 = 0; ks2 < 4; ks2++) {
                int off = ks2 * 16;
                const __half* ar0 = Sp + (mo * 16 + g) * LDSS + off + 2 * tg;
                const __half* ar1 = ar0 + 8 * LDSS;
                unsigned a0 = ldh2(ar0), a1 = ldh2(ar1);
                unsigned a2 = ldh2(ar0 + 8), a3 = ldh2(ar1 + 8);
#pragma unroll
                for (int ntl = 0; ntl < 2; ntl++) {
                    int nc = hb0 + nh * 16 + ntl * 8 + g;
                    const __half* br = Vt + nc * LDVT + off + 2 * tg;
                    unsigned b0 = ldh2(br), b1 = ldh2(br + 8);
                    MMA_F16(oreg[p][ntl], a0, a1, a2, a3, b0, b1);
                }
            }
            float s1v = 0.f, s2v = 0.f;
#pragma unroll
            for (int ntl = 0; ntl < 2; ntl++)
#pragma unroll
                for (int ci = 0; ci < 4; ci++) {
                    float v = oreg[p][ntl][ci];
                    s1v += v; s2v += v * v;
                }
#pragma unroll
            for (int o = 16; o; o >>= 1) {
                s1v += __shfl_xor_sync(0xffffffffu, s1v, o);
                s2v += __shfl_xor_sync(0xffffffffu, s2v, o);
            }
            if (lane == 0) {
                atomicAdd(&shead[hh * 2], s1v);
                atomicAdd(&shead[hh * 2 + 1], s2v);
            }
            __syncthreads();
        }

        if (tid < 4) {
            float mean = shead[tid * 2] * (1.0f / 2048.0f);
            float var = shead[tid * 2 + 1] * (1.0f / 2048.0f) - mean * mean;
            smean[tid] = mean;
            srstd[tid] = rsqrtf(var + EPS);
        }
        __syncthreads();

        float p1[2] = {0.f, 0.f}, p2[2] = {0.f, 0.f};
#pragma unroll
        for (int p = 0; p < 2; p++) {
            int hh = p * 2 + hsel;
            float mn = smean[hh], rs = srstd[hh];
#pragma unroll
            for (int ntl = 0; ntl < 2; ntl++)
#pragma unroll
                for (int ci = 0; ci < 4; ci++) {
                    int col = hh * 32 + nh * 16 + ntl * 8 + 2 * tg + (ci & 1);
                    float v = (oreg[p][ntl][ci] - mn) * rs * gnw[col] + gnb[col];
                    oreg[p][ntl][ci] = v;
                    int hf = (ci >= 2) ? 1 : 0;
                    p1[hf] += v;
                    p2[hf] += v * v;
                }
        }
#pragma unroll
        for (int o = 1; o <= 2; o <<= 1) {
            p1[0] += __shfl_xor_sync(0xffffffffu, p1[0], o);
            p1[1] += __shfl_xor_sync(0xffffffffu, p1[1], o);
            p2[0] += __shfl_xor_sync(0xffffffffu, p2[0], o);
            p2[1] += __shfl_xor_sync(0xffffffffu, p2[1], o);
        }
        int r0 = mo * 16 + g, r1 = r0 + 8;
        if (tg == 0) {
            atomicAdd(&sum1[r0], p1[0]);
            atomicAdd(&sum2[r0], p2[0]);
            atomicAdd(&sum1[r1], p1[1]);
            atomicAdd(&sum2[r1], p2[1]);
        }
        __syncthreads();

        float mu0 = sum1[r0] * (1.0f / 128.0f);
        float rs0 = rsqrtf(sum2[r0] * (1.0f / 128.0f) - mu0 * mu0 + EPS);
        float mu1 = sum1[r1] * (1.0f / 128.0f);
        float rs1 = rsqrtf(sum2[r1] * (1.0f / 128.0f) - mu1 * mu1 + EPS);

        __half* go = g_ret + (size_t)s * (TT * DD);
        int bb = s >> 9, ii = s & 511;
#pragma unroll
        for (int p = 0; p < 2; p++) {
            int hh = p * 2 + hsel;
#pragma unroll
            for (int ntl = 0; ntl < 2; ntl++) {
                int cb = hh * 32 + nh * 16 + ntl * 8 + 2 * tg;
                float lw0 = lnw[cb], lb0 = lnb[cb];
                float lw1 = lnw[cb + 1], lb1 = lnb[cb + 1];
                float u0 = (oreg[p][ntl][0] - mu0) * rs0 * lw0 + lb0;
                float u1 = (oreg[p][ntl][1] - mu0) * rs0 * lw1 + lb1;
                float w1x = (oreg[p][ntl][2] - mu1) * rs1 * lw0 + lb0;
                float w1y = (oreg[p][ntl][3] - mu1) * rs1 * lw1 + lb1;
                sth2(&go[r0 * DD + cb], u0, u1);
                sth2(&go[r1 * DD + cb], w1x, w1y);
                if (r1 == 63) {
                    g_hlT[((size_t)bb * DD + cb) * NN + ii] = __float2half(w1x);
                    g_hlT[((size_t)bb * DD + cb + 1) * NN + ii] = __float2half(w1y);
                }
            }
        }
        __syncthreads();
    }
}

// ---------------- transposed diffusion hop: Pt[d][i] = sum_j Xt[d][j] * A[i][j] ----------------
__global__ void __launch_bounds__(256, 4) k_hopT(int sel) {
    __shared__ __half Xs[128 * HX_LD];
    __shared__ __half Asb[16 * HX_LD];
    int tid = threadIdx.x, lane = tid & 31, w = tid >> 5, g = lane >> 2, tg = lane & 3;
    int b = blockIdx.y, i0 = blockIdx.x * 16;
    const __half* src = (sel ? g_curT_a : g_hlT) + (size_t)b * DD * NN;
    __half* dst = (sel ? g_curT_b : g_curT_a) + (size_t)b * DD * NN;
    const __half* adjb = g_adjn + (size_t)b * NN * NN;

    float c[2][4];
#pragma unroll
    for (int nt = 0; nt < 2; nt++)
#pragma unroll
        for (int ci = 0; ci < 4; ci++) c[nt][ci] = 0.f;

    for (int kc = 0; kc < NN; kc += 64) {
        __syncthreads();
        for (int e = tid; e < 1024; e += 256) {
            int r = e >> 3, u8 = (e & 7) * 8;
            *(uint4*)(Xs + r * HX_LD + u8) = *(const uint4*)(src + (size_t)r * NN + kc + u8);
        }
        if (tid < 128) {
            int r = tid >> 3, u8 = (tid & 7) * 8;
            *(uint4*)(Asb + r * HX_LD + u8) =
                *(const uint4*)(adjb + (size_t)(i0 + r) * NN + kc + u8);
        }
        __syncthreads();
#pragma unroll
        for (int ks2 = 0; ks2 < 4; ks2++) {
            int off = ks2 * 16;
            const __half* ar0 = Xs + (w * 16 + g) * HX_LD + off + 2 * tg;
            const __half* ar1 = ar0 + 8 * HX_LD;
            unsigned a0 = ldh2(ar0), a1 = ldh2(ar1);
            unsigned a2 = ldh2(ar0 + 8), a3 = ldh2(ar1 + 8);
#pragma unroll
            for (int nt = 0; nt < 2; nt++) {
                const __half* br = Asb + (nt * 8 + g) * HX_LD + off + 2 * tg;
                unsigned b0 = ldh2(br), b1 = ldh2(br + 8);
                MMA_F16(c[nt], a0, a1, a2, a3, b0, b1);
            }
        }
    }
    int m0 = w * 16 + g;
#pragma unroll
    for (int nt = 0; nt < 2; nt++) {
        int n = nt * 8 + 2 * tg;
        sth2(&dst[(size_t)m0 * NN + i0 + n], c[nt][0], c[nt][1]);
        sth2(&dst[(size_t)(m0 + 8) * NN + i0 + n], c[nt][2], c[nt][3]);
    }
}

// ---------------- diffusion finish ----------------
#define DF_O_W1 0
#define DF_O_W2 17408
#define DF_O_HS 34816
#define DF_O_HD 39168
#define DF_HALVES 43520
#define LDF 133
#define DF_SMEM (DF_HALVES * 2 + 32 * LDF * 4)
__global__ void __launch_bounds__(256, 2) k_dfin(
    const float* __restrict__ dw, const float* __restrict__ mw,
    const float* __restrict__ convw, const float* __restrict__ convb,
    const float* __restrict__ mbp) {
    extern __shared__ unsigned char smraw[];
    __half* ws1 = (__half*)smraw + DF_O_W1;
    __half* ws2 = (__half*)smraw + DF_O_W2;
    __half* hs = (__half*)smraw + DF_O_HS;
    __half* hd = (__half*)smraw + DF_O_HD;
    float* fcomb = (float*)(smraw + DF_HALVES * 2);
    int tid = threadIdx.x, lane = tid & 31, w = tid >> 5, g = lane >> 2, tg = lane & 3;
    int row0 = blockIdx.x * 32;
    int b = row0 >> 9, i0 = row0 & 511;

    for (int e = tid; e < 4096; e += 256) {
        int r = e >> 5, k4 = (e & 31) * 4;
        float4 v = *(const float4*)(dw + (size_t)r * DD + k4);
        sth2(ws1 + r * RW + k4, v.x, v.y);
        sth2(ws1 + r * RW + k4 + 2, v.z, v.w);
        float4 v2 = *(const float4*)(mw + (size_t)r * 256 + 128 + k4);
        sth2(ws2 + r * RW + k4, v2.x, v2.y);
        sth2(ws2 + r * RW + k4 + 2, v2.z, v2.w);
    }
    float c0 = convw[0], c1 = convw[1], c2 = convw[2], cb = convb[0];
    // pass A: c0 * H_last (coalesced row reads)
    for (int e = tid; e < 1024; e += 256) {
        int r = e >> 5, n4 = (e & 31) * 4;
        const __half* Hp = g_ret + ((size_t)(row0 + r) * TT + (TT - 1)) * DD + n4;
        uint2 raw = *(const uint2*)Hp;
        __half2 h0 = *(__half2*)&raw.x, h1 = *(__half2*)&raw.y;
        float* f = fcomb + r * LDF + n4;
        f[0] = c0 * __low2float(h0); f[1] = c0 * __high2float(h0);
        f[2] = c0 * __low2float(h1); f[3] = c0 * __high2float(h1);
    }
    __syncthreads();
    // pass B: + c1*P1 + c2*P2 (transposed coalesced reads)
    for (int e = tid; e < 2048; e += 256) {
        int d = e >> 4, i2 = (e & 15) * 2;
        size_t idx = ((size_t)b * DD + d) * NN + i0 + i2;
        __half2 pa = *(const __half2*)&g_curT_a[idx];
        __half2 pb2 = *(const __half2*)&g_curT_b[idx];
        fcomb[i2 * LDF + d] += c1 * __low2float(pa) + c2 * __low2float(pb2);
        fcomb[(i2 + 1) * LDF + d] += c1 * __high2float(pa) + c2 * __high2float(pb2);
    }
    __syncthreads();
    for (int e = tid; e < 2048; e += 256) {
        int r = e >> 6, d2 = (e & 63) * 2;
        sth2(&hs[r * RW + d2], fcomb[r * LDF + d2], fcomb[r * LDF + d2 + 1]);
    }
    __syncthreads();

    int mt2 = w & 1, nq = w >> 1;
    // GEMM1: hd = lrelu(hs @ ws1^T + cb)
    {
        float c[4][4];
#pragma unroll
        for (int nt = 0; nt < 4; nt++)
#pragma unroll
            for (int ci = 0; ci < 4; ci++) c[nt][ci] = 0.f;
#pragma unroll
        for (int ks2 = 0; ks2 < 8; ks2++) {
            int off = ks2 * 16;
            const __half* ar0 = hs + (mt2 * 16 + g) * RW + off + 2 * tg;
            const __half* ar1 = ar0 + 8 * RW;
            unsigned a0 = ldh2(ar0), a1 = ldh2(ar1);
            unsigned a2 = ldh2(ar0 + 8), a3 = ldh2(ar1 + 8);
#pragma unroll
            for (int nt = 0; nt < 4; nt++) {
                int nc = nq * 32 + nt * 8 + g;
                const __half* br = ws1 + nc * RW + off + 2 * tg;
                unsigned b0 = ldh2(br), b1 = ldh2(br + 8);
                MMA_F16(c[nt], a0, a1, a2, a3, b0, b1);
            }
        }
#pragma unroll
        for (int nt = 0; nt < 4; nt++) {
            int col0 = nq * 32 + nt * 8 + 2 * tg;
#pragma unroll
            for (int ci2 = 0; ci2 < 2; ci2++) {
                int r = mt2 * 16 + g + ci2 * 8;
                sth2(&hd[r * RW + col0], lrelu(c[nt][ci2 * 2] + cb),
                     lrelu(c[nt][ci2 * 2 + 1] + cb));
            }
        }
    }
    __syncthreads();
    // GEMM2: bias2 = hd @ ws2^T + mb
    {
        float c[4][4];
#pragma unroll
        for (int nt = 0; nt < 4; nt++)
#pragma unroll
            for (int ci = 0; ci < 4; ci++) c[nt][ci] = 0.f;
#pragma unroll
        for (int ks2 = 0; ks2 < 8; ks2++) {
            int off = ks2 * 16;
            const __half* ar0 = hd + (mt2 * 16 + g) * RW + off + 2 * tg;
            const __half* ar1 = ar0 + 8 * RW;
            unsigned a0 = ldh2(ar0), a1 = ldh2(ar1);
            unsigned a2 = ldh2(ar0 + 8), a3 = ldh2(ar1 + 8);
#pragma unroll
            for (int nt = 0; nt < 4; nt++) {
                int nc = nq * 32 + nt * 8 + g;
                const __half* br = ws2 + nc * RW + off + 2 * tg;
                unsigned b0 = ldh2(br), b1 = ldh2(br + 8);
                MMA_F16(c[nt], a0, a1, a2, a3, b0, b1);
            }
        }
#pragma unroll
        for (int nt = 0; nt < 4; nt++) {
            int col0 = nq * 32 + nt * 8 + 2 * tg;
            float m0 = mbp[col0], m1 = mbp[col0 + 1];
#pragma unroll
            for (int ci2 = 0; ci2 < 2; ci2++) {
                int r = mt2 * 16 + g + ci2 * 8;
                float2 ov = make_float2(c[nt][ci2 * 2] + m0, c[nt][ci2 * 2 + 1] + m1);
                *(float2*)&g_bias2[(size_t)(row0 + r) * DD + col0] = ov;
            }
        }
    }
}

// ---------------- MLP: persistent weights, 8 seqs per CTA ----------------
#define MLP_O_WS 0
#define MLP_O_HS 17408
#define MLP_HALVES 26112
#define MLP_SMEM (MLP_HALVES * 2)
__global__ void __launch_bounds__(256) k_mlp(const float* __restrict__ mw) {
    extern __shared__ unsigned char smraw[];
    __half* ws = (__half*)smraw + MLP_O_WS;
    __half* hs = (__half*)smraw + MLP_O_HS;
    __shared__ float sb[128];
    int tid = threadIdx.x, lane = tid & 31, w = tid >> 5, g = lane >> 2, tg = lane & 3;

    for (int e = tid; e < 4096; e += 256) {
        int r = e >> 5, k4 = (e & 31) * 4;
        float4 v = *(const float4*)(mw + (size_t)r * 256 + k4);
        sth2(ws + r * RW + k4, v.x, v.y);
        sth2(ws + r * RW + k4 + 2, v.z, v.w);
    }

    for (int bi = 0; bi < 8; bi++) {
        int s = blockIdx.x * 8 + bi;
        const __half* rb = g_ret + (size_t)s * (TT * DD);
        for (int e = tid; e < 1024; e += 256) {
            int r = e >> 4, c8 = (e & 15) * 8;
            *(uint4*)(hs + r * RW + c8) = *(const uint4*)(rb + r * DD + c8);
        }
        if (tid < 128) sb[tid] = g_bias2[(size_t)s * DD + tid];
        __syncthreads();

        float c[4][2][4];
#pragma unroll
        for (int mt = 0; mt < 4; mt++)
#pragma unroll
            for (int nt = 0; nt < 2; nt++)
#pragma unroll
                for (int ci = 0; ci < 4; ci++) c[mt][nt][ci] = 0.f;
#pragma unroll
        for (int ks2 = 0; ks2 < 8; ks2++) {
            int off = ks2 * 16;
            unsigned a[4][4];
#pragma unroll
            for (int mt = 0; mt < 4; mt++) {
                const __half* ar0 = hs + (mt * 16 + g) * RW + off + 2 * tg;
                const __half* ar1 = ar0 + 8 * RW;
                a[mt][0] = ldh2(ar0); a[mt][1] = ldh2(ar1);
                a[mt][2] = ldh2(ar0 + 8); a[mt][3] = ldh2(ar1 + 8);
            }
#pragma unroll
            for (int nt = 0; nt < 2; nt++) {
                int nc = w * 16 + nt * 8 + g;
                const __half* br = ws + nc * RW + off + 2 * tg;
                unsigned b0 = ldh2(br), b1 = ldh2(br + 8);
#pragma unroll
                for (int mt = 0; mt < 4; mt++)
                    MMA_F16(c[mt][nt], a[mt][0], a[mt][1], a[mt][2], a[mt][3], b0, b1);
            }
        }
        __half* gh = g_h + (size_t)s * (TT * DD);
#pragma unroll
        for (int mt = 0; mt < 4; mt++)
#pragma unroll
            for (int nt = 0; nt < 2; nt++) {
                int col0 = w * 16 + nt * 8 + 2 * tg;
                float b0 = sb[col0], b1 = sb[col0 + 1];
#pragma unroll
                for (int ci2 = 0; ci2 < 2; ci2++) {
                    int r = mt * 16 + g + ci2 * 8;
                    sth2(&gh[r * DD + col0], lrelu(c[mt][nt][ci2 * 2] + b0),
                         lrelu(c[mt][nt][ci2 * 2 + 1] + b1));
                }
            }
        __syncthreads();
    }
}

// ---------------- head ----------------
__global__ void k_head(const float* __restrict__ h1w, const float* __restrict__ h1b,
                       const float* __restrict__ h2w, const float* __restrict__ h2b,
                       float* __restrict__ out) {
    __shared__ float wt[128 * 65];
    __shared__ float lr[128];
    __shared__ float red[2];
    int bn = blockIdx.x;
    int tid = threadIdx.x;
    for (int e = tid; e < 128; e += 64)
        lr[e] = __half2float(g_h[((size_t)bn * TT + (TT - 1)) * DD + e]);
    for (int e = tid; e < 64 * 128; e += 64) {
        int jj = e >> 7, k = e & 127;
        wt[k * 65 + jj] = h1w[e];
    }
    __syncthreads();
    float s = 0.f;
    for (int k = 0; k < 128; k++) s += lr[k] * wt[k * 65 + tid];
    s += h1b[tid];
    s = lrelu(s);
    s *= h2w[tid];
#pragma unroll
    for (int o = 16; o; o >>= 1) s += __shfl_down_sync(0xffffffffu, s, o);
    if ((tid & 31) == 0) red[tid >> 5] = s;
    __syncthreads();
    if (tid == 0) out[bn] = red[0] + red[1] + h2b[0];
}

// ---------------- launch ----------------
extern "C" void kernel_launch(void* const* d_in, const int* in_sizes, int n_in,
                              void* d_out, int out_size) {
    const float* x      = (const float*)d_in[0];
    const float* adj    = (const float*)d_in[1];
    const float* proj_w = (const float*)d_in[2];
    const float* proj_b = (const float*)d_in[3];
    const float* pos    = (const float*)d_in[4];
    const float* diff_w = (const float*)d_in[5];
    const float* conv_w = (const float*)d_in[6];
    const float* conv_b = (const float*)d_in[7];
    const float* wq_w   = (const float*)d_in[8];
    const float* wq_b   = (const float*)d_in[9];
    const float* wk_w   = (const float*)d_in[10];
    const float* wk_b   = (const float*)d_in[11];
    const float* wv_w   = (const float*)d_in[12];
    const float* wv_b   = (const float*)d_in[13];
    const float* gn_w   = (const float*)d_in[14];
    const float* gn_b   = (const float*)d_in[15];
    const float* gamma  = (const float*)d_in[16];
    const float* ln_w   = (const float*)d_in[17];
    const float* ln_b   = (const float*)d_in[18];
    const float* mlp_w  = (const float*)d_in[19];
    const float* mlp_b  = (const float*)d_in[20];
    const float* h1w    = (const float*)d_in[21];
    const float* h1b    = (const float*)d_in[22];
    const float* h2w    = (const float*)d_in[23];
    const float* h2b    = (const float*)d_in[24];

    cudaFuncSetAttribute(k_ret, cudaFuncAttributeMaxDynamicSharedMemorySize, RET_SMEM);
    cudaFuncSetAttribute(k_mlp, cudaFuncAttributeMaxDynamicSharedMemorySize, MLP_SMEM);
    cudaFuncSetAttribute(k_dfin, cudaFuncAttributeMaxDynamicSharedMemorySize, DF_SMEM);

    k_proj<<<BN, 128>>>(x, proj_w, proj_b, pos);
    k_adjn<<<BB * NN, 256>>>(adj);

    for (int l = 0; l < 2; l++) {
        k_ret<<<NSM, 512, RET_SMEM>>>(
            wq_w + l * DD * DD, wq_b + l * DD, wk_w + l * DD * DD, wk_b + l * DD,
            wv_w + l * DD * DD, wv_b + l * DD, gn_w + l * DD, gn_b + l * DD,
            gamma + l, ln_w + l * DD, ln_b + l * DD);
        k_hopT<<<dim3(NN / 16, BB), 256>>>(0);  // P1t = H_lastT "@" A -> curT_a
        k_hopT<<<dim3(NN / 16, BB), 256>>>(1);  // P2t = P1t "@" A     -> curT_b
        k_dfin<<<BN / 32, 256, DF_SMEM>>>(diff_w + l * DD * DD,
                                          mlp_w + (size_t)l * DD * 2 * DD,
                                          conv_w + l * 3, conv_b + l, mlp_b + l * DD);
        k_mlp<<<BN / 8, 256, MLP_SMEM>>>(mlp_w + (size_t)l * DD * 2 * DD);
    }
    k_head<<<BN, 64>>>(h1w, h1b, h2w, h2b, (float*)d_out);
}